// round 7
// baseline (speedup 1.0000x reference)
#include <cuda_runtime.h>
#include <cuda_bf16.h>
#include <math.h>
#include <stdint.h>

#define B_ 8
#define N_ 1024
#define C_ 768
#define H_ 12
#define D_ 64
#define QKVC_ (3 * C_)
#define M_ (B_ * N_)

// ----------------------------- scratch ------------------------------------
__device__ __nv_bfloat16 g_xhi[M_ * C_],     g_xlo[M_ * C_];
__device__ __nv_bfloat16 g_whiT[QKVC_ * C_], g_wloT[QKVC_ * C_];
__device__ __nv_bfloat16 g_phiT[C_ * C_],    g_ploT[C_ * C_];
__device__ __nv_bfloat16 g_qkvhi[M_ * QKVC_], g_qkvlo[M_ * QKVC_];
__device__ __nv_bfloat16 g_ahi[M_ * C_],     g_alo[M_ * C_];

// ----------------------------- helpers ------------------------------------
__device__ __forceinline__ uint32_t smem_u32(const void* p) {
    uint32_t a;
    asm("{ .reg .u64 t; cvta.to.shared.u64 t, %1; cvt.u32.u64 %0, t; }"
        : "=r"(a) : "l"(p));
    return a;
}
__device__ __forceinline__ void cp16(uint32_t s, const void* g) {
    asm volatile("cp.async.cg.shared.global [%0], [%1], 16;"
                 :: "r"(s), "l"(g) : "memory");
}
#define CP_COMMIT() asm volatile("cp.async.commit_group;" ::: "memory")
#define CP_WAIT(n)  asm volatile("cp.async.wait_group %0;" :: "n"(n) : "memory")

__device__ __forceinline__ void ldsm_x4(uint32_t* f, uint32_t a) {
    asm volatile("ldmatrix.sync.aligned.m8n8.x4.shared.b16 {%0,%1,%2,%3}, [%4];"
                 : "=r"(f[0]), "=r"(f[1]), "=r"(f[2]), "=r"(f[3]) : "r"(a));
}
__device__ __forceinline__ void ldsm_x4t(uint32_t* f, uint32_t a) {
    asm volatile("ldmatrix.sync.aligned.m8n8.x4.trans.shared.b16 {%0,%1,%2,%3}, [%4];"
                 : "=r"(f[0]), "=r"(f[1]), "=r"(f[2]), "=r"(f[3]) : "r"(a));
}
__device__ __forceinline__ void ldsm_x2(uint32_t* f, uint32_t a) {
    asm volatile("ldmatrix.sync.aligned.m8n8.x2.shared.b16 {%0,%1}, [%2];"
                 : "=r"(f[0]), "=r"(f[1]) : "r"(a));
}
__device__ __forceinline__ void mma16816(float* d, const uint32_t* a,
                                         const uint32_t* b) {
    asm volatile(
        "mma.sync.aligned.m16n8k16.row.col.f32.bf16.bf16.f32 "
        "{%0,%1,%2,%3}, {%4,%5,%6,%7}, {%8,%9}, {%0,%1,%2,%3};"
        : "+f"(d[0]), "+f"(d[1]), "+f"(d[2]), "+f"(d[3])
        : "r"(a[0]), "r"(a[1]), "r"(a[2]), "r"(a[3]), "r"(b[0]), "r"(b[1]));
}
__device__ __forceinline__ uint32_t pk2(float f0, float f1) {
    __nv_bfloat162 h = __floats2bfloat162_rn(f0, f1);
    return *reinterpret_cast<uint32_t*>(&h);
}

// ----------------------------- split kernels ------------------------------
__global__ void split_ew(const float4* __restrict__ s,
                         __nv_bfloat16* __restrict__ hi,
                         __nv_bfloat16* __restrict__ lo, int n4) {
    int i = blockIdx.x * blockDim.x + threadIdx.x;
    if (i >= n4) return;
    float4 v = s[i];
    float a[4] = {v.x, v.y, v.z, v.w};
    __align__(8) __nv_bfloat16 h[4];
    __align__(8) __nv_bfloat16 l[4];
#pragma unroll
    for (int j = 0; j < 4; j++) {
        h[j] = __float2bfloat16(a[j]);
        l[j] = __float2bfloat16(a[j] - __bfloat162float(h[j]));
    }
    *reinterpret_cast<uint2*>(hi + (size_t)i * 4) = *reinterpret_cast<uint2*>(h);
    *reinterpret_cast<uint2*>(lo + (size_t)i * 4) = *reinterpret_cast<uint2*>(l);
}

__global__ void split_transpose(const float* __restrict__ w,
                                __nv_bfloat16* __restrict__ hiT,
                                __nv_bfloat16* __restrict__ loT, int K, int N) {
    __shared__ float t[32][33];
    const int n0 = blockIdx.x * 32, k0 = blockIdx.y * 32;
    for (int r = threadIdx.y; r < 32; r += 8)
        t[r][threadIdx.x] = w[(size_t)(k0 + r) * N + n0 + threadIdx.x];
    __syncthreads();
    for (int r = threadIdx.y; r < 32; r += 8) {
        float v = t[threadIdx.x][r];
        __nv_bfloat16 h = __float2bfloat16(v);
        __nv_bfloat16 l = __float2bfloat16(v - __bfloat162float(h));
        size_t o = (size_t)(n0 + r) * K + k0 + threadIdx.x;
        hiT[o] = h; loT[o] = l;
    }
}

// ----------------------------- mma.sync GEMM -------------------------------
// 512 threads, 16 warps 4x4, warp tile 32x32, BK=64, 2-stage cp.async.
#define BK_ 64
#define LROW_ 144
#define MATB_ (128 * LROW_)              // 18432
#define STGB_ (4 * MATB_)                // 73728
#define GEMM_SMEM (2 * STGB_)            // 147456

template <bool BIAS, bool SPLITOUT>
__global__ __launch_bounds__(512, 1)
void mma_gemm(const __nv_bfloat16* __restrict__ Ahi,
              const __nv_bfloat16* __restrict__ Alo,
              const __nv_bfloat16* __restrict__ BhiT,
              const __nv_bfloat16* __restrict__ BloT,
              const float* __restrict__ bias,
              float* __restrict__ Cf,
              __nv_bfloat16* __restrict__ Chi,
              __nv_bfloat16* __restrict__ Clo,
              int scale_cols, int Nn, int K) {
    extern __shared__ char smem[];
    const uint32_t sb = smem_u32(smem);
    const int tid = threadIdx.x;
    const int wid = tid >> 5;
    const int lane = tid & 31;
    const int row0 = blockIdx.y * 128;
    const int col0 = blockIdx.x * 128;
    const int wm = (wid >> 2) * 32;
    const int wn = (wid & 3) * 32;

    float acc[2][4][4];
#pragma unroll
    for (int i = 0; i < 2; i++)
#pragma unroll
        for (int j = 0; j < 4; j++)
#pragma unroll
            for (int k = 0; k < 4; k++) acc[i][j][k] = 0.f;

#define LOAD_STAGE(cc, ss)                                                   \
    {                                                                        \
        const uint32_t base = sb + (ss) * STGB_;                             \
        const int k0 = (cc) * BK_;                                           \
        _Pragma("unroll")                                                    \
        for (int t = 0; t < 8; t++) {                                        \
            const int idx = tid + t * 512;                                   \
            const int mat = idx >> 10, rem = idx & 1023;                     \
            const int r = rem >> 3, c8 = rem & 7;                            \
            const uint32_t off = (uint32_t)(mat * MATB_ + r * LROW_ + c8 * 16); \
            const __nv_bfloat16* src;                                        \
            if (mat == 0)      src = Ahi  + (size_t)(row0 + r) * K + k0 + c8 * 8; \
            else if (mat == 1) src = Alo  + (size_t)(row0 + r) * K + k0 + c8 * 8; \
            else if (mat == 2) src = BhiT + (size_t)(col0 + r) * K + k0 + c8 * 8; \
            else               src = BloT + (size_t)(col0 + r) * K + k0 + c8 * 8; \
            cp16(base + off, src);                                           \
        }                                                                    \
        CP_COMMIT();                                                         \
    }

    const int nch = K / BK_;    // 12
    LOAD_STAGE(0, 0);

    for (int c = 0; c < nch; c++) {
        const int cur = c & 1;
        if (c + 1 < nch) {
            LOAD_STAGE(c + 1, 1 - cur);
            CP_WAIT(1);
        } else {
            CP_WAIT(0);
        }
        __syncthreads();

        const uint32_t stg = sb + cur * STGB_;
#pragma unroll
        for (int kk = 0; kk < 4; kk++) {
            uint32_t ah[2][4], al[2][4], bh[4][2], bl[4][2];
            const uint32_t acol = (uint32_t)((kk * 16 + (lane >> 4) * 8) * 2);
            const uint32_t bcol =
                (uint32_t)((kk * 16 + ((lane >> 3) & 1) * 8) * 2);
#pragma unroll
            for (int mt = 0; mt < 2; mt++) {
                const uint32_t arow =
                    (uint32_t)((wm + mt * 16 + (lane & 15)) * LROW_);
                ldsm_x4(ah[mt], stg + arow + acol);
                ldsm_x4(al[mt], stg + MATB_ + arow + acol);
            }
#pragma unroll
            for (int nt = 0; nt < 4; nt++) {
                const uint32_t brow =
                    (uint32_t)((wn + nt * 8 + (lane & 7)) * LROW_);
                ldsm_x2(bh[nt], stg + 2 * MATB_ + brow + bcol);
                ldsm_x2(bl[nt], stg + 3 * MATB_ + brow + bcol);
            }
            // pass-major
#pragma unroll
            for (int mt = 0; mt < 2; mt++)
#pragma unroll
                for (int nt = 0; nt < 4; nt++)
                    mma16816(acc[mt][nt], ah[mt], bh[nt]);
#pragma unroll
            for (int mt = 0; mt < 2; mt++)
#pragma unroll
                for (int nt = 0; nt < 4; nt++)
                    mma16816(acc[mt][nt], ah[mt], bl[nt]);
#pragma unroll
            for (int mt = 0; mt < 2; mt++)
#pragma unroll
                for (int nt = 0; nt < 4; nt++)
                    mma16816(acc[mt][nt], al[mt], bh[nt]);
        }
        __syncthreads();
    }
#undef LOAD_STAGE

    const int g = lane >> 2, t4 = lane & 3;
#pragma unroll
    for (int nt = 0; nt < 4; nt++) {
        const int col = col0 + wn + nt * 8 + t4 * 2;
        if (SPLITOUT) {
            const float sc = (col < scale_cols) ? 0.125f : 1.0f;
#pragma unroll
            for (int mt = 0; mt < 2; mt++) {
                const int ra = row0 + wm + mt * 16 + g;
#pragma unroll
                for (int half = 0; half < 2; half++) {
                    const int r = ra + half * 8;
                    const float v0 = acc[mt][nt][half * 2 + 0] * sc;
                    const float v1 = acc[mt][nt][half * 2 + 1] * sc;
                    __nv_bfloat16 h0 = __float2bfloat16(v0);
                    __nv_bfloat16 h1 = __float2bfloat16(v1);
                    const float l0 = v0 - __bfloat162float(h0);
                    const float l1 = v1 - __bfloat162float(h1);
                    const size_t off = (size_t)r * Nn + col;
                    *reinterpret_cast<uint32_t*>(Chi + off) =
                        pk2(__bfloat162float(h0), __bfloat162float(h1));
                    *reinterpret_cast<uint32_t*>(Clo + off) = pk2(l0, l1);
                }
            }
        } else {
            float b0 = 0.f, b1 = 0.f;
            if (BIAS) { b0 = bias[col]; b1 = bias[col + 1]; }
#pragma unroll
            for (int mt = 0; mt < 2; mt++) {
                const int ra = row0 + wm + mt * 16 + g;
                float2 v0 = make_float2(acc[mt][nt][0] + b0, acc[mt][nt][1] + b1);
                float2 v1 = make_float2(acc[mt][nt][2] + b0, acc[mt][nt][3] + b1);
                *reinterpret_cast<float2*>(&Cf[(size_t)ra * Nn + col]) = v0;
                *reinterpret_cast<float2*>(&Cf[(size_t)(ra + 8) * Nn + col]) = v1;
            }
        }
    }
}

// ----------------------------- mma flash attention -------------------------
// 512 threads, 16 warps. Warp pair (w, w+8): same 16 q-rows, key halves
// (64 keys each). Independent online softmax per half; one final merge.
#define ATT_LD 144
#define ATT_MAT 18432
#define ATT_STG0 (2 * ATT_MAT)
#define ATT_STGSZ (4 * ATT_MAT)
#define ATT_SMEM (ATT_STG0 + 2 * ATT_STGSZ)  // 184320

__global__ __launch_bounds__(512, 1)
void attn_mma(const __nv_bfloat16* __restrict__ qhi,
              const __nv_bfloat16* __restrict__ qlo,
              __nv_bfloat16* __restrict__ ohi,
              __nv_bfloat16* __restrict__ olo) {
    extern __shared__ char smem[];
    const uint32_t sb = smem_u32(smem);
    const int tid = threadIdx.x, wid = tid >> 5, lane = tid & 31;
    const int qw = wid & 7;            // q-row group
    const int ks = wid >> 3;           // key half (0 or 1)
    const int b = blockIdx.y / H_, h = blockIdx.y % H_;
    const int q0 = blockIdx.x * 128;
    const size_t rowbase = (size_t)b * N_;

    // ---- load Q (hi/lo) ----
#pragma unroll
    for (int t = 0; t < 4; t++) {
        const int idx = tid + t * 512;
        const int mat = idx >> 10, rem = idx & 1023;
        const int r = rem >> 3, c = rem & 7;
        const uint32_t so = sb + mat * ATT_MAT + r * ATT_LD + c * 16;
        const __nv_bfloat16* src =
            (mat ? qlo : qhi) + ((rowbase + q0 + r) * QKVC_ + h * D_ + c * 8);
        cp16(so, src);
    }

#define LOAD_STAGE_ATT(ktile, ss)                                            \
    {                                                                        \
        const uint32_t base = sb + ATT_STG0 + (ss) * ATT_STGSZ;              \
        const size_t krow = rowbase + (ktile) * 128;                         \
        _Pragma("unroll")                                                    \
        for (int t = 0; t < 8; t++) {                                        \
            const int idx = tid + t * 512;                                   \
            const int mat = idx >> 10, rem = idx & 1023;                     \
            const int r = rem >> 3, c = rem & 7;                             \
            const uint32_t so = base + mat * ATT_MAT + r * ATT_LD + c * 16;  \
            const __nv_bfloat16* sp = ((mat & 1) ? qlo : qhi) +              \
                ((krow + r) * QKVC_ + ((mat >> 1) ? 2 * C_ : C_) +           \
                 h * D_ + c * 8);                                            \
            cp16(so, sp);                                                    \
        }                                                                    \
        CP_COMMIT();                                                         \
    }

    LOAD_STAGE_ATT(0, 0);

    float m_lo = -INFINITY, m_hi = -INFINITY, l_lo = 0.f, l_hi = 0.f;
    float o[8][4];
#pragma unroll
    for (int i = 0; i < 8; i++)
#pragma unroll
        for (int j = 0; j < 4; j++) o[i][j] = 0.f;

    const uint32_t qa =
        sb + (qw * 16 + (lane & 15)) * ATT_LD + ((lane >> 4) * 8) * 2;

    for (int kt = 0; kt < N_ / 128; kt++) {
        if (kt + 1 < N_ / 128) {
            LOAD_STAGE_ATT(kt + 1, (kt + 1) & 1);
            CP_WAIT(1);
        } else {
            CP_WAIT(0);
        }
        __syncthreads();

        const uint32_t stg = sb + ATT_STG0 + (kt & 1) * ATT_STGSZ;

        // ---- S = Q @ K^T over this warp's 64-key half ----
        float s[8][4];
#pragma unroll
        for (int nt = 0; nt < 8; nt++)
#pragma unroll
            for (int j = 0; j < 4; j++) s[nt][j] = 0.f;

#pragma unroll
        for (int k4 = 0; k4 < 4; k4++) {
            uint32_t qh[4], ql[4];
            ldsm_x4(qh, qa + k4 * 32);
            ldsm_x4(ql, qa + ATT_MAT + k4 * 32);
            const uint32_t ka = stg + (ks * 64 + (lane & 7)) * ATT_LD +
                                (k4 * 16 + ((lane >> 3) & 1) * 8) * 2;
#pragma unroll
            for (int blk = 0; blk < 2; blk++) {
                uint32_t kh[4][2], kl[4][2];
#pragma unroll
                for (int j = 0; j < 4; j++) {
                    const int nt = blk * 4 + j;
                    ldsm_x2(kh[j], ka + nt * 8 * ATT_LD);
                    ldsm_x2(kl[j], ka + ATT_MAT + nt * 8 * ATT_LD);
                }
#pragma unroll
                for (int j = 0; j < 4; j++)
                    mma16816(s[blk * 4 + j], qh, kh[j]);
#pragma unroll
                for (int j = 0; j < 4; j++)
                    mma16816(s[blk * 4 + j], qh, kl[j]);
#pragma unroll
                for (int j = 0; j < 4; j++)
                    mma16816(s[blk * 4 + j], ql, kh[j]);
            }
        }

        // ---- online softmax over this half (quad shfl) ----
        float tmlo = -INFINITY, tmhi = -INFINITY;
#pragma unroll
        for (int nt = 0; nt < 8; nt++) {
            tmlo = fmaxf(tmlo, fmaxf(s[nt][0], s[nt][1]));
            tmhi = fmaxf(tmhi, fmaxf(s[nt][2], s[nt][3]));
        }
        tmlo = fmaxf(tmlo, __shfl_xor_sync(0xffffffffu, tmlo, 1));
        tmlo = fmaxf(tmlo, __shfl_xor_sync(0xffffffffu, tmlo, 2));
        tmhi = fmaxf(tmhi, __shfl_xor_sync(0xffffffffu, tmhi, 1));
        tmhi = fmaxf(tmhi, __shfl_xor_sync(0xffffffffu, tmhi, 2));

        const float mnlo = fmaxf(m_lo, tmlo);
        const float mnhi = fmaxf(m_hi, tmhi);
        const float corrlo = __expf(m_lo - mnlo);
        const float corrhi = __expf(m_hi - mnhi);
        m_lo = mnlo; m_hi = mnhi;

        float pslo = 0.f, pshi = 0.f;
#pragma unroll
        for (int nt = 0; nt < 8; nt++) {
            s[nt][0] = __expf(s[nt][0] - mnlo);
            s[nt][1] = __expf(s[nt][1] - mnlo);
            s[nt][2] = __expf(s[nt][2] - mnhi);
            s[nt][3] = __expf(s[nt][3] - mnhi);
            pslo += s[nt][0] + s[nt][1];
            pshi += s[nt][2] + s[nt][3];
        }
        pslo += __shfl_xor_sync(0xffffffffu, pslo, 1);
        pslo += __shfl_xor_sync(0xffffffffu, pslo, 2);
        pshi += __shfl_xor_sync(0xffffffffu, pshi, 1);
        pshi += __shfl_xor_sync(0xffffffffu, pshi, 2);
        l_lo = l_lo * corrlo + pslo;
        l_hi = l_hi * corrhi + pshi;

#pragma unroll
        for (int nt = 0; nt < 8; nt++) {
            o[nt][0] *= corrlo; o[nt][1] *= corrlo;
            o[nt][2] *= corrhi; o[nt][3] *= corrhi;
        }

        // ---- O += P @ V over this half ----
#pragma unroll
        for (int t8 = 0; t8 < 4; t8++) {
            uint32_t ah[4], al[4];
#pragma unroll
            for (int half = 0; half < 2; half++) {
                const float p0 = s[2 * t8 + half][0];
                const float p1 = s[2 * t8 + half][1];
                const float p2 = s[2 * t8 + half][2];
                const float p3 = s[2 * t8 + half][3];
                const __nv_bfloat16 h0 = __float2bfloat16(p0);
                const __nv_bfloat16 h1 = __float2bfloat16(p1);
                const __nv_bfloat16 h2 = __float2bfloat16(p2);
                const __nv_bfloat16 h3 = __float2bfloat16(p3);
                ah[half * 2 + 0] = pk2(__bfloat162float(h0), __bfloat162float(h1));
                ah[half * 2 + 1] = pk2(__bfloat162float(h2), __bfloat162float(h3));
                al[half * 2 + 0] = pk2(p0 - __bfloat162float(h0),
                                       p1 - __bfloat162float(h1));
                al[half * 2 + 1] = pk2(p2 - __bfloat162float(h2),
                                       p3 - __bfloat162float(h3));
            }

            const uint32_t va = stg + 2 * ATT_MAT +
                (ks * 64 + t8 * 16 + (lane & 7) + 8 * ((lane >> 3) & 1)) * ATT_LD +
                ((lane >> 4) & 1) * 16;
#pragma unroll
            for (int g2 = 0; g2 < 2; g2++) {
                uint32_t vh[2][4], vl[2][4];
#pragma unroll
                for (int j = 0; j < 2; j++) {
                    ldsm_x4t(vh[j], va + (g2 * 2 + j) * 32);
                    ldsm_x4t(vl[j], va + ATT_MAT + (g2 * 2 + j) * 32);
                }
#pragma unroll
                for (int j = 0; j < 2; j++) {
                    const int nt2 = g2 * 2 + j;
                    mma16816(o[2 * nt2],     ah, vh[j]);
                    mma16816(o[2 * nt2 + 1], ah, vh[j] + 2);
                }
#pragma unroll
                for (int j = 0; j < 2; j++) {
                    const int nt2 = g2 * 2 + j;
                    mma16816(o[2 * nt2],     ah, vl[j]);
                    mma16816(o[2 * nt2 + 1], ah, vl[j] + 2);
                }
#pragma unroll
                for (int j = 0; j < 2; j++) {
                    const int nt2 = g2 * 2 + j;
                    mma16816(o[2 * nt2],     al, vh[j]);
                    mma16816(o[2 * nt2 + 1], al, vh[j] + 2);
                }
            }
        }
        __syncthreads();
    }
#undef LOAD_STAGE_ATT

    // ---- cross-half merge (warp pair qw, qw+8), then normalize+store ----
    float* ex = reinterpret_cast<float*>(smem);   // K/V/Q areas are dead now
    if (ks == 1) {
        float* dst = ex + (size_t)(qw * 32 + lane) * 37;
#pragma unroll
        for (int nt = 0; nt < 8; nt++)
#pragma unroll
            for (int j = 0; j < 4; j++) dst[nt * 4 + j] = o[nt][j];
        dst[32] = m_lo; dst[33] = m_hi; dst[34] = l_lo; dst[35] = l_hi;
    }
    __syncthreads();
    if (ks == 0) {
        const float* src = ex + (size_t)(qw * 32 + lane) * 37;
        const float pm_lo = src[32], pm_hi = src[33];
        const float pl_lo = src[34], pl_hi = src[35];
        const float Mlo = fmaxf(m_lo, pm_lo), Mhi = fmaxf(m_hi, pm_hi);
        const float c1lo = __expf(m_lo - Mlo), c2lo = __expf(pm_lo - Mlo);
        const float c1hi = __expf(m_hi - Mhi), c2hi = __expf(pm_hi - Mhi);
        const float invlo = 1.f / (l_lo * c1lo + pl_lo * c2lo);
        const float invhi = 1.f / (l_hi * c1hi + pl_hi * c2hi);

        const size_t rlo = rowbase + q0 + qw * 16 + (lane >> 2);
        const int colb = h * D_ + (lane & 3) * 2;
#pragma unroll
        for (int nt = 0; nt < 8; nt++) {
            const int col = colb + nt * 8;
            {
                const float v0 =
                    (o[nt][0] * c1lo + src[nt * 4 + 0] * c2lo) * invlo;
                const float v1 =
                    (o[nt][1] * c1lo + src[nt * 4 + 1] * c2lo) * invlo;
                const __nv_bfloat16 h0 = __float2bfloat16(v0);
                const __nv_bfloat16 h1 = __float2bfloat16(v1);
                const size_t off = rlo * C_ + col;
                *reinterpret_cast<uint32_t*>(ohi + off) =
                    pk2(__bfloat162float(h0), __bfloat162float(h1));
                *reinterpret_cast<uint32_t*>(olo + off) =
                    pk2(v0 - __bfloat162float(h0), v1 - __bfloat162float(h1));
            }
            {
                const float v0 =
                    (o[nt][2] * c1hi + src[nt * 4 + 2] * c2hi) * invhi;
                const float v1 =
                    (o[nt][3] * c1hi + src[nt * 4 + 3] * c2hi) * invhi;
                const __nv_bfloat16 h0 = __float2bfloat16(v0);
                const __nv_bfloat16 h1 = __float2bfloat16(v1);
                const size_t off = (rlo + 8) * C_ + col;
                *reinterpret_cast<uint32_t*>(ohi + off) =
                    pk2(__bfloat162float(h0), __bfloat162float(h1));
                *reinterpret_cast<uint32_t*>(olo + off) =
                    pk2(v0 - __bfloat162float(h0), v1 - __bfloat162float(h1));
            }
        }
    }
}

// ----------------------------- launch -------------------------------------
extern "C" void kernel_launch(void* const* d_in, const int* in_sizes, int n_in,
                              void* d_out, int out_size) {
    const float* x      = (const float*)d_in[0];
    const float* w_qkv  = (const float*)d_in[1];
    const float* w_proj = (const float*)d_in[2];
    const float* b_proj = (const float*)d_in[3];
    float* out = (float*)d_out;

    __nv_bfloat16 *xhi, *xlo, *whiT, *wloT, *phiT, *ploT;
    __nv_bfloat16 *qhi, *qlo, *ahi, *alo;
    cudaGetSymbolAddress((void**)&xhi,  g_xhi);
    cudaGetSymbolAddress((void**)&xlo,  g_xlo);
    cudaGetSymbolAddress((void**)&whiT, g_whiT);
    cudaGetSymbolAddress((void**)&wloT, g_wloT);
    cudaGetSymbolAddress((void**)&phiT, g_phiT);
    cudaGetSymbolAddress((void**)&ploT, g_ploT);
    cudaGetSymbolAddress((void**)&qhi,  g_qkvhi);
    cudaGetSymbolAddress((void**)&qlo,  g_qkvlo);
    cudaGetSymbolAddress((void**)&ahi,  g_ahi);
    cudaGetSymbolAddress((void**)&alo,  g_alo);

    cudaFuncSetAttribute((const void*)mma_gemm<false, true>,
                         cudaFuncAttributeMaxDynamicSharedMemorySize, GEMM_SMEM);
    cudaFuncSetAttribute((const void*)mma_gemm<true, false>,
                         cudaFuncAttributeMaxDynamicSharedMemorySize, GEMM_SMEM);
    cudaFuncSetAttribute((const void*)attn_mma,
                         cudaFuncAttributeMaxDynamicSharedMemorySize, ATT_SMEM);

    // 0) splits
    {
        int n4 = (M_ * C_) / 4;
        split_ew<<<(n4 + 255) / 256, 256>>>((const float4*)x, xhi, xlo, n4);
        dim3 blk(32, 8);
        dim3 g1(QKVC_ / 32, C_ / 32);
        split_transpose<<<g1, blk>>>(w_qkv, whiT, wloT, C_, QKVC_);
        dim3 g2(C_ / 32, C_ / 32);
        split_transpose<<<g2, blk>>>(w_proj, phiT, ploT, C_, C_);
    }
    // 1) QKV projection -> split bf16, Q pre-scaled by 0.125
    {
        dim3 grid(QKVC_ / 128, M_ / 128);
        mma_gemm<false, true><<<grid, 512, GEMM_SMEM>>>(
            xhi, xlo, whiT, wloT, nullptr, nullptr, qhi, qlo, C_, QKVC_, C_);
    }
    // 2) attention (tensor cores) -> split bf16 output
    {
        dim3 grid(N_ / 128, B_ * H_);
        attn_mma<<<grid, 512, ATT_SMEM>>>(qhi, qlo, ahi, alo);
    }
    // 3) output projection + bias -> fp32 out
    {
        dim3 grid(C_ / 128, M_ / 128);
        mma_gemm<true, false><<<grid, 512, GEMM_SMEM>>>(
            ahi, alo, phiT, ploT, b_proj, out, nullptr, nullptr, 0, C_, C_);
    }
}

// round 8
// speedup vs baseline: 1.0493x; 1.0493x over previous
#include <cuda_runtime.h>
#include <cuda_bf16.h>
#include <math.h>
#include <stdint.h>

#define B_ 8
#define N_ 1024
#define C_ 768
#define H_ 12
#define D_ 64
#define QKVC_ (3 * C_)
#define M_ (B_ * N_)

// ----------------------------- scratch ------------------------------------
__device__ __nv_bfloat16 g_xhi[M_ * C_],     g_xlo[M_ * C_];
__device__ __nv_bfloat16 g_whiT[QKVC_ * C_], g_wloT[QKVC_ * C_];
__device__ __nv_bfloat16 g_phiT[C_ * C_],    g_ploT[C_ * C_];
__device__ __nv_bfloat16 g_qkvhi[M_ * QKVC_], g_qkvlo[M_ * QKVC_];
__device__ __nv_bfloat16 g_ahi[M_ * C_],     g_alo[M_ * C_];

// ----------------------------- helpers ------------------------------------
__device__ __forceinline__ uint32_t smem_u32(const void* p) {
    uint32_t a;
    asm("{ .reg .u64 t; cvta.to.shared.u64 t, %1; cvt.u32.u64 %0, t; }"
        : "=r"(a) : "l"(p));
    return a;
}
__device__ __forceinline__ void cp16(uint32_t s, const void* g) {
    asm volatile("cp.async.cg.shared.global [%0], [%1], 16;"
                 :: "r"(s), "l"(g) : "memory");
}
#define CP_COMMIT() asm volatile("cp.async.commit_group;" ::: "memory")
#define CP_WAIT(n)  asm volatile("cp.async.wait_group %0;" :: "n"(n) : "memory")

__device__ __forceinline__ void ldsm_x4(uint32_t* f, uint32_t a) {
    asm volatile("ldmatrix.sync.aligned.m8n8.x4.shared.b16 {%0,%1,%2,%3}, [%4];"
                 : "=r"(f[0]), "=r"(f[1]), "=r"(f[2]), "=r"(f[3]) : "r"(a));
}
__device__ __forceinline__ void ldsm_x4t(uint32_t* f, uint32_t a) {
    asm volatile("ldmatrix.sync.aligned.m8n8.x4.trans.shared.b16 {%0,%1,%2,%3}, [%4];"
                 : "=r"(f[0]), "=r"(f[1]), "=r"(f[2]), "=r"(f[3]) : "r"(a));
}
__device__ __forceinline__ void ldsm_x2(uint32_t* f, uint32_t a) {
    asm volatile("ldmatrix.sync.aligned.m8n8.x2.shared.b16 {%0,%1}, [%2];"
                 : "=r"(f[0]), "=r"(f[1]) : "r"(a));
}
__device__ __forceinline__ void mma16816(float* d, const uint32_t* a,
                                         const uint32_t* b) {
    asm volatile(
        "mma.sync.aligned.m16n8k16.row.col.f32.bf16.bf16.f32 "
        "{%0,%1,%2,%3}, {%4,%5,%6,%7}, {%8,%9}, {%0,%1,%2,%3};"
        : "+f"(d[0]), "+f"(d[1]), "+f"(d[2]), "+f"(d[3])
        : "r"(a[0]), "r"(a[1]), "r"(a[2]), "r"(a[3]), "r"(b[0]), "r"(b[1]));
}
__device__ __forceinline__ uint32_t pk2(float f0, float f1) {
    __nv_bfloat162 h = __floats2bfloat162_rn(f0, f1);
    return *reinterpret_cast<uint32_t*>(&h);
}

// ----------------------------- split kernels ------------------------------
__global__ void split_ew(const float4* __restrict__ s,
                         __nv_bfloat16* __restrict__ hi,
                         __nv_bfloat16* __restrict__ lo, int n4) {
    int i = blockIdx.x * blockDim.x + threadIdx.x;
    if (i >= n4) return;
    float4 v = s[i];
    float a[4] = {v.x, v.y, v.z, v.w};
    __align__(8) __nv_bfloat16 h[4];
    __align__(8) __nv_bfloat16 l[4];
#pragma unroll
    for (int j = 0; j < 4; j++) {
        h[j] = __float2bfloat16(a[j]);
        l[j] = __float2bfloat16(a[j] - __bfloat162float(h[j]));
    }
    *reinterpret_cast<uint2*>(hi + (size_t)i * 4) = *reinterpret_cast<uint2*>(h);
    *reinterpret_cast<uint2*>(lo + (size_t)i * 4) = *reinterpret_cast<uint2*>(l);
}

__global__ void split_transpose(const float* __restrict__ w,
                                __nv_bfloat16* __restrict__ hiT,
                                __nv_bfloat16* __restrict__ loT, int K, int N) {
    __shared__ float t[32][33];
    const int n0 = blockIdx.x * 32, k0 = blockIdx.y * 32;
    for (int r = threadIdx.y; r < 32; r += 8)
        t[r][threadIdx.x] = w[(size_t)(k0 + r) * N + n0 + threadIdx.x];
    __syncthreads();
    for (int r = threadIdx.y; r < 32; r += 8) {
        float v = t[threadIdx.x][r];
        __nv_bfloat16 h = __float2bfloat16(v);
        __nv_bfloat16 l = __float2bfloat16(v - __bfloat162float(h));
        size_t o = (size_t)(n0 + r) * K + k0 + threadIdx.x;
        hiT[o] = h; loT[o] = l;
    }
}

// ----------------------------- mma.sync GEMM -------------------------------
// 256 threads, 8 warps 2x4, warp tile 64x32, BK=32, 2-stage cp.async,
// 2 CTAs per SM (smem 80KB/CTA, regs capped at 128 via launch_bounds).
#define BK_ 32
#define LROW_ 80
#define MATB_ (128 * LROW_)              // 10240
#define STGB_ (4 * MATB_)                // 40960
#define GEMM_SMEM (2 * STGB_)            // 81920

template <bool BIAS, bool SPLITOUT>
__global__ __launch_bounds__(256, 2)
void mma_gemm(const __nv_bfloat16* __restrict__ Ahi,
              const __nv_bfloat16* __restrict__ Alo,
              const __nv_bfloat16* __restrict__ BhiT,
              const __nv_bfloat16* __restrict__ BloT,
              const float* __restrict__ bias,
              float* __restrict__ Cf,
              __nv_bfloat16* __restrict__ Chi,
              __nv_bfloat16* __restrict__ Clo,
              int scale_cols, int Nn, int K) {
    extern __shared__ char smem[];
    const uint32_t sb = smem_u32(smem);
    const int tid = threadIdx.x;
    const int wid = tid >> 5;
    const int lane = tid & 31;
    const int row0 = blockIdx.y * 128;
    const int col0 = blockIdx.x * 128;
    const int wm = (wid >> 2) * 64;
    const int wn = (wid & 3) * 32;

    float acc[4][4][4];
#pragma unroll
    for (int i = 0; i < 4; i++)
#pragma unroll
        for (int j = 0; j < 4; j++)
#pragma unroll
            for (int k = 0; k < 4; k++) acc[i][j][k] = 0.f;

#define LOAD_STAGE(cc, ss)                                                   \
    {                                                                        \
        const uint32_t base = sb + (ss) * STGB_;                             \
        const int k0 = (cc) * BK_;                                           \
        _Pragma("unroll")                                                    \
        for (int t = 0; t < 2; t++) {                                        \
            const int fid = tid + t * 256;                                   \
            const int r = fid >> 2, ch = fid & 3;                            \
            const uint32_t off = (uint32_t)(r * LROW_ + ch * 16);            \
            const size_t ga = (size_t)(row0 + r) * K + k0 + ch * 8;          \
            const size_t gb = (size_t)(col0 + r) * K + k0 + ch * 8;          \
            cp16(base + off,             Ahi + ga);                          \
            cp16(base + MATB_ + off,     Alo + ga);                          \
            cp16(base + 2 * MATB_ + off, BhiT + gb);                         \
            cp16(base + 3 * MATB_ + off, BloT + gb);                         \
        }                                                                    \
        CP_COMMIT();                                                         \
    }

    const int nch = K / BK_;    // 24
    LOAD_STAGE(0, 0);

    for (int c = 0; c < nch; c++) {
        const int cur = c & 1;
        if (c + 1 < nch) {
            LOAD_STAGE(c + 1, 1 - cur);
            CP_WAIT(1);
        } else {
            CP_WAIT(0);
        }
        __syncthreads();

        const uint32_t stg = sb + cur * STGB_;
#pragma unroll
        for (int kk = 0; kk < 2; kk++) {
            uint32_t ah[4][4], al[4][4], bh[4][2], bl[4][2];
            const uint32_t acol = (uint32_t)((kk * 16 + (lane >> 4) * 8) * 2);
            const uint32_t bcol =
                (uint32_t)((kk * 16 + ((lane >> 3) & 1) * 8) * 2);
#pragma unroll
            for (int mt = 0; mt < 4; mt++) {
                const uint32_t arow =
                    (uint32_t)((wm + mt * 16 + (lane & 15)) * LROW_);
                ldsm_x4(ah[mt], stg + arow + acol);
                ldsm_x4(al[mt], stg + MATB_ + arow + acol);
            }
#pragma unroll
            for (int nt = 0; nt < 4; nt++) {
                const uint32_t brow =
                    (uint32_t)((wn + nt * 8 + (lane & 7)) * LROW_);
                ldsm_x2(bh[nt], stg + 2 * MATB_ + brow + bcol);
                ldsm_x2(bl[nt], stg + 3 * MATB_ + brow + bcol);
            }
            // pass-major: dependent MMAs on same acc 16 apart
#pragma unroll
            for (int mt = 0; mt < 4; mt++)
#pragma unroll
                for (int nt = 0; nt < 4; nt++)
                    mma16816(acc[mt][nt], ah[mt], bh[nt]);
#pragma unroll
            for (int mt = 0; mt < 4; mt++)
#pragma unroll
                for (int nt = 0; nt < 4; nt++)
                    mma16816(acc[mt][nt], ah[mt], bl[nt]);
#pragma unroll
            for (int mt = 0; mt < 4; mt++)
#pragma unroll
                for (int nt = 0; nt < 4; nt++)
                    mma16816(acc[mt][nt], al[mt], bh[nt]);
        }
        __syncthreads();
    }
#undef LOAD_STAGE

    const int g = lane >> 2, t4 = lane & 3;
#pragma unroll
    for (int nt = 0; nt < 4; nt++) {
        const int col = col0 + wn + nt * 8 + t4 * 2;
        if (SPLITOUT) {
            const float sc = (col < scale_cols) ? 0.125f : 1.0f;
#pragma unroll
            for (int mt = 0; mt < 4; mt++) {
                const int ra = row0 + wm + mt * 16 + g;
#pragma unroll
                for (int half = 0; half < 2; half++) {
                    const int r = ra + half * 8;
                    const float v0 = acc[mt][nt][half * 2 + 0] * sc;
                    const float v1 = acc[mt][nt][half * 2 + 1] * sc;
                    __nv_bfloat16 h0 = __float2bfloat16(v0);
                    __nv_bfloat16 h1 = __float2bfloat16(v1);
                    const float l0 = v0 - __bfloat162float(h0);
                    const float l1 = v1 - __bfloat162float(h1);
                    const size_t off = (size_t)r * Nn + col;
                    *reinterpret_cast<uint32_t*>(Chi + off) =
                        pk2(__bfloat162float(h0), __bfloat162float(h1));
                    *reinterpret_cast<uint32_t*>(Clo + off) = pk2(l0, l1);
                }
            }
        } else {
            float b0 = 0.f, b1 = 0.f;
            if (BIAS) { b0 = bias[col]; b1 = bias[col + 1]; }
#pragma unroll
            for (int mt = 0; mt < 4; mt++) {
                const int ra = row0 + wm + mt * 16 + g;
                float2 v0 = make_float2(acc[mt][nt][0] + b0, acc[mt][nt][1] + b1);
                float2 v1 = make_float2(acc[mt][nt][2] + b0, acc[mt][nt][3] + b1);
                *reinterpret_cast<float2*>(&Cf[(size_t)ra * Nn + col]) = v0;
                *reinterpret_cast<float2*>(&Cf[(size_t)(ra + 8) * Nn + col]) = v1;
            }
        }
    }
}

// ----------------------------- mma flash attention (R6, verified) ----------
#define ATT_LD 144
#define ATT_MAT 18432
#define ATT_STG0 (2 * ATT_MAT)
#define ATT_STGSZ (4 * ATT_MAT)
#define ATT_SMEM (ATT_STG0 + 2 * ATT_STGSZ)  // 184320

__global__ __launch_bounds__(256, 1)
void attn_mma(const __nv_bfloat16* __restrict__ qhi,
              const __nv_bfloat16* __restrict__ qlo,
              __nv_bfloat16* __restrict__ ohi,
              __nv_bfloat16* __restrict__ olo) {
    extern __shared__ char smem[];
    const uint32_t sb = smem_u32(smem);
    const int tid = threadIdx.x, wid = tid >> 5, lane = tid & 31;
    const int b = blockIdx.y / H_, h = blockIdx.y % H_;
    const int q0 = blockIdx.x * 128;
    const size_t rowbase = (size_t)b * N_;

#pragma unroll
    for (int t = 0; t < 8; t++) {
        const int idx = tid + t * 256;
        const int mat = idx >> 10, rem = idx & 1023;
        const int r = rem >> 3, c = rem & 7;
        const uint32_t so = sb + mat * ATT_MAT + r * ATT_LD + c * 16;
        const __nv_bfloat16* src =
            (mat ? qlo : qhi) + ((rowbase + q0 + r) * QKVC_ + h * D_ + c * 8);
        cp16(so, src);
    }

#define LOAD_STAGE_ATT(ktile, ss)                                            \
    {                                                                        \
        const uint32_t base = sb + ATT_STG0 + (ss) * ATT_STGSZ;              \
        const size_t krow = rowbase + (ktile) * 128;                         \
        _Pragma("unroll")                                                    \
        for (int t = 0; t < 16; t++) {                                       \
            const int idx = tid + t * 256;                                   \
            const int mat = idx >> 10, rem = idx & 1023;                     \
            const int r = rem >> 3, c = rem & 7;                             \
            const uint32_t so = base + mat * ATT_MAT + r * ATT_LD + c * 16;  \
            const __nv_bfloat16* sp = ((mat & 1) ? qlo : qhi) +              \
                ((krow + r) * QKVC_ + ((mat >> 1) ? 2 * C_ : C_) +           \
                 h * D_ + c * 8);                                            \
            cp16(so, sp);                                                    \
        }                                                                    \
        CP_COMMIT();                                                         \
    }

    LOAD_STAGE_ATT(0, 0);

    float m_lo = -INFINITY, m_hi = -INFINITY, l_lo = 0.f, l_hi = 0.f;
    float o[8][4];
#pragma unroll
    for (int i = 0; i < 8; i++)
#pragma unroll
        for (int j = 0; j < 4; j++) o[i][j] = 0.f;

    const uint32_t qa =
        sb + (wid * 16 + (lane & 15)) * ATT_LD + ((lane >> 4) * 8) * 2;

    for (int kt = 0; kt < N_ / 128; kt++) {
        if (kt + 1 < N_ / 128) {
            LOAD_STAGE_ATT(kt + 1, (kt + 1) & 1);
            CP_WAIT(1);
        } else {
            CP_WAIT(0);
        }
        __syncthreads();

        const uint32_t stg = sb + ATT_STG0 + (kt & 1) * ATT_STGSZ;

        float s[16][4];
#pragma unroll
        for (int nt = 0; nt < 16; nt++)
#pragma unroll
            for (int j = 0; j < 4; j++) s[nt][j] = 0.f;

#pragma unroll
        for (int k4 = 0; k4 < 4; k4++) {
            uint32_t qh[4], ql[4];
            ldsm_x4(qh, qa + k4 * 32);
            ldsm_x4(ql, qa + ATT_MAT + k4 * 32);
            const uint32_t ka = stg + (lane & 7) * ATT_LD +
                                (k4 * 16 + ((lane >> 3) & 1) * 8) * 2;
#pragma unroll
            for (int blk = 0; blk < 2; blk++) {
                uint32_t kh[8][2], kl[8][2];
#pragma unroll
                for (int j = 0; j < 8; j++) {
                    const int nt = blk * 8 + j;
                    ldsm_x2(kh[j], ka + nt * 8 * ATT_LD);
                    ldsm_x2(kl[j], ka + ATT_MAT + nt * 8 * ATT_LD);
                }
#pragma unroll
                for (int j = 0; j < 8; j++)
                    mma16816(s[blk * 8 + j], qh, kh[j]);
#pragma unroll
                for (int j = 0; j < 8; j++)
                    mma16816(s[blk * 8 + j], qh, kl[j]);
#pragma unroll
                for (int j = 0; j < 8; j++)
                    mma16816(s[blk * 8 + j], ql, kh[j]);
            }
        }

        float tmlo = -INFINITY, tmhi = -INFINITY;
#pragma unroll
        for (int nt = 0; nt < 16; nt++) {
            tmlo = fmaxf(tmlo, fmaxf(s[nt][0], s[nt][1]));
            tmhi = fmaxf(tmhi, fmaxf(s[nt][2], s[nt][3]));
        }
        tmlo = fmaxf(tmlo, __shfl_xor_sync(0xffffffffu, tmlo, 1));
        tmlo = fmaxf(tmlo, __shfl_xor_sync(0xffffffffu, tmlo, 2));
        tmhi = fmaxf(tmhi, __shfl_xor_sync(0xffffffffu, tmhi, 1));
        tmhi = fmaxf(tmhi, __shfl_xor_sync(0xffffffffu, tmhi, 2));

        const float mnlo = fmaxf(m_lo, tmlo);
        const float mnhi = fmaxf(m_hi, tmhi);
        const float corrlo = __expf(m_lo - mnlo);
        const float corrhi = __expf(m_hi - mnhi);
        m_lo = mnlo; m_hi = mnhi;

        float pslo = 0.f, pshi = 0.f;
#pragma unroll
        for (int nt = 0; nt < 16; nt++) {
            s[nt][0] = __expf(s[nt][0] - mnlo);
            s[nt][1] = __expf(s[nt][1] - mnlo);
            s[nt][2] = __expf(s[nt][2] - mnhi);
            s[nt][3] = __expf(s[nt][3] - mnhi);
            pslo += s[nt][0] + s[nt][1];
            pshi += s[nt][2] + s[nt][3];
        }
        pslo += __shfl_xor_sync(0xffffffffu, pslo, 1);
        pslo += __shfl_xor_sync(0xffffffffu, pslo, 2);
        pshi += __shfl_xor_sync(0xffffffffu, pshi, 1);
        pshi += __shfl_xor_sync(0xffffffffu, pshi, 2);
        l_lo = l_lo * corrlo + pslo;
        l_hi = l_hi * corrhi + pshi;

#pragma unroll
        for (int nt = 0; nt < 8; nt++) {
            o[nt][0] *= corrlo; o[nt][1] *= corrlo;
            o[nt][2] *= corrhi; o[nt][3] *= corrhi;
        }

#pragma unroll
        for (int t8 = 0; t8 < 8; t8++) {
            uint32_t ah[4], al[4];
#pragma unroll
            for (int half = 0; half < 2; half++) {
                const float p0 = s[2 * t8 + half][0];
                const float p1 = s[2 * t8 + half][1];
                const float p2 = s[2 * t8 + half][2];
                const float p3 = s[2 * t8 + half][3];
                const __nv_bfloat16 h0 = __float2bfloat16(p0);
                const __nv_bfloat16 h1 = __float2bfloat16(p1);
                const __nv_bfloat16 h2 = __float2bfloat16(p2);
                const __nv_bfloat16 h3 = __float2bfloat16(p3);
                ah[half * 2 + 0] = pk2(__bfloat162float(h0), __bfloat162float(h1));
                ah[half * 2 + 1] = pk2(__bfloat162float(h2), __bfloat162float(h3));
                al[half * 2 + 0] = pk2(p0 - __bfloat162float(h0),
                                       p1 - __bfloat162float(h1));
                al[half * 2 + 1] = pk2(p2 - __bfloat162float(h2),
                                       p3 - __bfloat162float(h3));
            }

            const uint32_t va = stg + 2 * ATT_MAT +
                ((lane & 7) + 8 * ((lane >> 3) & 1) + t8 * 16) * ATT_LD +
                ((lane >> 4) & 1) * 16;
            uint32_t vh[4][4], vl[4][4];
#pragma unroll
            for (int nt2 = 0; nt2 < 4; nt2++) {
                ldsm_x4t(vh[nt2], va + nt2 * 32);
                ldsm_x4t(vl[nt2], va + ATT_MAT + nt2 * 32);
            }
#pragma unroll
            for (int nt2 = 0; nt2 < 4; nt2++) {
                mma16816(o[2 * nt2],     ah, vh[nt2]);
                mma16816(o[2 * nt2 + 1], ah, vh[nt2] + 2);
            }
#pragma unroll
            for (int nt2 = 0; nt2 < 4; nt2++) {
                mma16816(o[2 * nt2],     ah, vl[nt2]);
                mma16816(o[2 * nt2 + 1], ah, vl[nt2] + 2);
            }
#pragma unroll
            for (int nt2 = 0; nt2 < 4; nt2++) {
                mma16816(o[2 * nt2],     al, vh[nt2]);
                mma16816(o[2 * nt2 + 1], al, vh[nt2] + 2);
            }
        }
        __syncthreads();
    }
#undef LOAD_STAGE_ATT

    const float invlo = 1.f / l_lo;
    const float invhi = 1.f / l_hi;
    const size_t rlo = rowbase + q0 + wid * 16 + (lane >> 2);
    const int colb = h * D_ + (lane & 3) * 2;
#pragma unroll
    for (int nt = 0; nt < 8; nt++) {
        const int col = colb + nt * 8;
        {
            const float v0 = o[nt][0] * invlo, v1 = o[nt][1] * invlo;
            const __nv_bfloat16 h0 = __float2bfloat16(v0);
            const __nv_bfloat16 h1 = __float2bfloat16(v1);
            const size_t off = rlo * C_ + col;
            *reinterpret_cast<uint32_t*>(ohi + off) =
                pk2(__bfloat162float(h0), __bfloat162float(h1));
            *reinterpret_cast<uint32_t*>(olo + off) =
                pk2(v0 - __bfloat162float(h0), v1 - __bfloat162float(h1));
        }
        {
            const float v0 = o[nt][2] * invhi, v1 = o[nt][3] * invhi;
            const __nv_bfloat16 h0 = __float2bfloat16(v0);
            const __nv_bfloat16 h1 = __float2bfloat16(v1);
            const size_t off = (rlo + 8) * C_ + col;
            *reinterpret_cast<uint32_t*>(ohi + off) =
                pk2(__bfloat162float(h0), __bfloat162float(h1));
            *reinterpret_cast<uint32_t*>(olo + off) =
                pk2(v0 - __bfloat162float(h0), v1 - __bfloat162float(h1));
        }
    }
}

// ----------------------------- launch -------------------------------------
extern "C" void kernel_launch(void* const* d_in, const int* in_sizes, int n_in,
                              void* d_out, int out_size) {
    const float* x      = (const float*)d_in[0];
    const float* w_qkv  = (const float*)d_in[1];
    const float* w_proj = (const float*)d_in[2];
    const float* b_proj = (const float*)d_in[3];
    float* out = (float*)d_out;

    __nv_bfloat16 *xhi, *xlo, *whiT, *wloT, *phiT, *ploT;
    __nv_bfloat16 *qhi, *qlo, *ahi, *alo;
    cudaGetSymbolAddress((void**)&xhi,  g_xhi);
    cudaGetSymbolAddress((void**)&xlo,  g_xlo);
    cudaGetSymbolAddress((void**)&whiT, g_whiT);
    cudaGetSymbolAddress((void**)&wloT, g_wloT);
    cudaGetSymbolAddress((void**)&phiT, g_phiT);
    cudaGetSymbolAddress((void**)&ploT, g_ploT);
    cudaGetSymbolAddress((void**)&qhi,  g_qkvhi);
    cudaGetSymbolAddress((void**)&qlo,  g_qkvlo);
    cudaGetSymbolAddress((void**)&ahi,  g_ahi);
    cudaGetSymbolAddress((void**)&alo,  g_alo);

    cudaFuncSetAttribute((const void*)mma_gemm<false, true>,
                         cudaFuncAttributeMaxDynamicSharedMemorySize, GEMM_SMEM);
    cudaFuncSetAttribute((const void*)mma_gemm<true, false>,
                         cudaFuncAttributeMaxDynamicSharedMemorySize, GEMM_SMEM);
    cudaFuncSetAttribute((const void*)attn_mma,
                         cudaFuncAttributeMaxDynamicSharedMemorySize, ATT_SMEM);

    // 0) splits
    {
        int n4 = (M_ * C_) / 4;
        split_ew<<<(n4 + 255) / 256, 256>>>((const float4*)x, xhi, xlo, n4);
        dim3 blk(32, 8);
        dim3 g1(QKVC_ / 32, C_ / 32);
        split_transpose<<<g1, blk>>>(w_qkv, whiT, wloT, C_, QKVC_);
        dim3 g2(C_ / 32, C_ / 32);
        split_transpose<<<g2, blk>>>(w_proj, phiT, ploT, C_, C_);
    }
    // 1) QKV projection -> split bf16, Q pre-scaled by 0.125
    {
        dim3 grid(QKVC_ / 128, M_ / 128);
        mma_gemm<false, true><<<grid, 256, GEMM_SMEM>>>(
            xhi, xlo, whiT, wloT, nullptr, nullptr, qhi, qlo, C_, QKVC_, C_);
    }
    // 2) attention (tensor cores) -> split bf16 output
    {
        dim3 grid(N_ / 128, B_ * H_);
        attn_mma<<<grid, 256, ATT_SMEM>>>(qhi, qlo, ahi, alo);
    }
    // 3) output projection + bias -> fp32 out
    {
        dim3 grid(C_ / 128, M_ / 128);
        mma_gemm<true, false><<<grid, 256, GEMM_SMEM>>>(
            ahi, alo, phiT, ploT, b_proj, out, nullptr, nullptr, 0, C_, C_);
    }
}

// round 9
// speedup vs baseline: 1.2559x; 1.1968x over previous
#include <cuda_runtime.h>
#include <cuda_fp16.h>
#include <math.h>
#include <stdint.h>

#define B_ 8
#define N_ 1024
#define C_ 768
#define H_ 12
#define D_ 64
#define QKVC_ (3 * C_)
#define M_ (B_ * N_)

// ----------------------------- scratch ------------------------------------
__device__ __half g_xhi[M_ * C_];
__device__ __half g_whiT[QKVC_ * C_], g_wloT[QKVC_ * C_];
__device__ __half g_phiT[C_ * C_],    g_ploT[C_ * C_];
__device__ __half g_qkvhi[M_ * QKVC_], g_qkvlo[M_ * QKVC_];
__device__ __half g_ahi[M_ * C_];

// ----------------------------- helpers ------------------------------------
__device__ __forceinline__ uint32_t smem_u32(const void* p) {
    uint32_t a;
    asm("{ .reg .u64 t; cvta.to.shared.u64 t, %1; cvt.u32.u64 %0, t; }"
        : "=r"(a) : "l"(p));
    return a;
}
__device__ __forceinline__ void cp16(uint32_t s, const void* g) {
    asm volatile("cp.async.cg.shared.global [%0], [%1], 16;"
                 :: "r"(s), "l"(g) : "memory");
}
#define CP_COMMIT() asm volatile("cp.async.commit_group;" ::: "memory")
#define CP_WAIT(n)  asm volatile("cp.async.wait_group %0;" :: "n"(n) : "memory")

__device__ __forceinline__ void ldsm_x4(uint32_t* f, uint32_t a) {
    asm volatile("ldmatrix.sync.aligned.m8n8.x4.shared.b16 {%0,%1,%2,%3}, [%4];"
                 : "=r"(f[0]), "=r"(f[1]), "=r"(f[2]), "=r"(f[3]) : "r"(a));
}
__device__ __forceinline__ void ldsm_x4t(uint32_t* f, uint32_t a) {
    asm volatile("ldmatrix.sync.aligned.m8n8.x4.trans.shared.b16 {%0,%1,%2,%3}, [%4];"
                 : "=r"(f[0]), "=r"(f[1]), "=r"(f[2]), "=r"(f[3]) : "r"(a));
}
__device__ __forceinline__ void ldsm_x2(uint32_t* f, uint32_t a) {
    asm volatile("ldmatrix.sync.aligned.m8n8.x2.shared.b16 {%0,%1}, [%2];"
                 : "=r"(f[0]), "=r"(f[1]) : "r"(a));
}
// fp16 inputs, fp32 accumulate
__device__ __forceinline__ void mma16816(float* d, const uint32_t* a,
                                         const uint32_t* b) {
    asm volatile(
        "mma.sync.aligned.m16n8k16.row.col.f32.f16.f16.f32 "
        "{%0,%1,%2,%3}, {%4,%5,%6,%7}, {%8,%9}, {%0,%1,%2,%3};"
        : "+f"(d[0]), "+f"(d[1]), "+f"(d[2]), "+f"(d[3])
        : "r"(a[0]), "r"(a[1]), "r"(a[2]), "r"(a[3]), "r"(b[0]), "r"(b[1]));
}
__device__ __forceinline__ uint32_t pk2h(float f0, float f1) {
    __half2 h = __floats2half2_rn(f0, f1);
    return *reinterpret_cast<uint32_t*>(&h);
}

// ----------------------------- prep kernels --------------------------------
// x -> fp16 hi only (2-pass QKV drops x-lo)
__global__ void convert_hi(const float4* __restrict__ s,
                           __half* __restrict__ hi, int n4) {
    int i = blockIdx.x * blockDim.x + threadIdx.x;
    if (i >= n4) return;
    float4 v = s[i];
    __align__(8) __half h[4];
    h[0] = __float2half_rn(v.x); h[1] = __float2half_rn(v.y);
    h[2] = __float2half_rn(v.z); h[3] = __float2half_rn(v.w);
    *reinterpret_cast<uint2*>(hi + (size_t)i * 4) = *reinterpret_cast<uint2*>(h);
}

// w[K,N] -> hi/lo transposed [N,K], pre-scaled by 32 (keeps lo in fp16 normals)
__global__ void split_transpose(const float* __restrict__ w,
                                __half* __restrict__ hiT,
                                __half* __restrict__ loT, int K, int N) {
    __shared__ float t[32][33];
    const int n0 = blockIdx.x * 32, k0 = blockIdx.y * 32;
    for (int r = threadIdx.y; r < 32; r += 8)
        t[r][threadIdx.x] = w[(size_t)(k0 + r) * N + n0 + threadIdx.x];
    __syncthreads();
    for (int r = threadIdx.y; r < 32; r += 8) {
        float v = t[threadIdx.x][r] * 32.0f;
        __half h = __float2half_rn(v);
        __half l = __float2half_rn(v - __half2float(h));
        size_t o = (size_t)(n0 + r) * K + k0 + threadIdx.x;
        hiT[o] = h; loT[o] = l;
    }
}

// ----------------------------- mma.sync GEMM (2-pass fp16) -----------------
// C = Ahi @ (Bhi + Blo)^T, B pre-scaled x32, epilogue x(1/32).
// 256 thr, 8 warps 2x4, warp tile 64x32, BK=32, 2-stage, 2 CTAs/SM.
#define BK_ 32
#define LROW_ 80
#define MATB_ (128 * LROW_)              // 10240
#define STGB_ (3 * MATB_)                // 30720
#define GEMM_SMEM (2 * STGB_)            // 61440

template <bool BIAS, bool SPLITOUT>
__global__ __launch_bounds__(256, 2)
void mma_gemm(const __half* __restrict__ Ahi,
              const __half* __restrict__ BhiT,
              const __half* __restrict__ BloT,
              const float* __restrict__ bias,
              float* __restrict__ Cf,
              __half* __restrict__ Chi,
              __half* __restrict__ Clo,
              int scale_cols, int Nn, int K) {
    extern __shared__ char smem[];
    const uint32_t sb = smem_u32(smem);
    const int tid = threadIdx.x;
    const int wid = tid >> 5;
    const int lane = tid & 31;
    const int row0 = blockIdx.y * 128;
    const int col0 = blockIdx.x * 128;
    const int wm = (wid >> 2) * 64;
    const int wn = (wid & 3) * 32;

    float acc[4][4][4];
#pragma unroll
    for (int i = 0; i < 4; i++)
#pragma unroll
        for (int j = 0; j < 4; j++)
#pragma unroll
            for (int k = 0; k < 4; k++) acc[i][j][k] = 0.f;

#define LOAD_STAGE(cc, ss)                                                   \
    {                                                                        \
        const uint32_t base = sb + (ss) * STGB_;                             \
        const int k0 = (cc) * BK_;                                           \
        _Pragma("unroll")                                                    \
        for (int t = 0; t < 6; t++) {                                        \
            const int idx = tid + t * 256;                                   \
            const int mat = idx >> 9, rem = idx & 511;                       \
            const int r = rem >> 2, ch = rem & 3;                            \
            const uint32_t off = (uint32_t)(mat * MATB_ + r * LROW_ + ch * 16); \
            const __half* src;                                               \
            if (mat == 0)      src = Ahi  + (size_t)(row0 + r) * K + k0 + ch * 8; \
            else if (mat == 1) src = BhiT + (size_t)(col0 + r) * K + k0 + ch * 8; \
            else               src = BloT + (size_t)(col0 + r) * K + k0 + ch * 8; \
            cp16(base + off, src);                                           \
        }                                                                    \
        CP_COMMIT();                                                         \
    }

    const int nch = K / BK_;    // 24
    LOAD_STAGE(0, 0);

    for (int c = 0; c < nch; c++) {
        const int cur = c & 1;
        if (c + 1 < nch) {
            LOAD_STAGE(c + 1, 1 - cur);
            CP_WAIT(1);
        } else {
            CP_WAIT(0);
        }
        __syncthreads();

        const uint32_t stg = sb + cur * STGB_;
#pragma unroll
        for (int kk = 0; kk < 2; kk++) {
            uint32_t ah[4][4], bh[4][2], bl[4][2];
            const uint32_t acol = (uint32_t)((kk * 16 + (lane >> 4) * 8) * 2);
            const uint32_t bcol =
                (uint32_t)((kk * 16 + ((lane >> 3) & 1) * 8) * 2);
#pragma unroll
            for (int mt = 0; mt < 4; mt++) {
                const uint32_t arow =
                    (uint32_t)((wm + mt * 16 + (lane & 15)) * LROW_);
                ldsm_x4(ah[mt], stg + arow + acol);
            }
#pragma unroll
            for (int nt = 0; nt < 4; nt++) {
                const uint32_t brow =
                    (uint32_t)((wn + nt * 8 + (lane & 7)) * LROW_);
                ldsm_x2(bh[nt], stg + MATB_ + brow + bcol);
                ldsm_x2(bl[nt], stg + 2 * MATB_ + brow + bcol);
            }
            // pass-major: 2 passes (hi, lo)
#pragma unroll
            for (int mt = 0; mt < 4; mt++)
#pragma unroll
                for (int nt = 0; nt < 4; nt++)
                    mma16816(acc[mt][nt], ah[mt], bh[nt]);
#pragma unroll
            for (int mt = 0; mt < 4; mt++)
#pragma unroll
                for (int nt = 0; nt < 4; nt++)
                    mma16816(acc[mt][nt], ah[mt], bl[nt]);
        }
        __syncthreads();
    }
#undef LOAD_STAGE

    const float wsc = 0.03125f;   // 1/32 (w pre-scaled x32)
    const int g = lane >> 2, t4 = lane & 3;
#pragma unroll
    for (int nt = 0; nt < 4; nt++) {
        const int col = col0 + wn + nt * 8 + t4 * 2;
        if (SPLITOUT) {
            const float sc = ((col < scale_cols) ? 0.125f : 1.0f) * wsc;
#pragma unroll
            for (int mt = 0; mt < 4; mt++) {
                const int ra = row0 + wm + mt * 16 + g;
#pragma unroll
                for (int half = 0; half < 2; half++) {
                    const int r = ra + half * 8;
                    const float v0 = acc[mt][nt][half * 2 + 0] * sc;
                    const float v1 = acc[mt][nt][half * 2 + 1] * sc;
                    const __half h0 = __float2half_rn(v0);
                    const __half h1 = __float2half_rn(v1);
                    const float l0 = v0 - __half2float(h0);
                    const float l1 = v1 - __half2float(h1);
                    const size_t off = (size_t)r * Nn + col;
                    *reinterpret_cast<uint32_t*>(Chi + off) =
                        pk2h(__half2float(h0), __half2float(h1));
                    *reinterpret_cast<uint32_t*>(Clo + off) = pk2h(l0, l1);
                }
            }
        } else {
            float b0 = 0.f, b1 = 0.f;
            if (BIAS) { b0 = bias[col]; b1 = bias[col + 1]; }
#pragma unroll
            for (int mt = 0; mt < 4; mt++) {
                const int ra = row0 + wm + mt * 16 + g;
                float2 v0 = make_float2(acc[mt][nt][0] * wsc + b0,
                                        acc[mt][nt][1] * wsc + b1);
                float2 v1 = make_float2(acc[mt][nt][2] * wsc + b0,
                                        acc[mt][nt][3] * wsc + b1);
                *reinterpret_cast<float2*>(&Cf[(size_t)ra * Nn + col]) = v0;
                *reinterpret_cast<float2*>(&Cf[(size_t)(ra + 8) * Nn + col]) = v1;
            }
        }
    }
}

// ----------------------------- mma flash attention (3-pass fp16) -----------
// P scaled x1024 (l scaled identically; O/l invariant) to keep P-lo normal.
// Output: hi-only fp16 (proj is 2-pass; a-lo dropped by design).
#define ATT_LD 144
#define ATT_MAT 18432
#define ATT_STG0 (2 * ATT_MAT)
#define ATT_STGSZ (4 * ATT_MAT)
#define ATT_SMEM (ATT_STG0 + 2 * ATT_STGSZ)  // 184320

__global__ __launch_bounds__(256, 1)
void attn_mma(const __half* __restrict__ qhi,
              const __half* __restrict__ qlo,
              __half* __restrict__ ohi) {
    extern __shared__ char smem[];
    const uint32_t sb = smem_u32(smem);
    const int tid = threadIdx.x, wid = tid >> 5, lane = tid & 31;
    const int b = blockIdx.y / H_, h = blockIdx.y % H_;
    const int q0 = blockIdx.x * 128;
    const size_t rowbase = (size_t)b * N_;

#pragma unroll
    for (int t = 0; t < 8; t++) {
        const int idx = tid + t * 256;
        const int mat = idx >> 10, rem = idx & 1023;
        const int r = rem >> 3, c = rem & 7;
        const uint32_t so = sb + mat * ATT_MAT + r * ATT_LD + c * 16;
        const __half* src =
            (mat ? qlo : qhi) + ((rowbase + q0 + r) * QKVC_ + h * D_ + c * 8);
        cp16(so, src);
    }

#define LOAD_STAGE_ATT(ktile, ss)                                            \
    {                                                                        \
        const uint32_t base = sb + ATT_STG0 + (ss) * ATT_STGSZ;              \
        const size_t krow = rowbase + (ktile) * 128;                         \
        _Pragma("unroll")                                                    \
        for (int t = 0; t < 16; t++) {                                       \
            const int idx = tid + t * 256;                                   \
            const int mat = idx >> 10, rem = idx & 1023;                     \
            const int r = rem >> 3, c = rem & 7;                             \
            const uint32_t so = base + mat * ATT_MAT + r * ATT_LD + c * 16;  \
            const __half* sp = ((mat & 1) ? qlo : qhi) +                     \
                ((krow + r) * QKVC_ + ((mat >> 1) ? 2 * C_ : C_) +           \
                 h * D_ + c * 8);                                            \
            cp16(so, sp);                                                    \
        }                                                                    \
        CP_COMMIT();                                                         \
    }

    LOAD_STAGE_ATT(0, 0);

    float m_lo = -INFINITY, m_hi = -INFINITY, l_lo = 0.f, l_hi = 0.f;
    float o[8][4];
#pragma unroll
    for (int i = 0; i < 8; i++)
#pragma unroll
        for (int j = 0; j < 4; j++) o[i][j] = 0.f;

    const uint32_t qa =
        sb + (wid * 16 + (lane & 15)) * ATT_LD + ((lane >> 4) * 8) * 2;

    for (int kt = 0; kt < N_ / 128; kt++) {
        if (kt + 1 < N_ / 128) {
            LOAD_STAGE_ATT(kt + 1, (kt + 1) & 1);
            CP_WAIT(1);
        } else {
            CP_WAIT(0);
        }
        __syncthreads();

        const uint32_t stg = sb + ATT_STG0 + (kt & 1) * ATT_STGSZ;

        float s[16][4];
#pragma unroll
        for (int nt = 0; nt < 16; nt++)
#pragma unroll
            for (int j = 0; j < 4; j++) s[nt][j] = 0.f;

#pragma unroll
        for (int k4 = 0; k4 < 4; k4++) {
            uint32_t qh[4], ql[4];
            ldsm_x4(qh, qa + k4 * 32);
            ldsm_x4(ql, qa + ATT_MAT + k4 * 32);
            const uint32_t ka = stg + (lane & 7) * ATT_LD +
                                (k4 * 16 + ((lane >> 3) & 1) * 8) * 2;
#pragma unroll
            for (int blk = 0; blk < 2; blk++) {
                uint32_t kh[8][2], kl[8][2];
#pragma unroll
                for (int j = 0; j < 8; j++) {
                    const int nt = blk * 8 + j;
                    ldsm_x2(kh[j], ka + nt * 8 * ATT_LD);
                    ldsm_x2(kl[j], ka + ATT_MAT + nt * 8 * ATT_LD);
                }
#pragma unroll
                for (int j = 0; j < 8; j++)
                    mma16816(s[blk * 8 + j], qh, kh[j]);
#pragma unroll
                for (int j = 0; j < 8; j++)
                    mma16816(s[blk * 8 + j], qh, kl[j]);
#pragma unroll
                for (int j = 0; j < 8; j++)
                    mma16816(s[blk * 8 + j], ql, kh[j]);
            }
        }

        float tmlo = -INFINITY, tmhi = -INFINITY;
#pragma unroll
        for (int nt = 0; nt < 16; nt++) {
            tmlo = fmaxf(tmlo, fmaxf(s[nt][0], s[nt][1]));
            tmhi = fmaxf(tmhi, fmaxf(s[nt][2], s[nt][3]));
        }
        tmlo = fmaxf(tmlo, __shfl_xor_sync(0xffffffffu, tmlo, 1));
        tmlo = fmaxf(tmlo, __shfl_xor_sync(0xffffffffu, tmlo, 2));
        tmhi = fmaxf(tmhi, __shfl_xor_sync(0xffffffffu, tmhi, 1));
        tmhi = fmaxf(tmhi, __shfl_xor_sync(0xffffffffu, tmhi, 2));

        const float mnlo = fmaxf(m_lo, tmlo);
        const float mnhi = fmaxf(m_hi, tmhi);
        const float corrlo = __expf(m_lo - mnlo);
        const float corrhi = __expf(m_hi - mnhi);
        m_lo = mnlo; m_hi = mnhi;

        float pslo = 0.f, pshi = 0.f;
#pragma unroll
        for (int nt = 0; nt < 16; nt++) {
            // exp scaled by 1024 (exact pow2) so P-lo stays in fp16 normals
            s[nt][0] = __expf(s[nt][0] - mnlo) * 1024.f;
            s[nt][1] = __expf(s[nt][1] - mnlo) * 1024.f;
            s[nt][2] = __expf(s[nt][2] - mnhi) * 1024.f;
            s[nt][3] = __expf(s[nt][3] - mnhi) * 1024.f;
            pslo += s[nt][0] + s[nt][1];
            pshi += s[nt][2] + s[nt][3];
        }
        pslo += __shfl_xor_sync(0xffffffffu, pslo, 1);
        pslo += __shfl_xor_sync(0xffffffffu, pslo, 2);
        pshi += __shfl_xor_sync(0xffffffffu, pshi, 1);
        pshi += __shfl_xor_sync(0xffffffffu, pshi, 2);
        l_lo = l_lo * corrlo + pslo;
        l_hi = l_hi * corrhi + pshi;

#pragma unroll
        for (int nt = 0; nt < 8; nt++) {
            o[nt][0] *= corrlo; o[nt][1] *= corrlo;
            o[nt][2] *= corrhi; o[nt][3] *= corrhi;
        }

#pragma unroll
        for (int t8 = 0; t8 < 8; t8++) {
            uint32_t ah[4], al[4];
#pragma unroll
            for (int half = 0; half < 2; half++) {
                const float p0 = s[2 * t8 + half][0];
                const float p1 = s[2 * t8 + half][1];
                const float p2 = s[2 * t8 + half][2];
                const float p3 = s[2 * t8 + half][3];
                const __half h0 = __float2half_rn(p0);
                const __half h1 = __float2half_rn(p1);
                const __half h2 = __float2half_rn(p2);
                const __half h3 = __float2half_rn(p3);
                ah[half * 2 + 0] = pk2h(__half2float(h0), __half2float(h1));
                ah[half * 2 + 1] = pk2h(__half2float(h2), __half2float(h3));
                al[half * 2 + 0] = pk2h(p0 - __half2float(h0),
                                        p1 - __half2float(h1));
                al[half * 2 + 1] = pk2h(p2 - __half2float(h2),
                                        p3 - __half2float(h3));
            }

            const uint32_t va = stg + 2 * ATT_MAT +
                ((lane & 7) + 8 * ((lane >> 3) & 1) + t8 * 16) * ATT_LD +
                ((lane >> 4) & 1) * 16;
            uint32_t vh[4][4], vl[4][4];
#pragma unroll
            for (int nt2 = 0; nt2 < 4; nt2++) {
                ldsm_x4t(vh[nt2], va + nt2 * 32);
                ldsm_x4t(vl[nt2], va + ATT_MAT + nt2 * 32);
            }
#pragma unroll
            for (int nt2 = 0; nt2 < 4; nt2++) {
                mma16816(o[2 * nt2],     ah, vh[nt2]);
                mma16816(o[2 * nt2 + 1], ah, vh[nt2] + 2);
            }
#pragma unroll
            for (int nt2 = 0; nt2 < 4; nt2++) {
                mma16816(o[2 * nt2],     ah, vl[nt2]);
                mma16816(o[2 * nt2 + 1], ah, vl[nt2] + 2);
            }
#pragma unroll
            for (int nt2 = 0; nt2 < 4; nt2++) {
                mma16816(o[2 * nt2],     al, vh[nt2]);
                mma16816(o[2 * nt2 + 1], al, vh[nt2] + 2);
            }
        }
        __syncthreads();
    }
#undef LOAD_STAGE_ATT

    // normalize + store hi-only fp16 (a-lo dropped: proj is 2-pass)
    const float invlo = 1.f / l_lo;
    const float invhi = 1.f / l_hi;
    const size_t rlo = rowbase + q0 + wid * 16 + (lane >> 2);
    const int colb = h * D_ + (lane & 3) * 2;
#pragma unroll
    for (int nt = 0; nt < 8; nt++) {
        const int col = colb + nt * 8;
        *reinterpret_cast<uint32_t*>(ohi + rlo * C_ + col) =
            pk2h(o[nt][0] * invlo, o[nt][1] * invlo);
        *reinterpret_cast<uint32_t*>(ohi + (rlo + 8) * C_ + col) =
            pk2h(o[nt][2] * invhi, o[nt][3] * invhi);
    }
}

// ----------------------------- launch -------------------------------------
extern "C" void kernel_launch(void* const* d_in, const int* in_sizes, int n_in,
                              void* d_out, int out_size) {
    const float* x      = (const float*)d_in[0];
    const float* w_qkv  = (const float*)d_in[1];
    const float* w_proj = (const float*)d_in[2];
    const float* b_proj = (const float*)d_in[3];
    float* out = (float*)d_out;

    __half *xhi, *whiT, *wloT, *phiT, *ploT, *qhi, *qlo, *ahi;
    cudaGetSymbolAddress((void**)&xhi,  g_xhi);
    cudaGetSymbolAddress((void**)&whiT, g_whiT);
    cudaGetSymbolAddress((void**)&wloT, g_wloT);
    cudaGetSymbolAddress((void**)&phiT, g_phiT);
    cudaGetSymbolAddress((void**)&ploT, g_ploT);
    cudaGetSymbolAddress((void**)&qhi,  g_qkvhi);
    cudaGetSymbolAddress((void**)&qlo,  g_qkvlo);
    cudaGetSymbolAddress((void**)&ahi,  g_ahi);

    cudaFuncSetAttribute((const void*)mma_gemm<false, true>,
                         cudaFuncAttributeMaxDynamicSharedMemorySize, GEMM_SMEM);
    cudaFuncSetAttribute((const void*)mma_gemm<true, false>,
                         cudaFuncAttributeMaxDynamicSharedMemorySize, GEMM_SMEM);
    cudaFuncSetAttribute((const void*)attn_mma,
                         cudaFuncAttributeMaxDynamicSharedMemorySize, ATT_SMEM);

    // 0) prep: x -> fp16 hi; weights -> x32, split-transpose fp16 hi/lo
    {
        int n4 = (M_ * C_) / 4;
        convert_hi<<<(n4 + 255) / 256, 256>>>((const float4*)x, xhi, n4);
        dim3 blk(32, 8);
        dim3 g1(QKVC_ / 32, C_ / 32);
        split_transpose<<<g1, blk>>>(w_qkv, whiT, wloT, C_, QKVC_);
        dim3 g2(C_ / 32, C_ / 32);
        split_transpose<<<g2, blk>>>(w_proj, phiT, ploT, C_, C_);
    }
    // 1) QKV projection (2-pass) -> split fp16, Q pre-scaled by 0.125
    {
        dim3 grid(QKVC_ / 128, M_ / 128);
        mma_gemm<false, true><<<grid, 256, GEMM_SMEM>>>(
            xhi, whiT, wloT, nullptr, nullptr, qhi, qlo, C_, QKVC_, C_);
    }
    // 2) attention (3-pass) -> fp16 hi output
    {
        dim3 grid(N_ / 128, B_ * H_);
        attn_mma<<<grid, 256, ATT_SMEM>>>(qhi, qlo, ahi);
    }
    // 3) output projection + bias (2-pass) -> fp32 out
    {
        dim3 grid(C_ / 128, M_ / 128);
        mma_gemm<true, false><<<grid, 256, GEMM_SMEM>>>(
            ahi, phiT, ploT, b_proj, out, nullptr, nullptr, 0, C_, C_);
    }
}

// round 10
// speedup vs baseline: 1.4219x; 1.1322x over previous
#include <cuda_runtime.h>
#include <cuda_fp16.h>
#include <math.h>
#include <stdint.h>

#define B_ 8
#define N_ 1024
#define C_ 768
#define H_ 12
#define D_ 64
#define QKVC_ (3 * C_)
#define M_ (B_ * N_)

// ----------------------------- scratch ------------------------------------
__device__ __half g_xhi[M_ * C_];
__device__ __half g_whiT[QKVC_ * C_], g_wloT[QKVC_ * C_];
__device__ __half g_phiT[C_ * C_],    g_ploT[C_ * C_];
__device__ __half g_qkvhi[M_ * QKVC_], g_qkvlo[M_ * QKVC_];
__device__ __half g_ahi[M_ * C_];

// ----------------------------- helpers ------------------------------------
__device__ __forceinline__ uint32_t smem_u32(const void* p) {
    uint32_t a;
    asm("{ .reg .u64 t; cvta.to.shared.u64 t, %1; cvt.u32.u64 %0, t; }"
        : "=r"(a) : "l"(p));
    return a;
}
__device__ __forceinline__ void cp16(uint32_t s, const void* g) {
    asm volatile("cp.async.cg.shared.global [%0], [%1], 16;"
                 :: "r"(s), "l"(g) : "memory");
}
#define CP_COMMIT() asm volatile("cp.async.commit_group;" ::: "memory")
#define CP_WAIT(n)  asm volatile("cp.async.wait_group %0;" :: "n"(n) : "memory")

__device__ __forceinline__ void ldsm_x4(uint32_t* f, uint32_t a) {
    asm volatile("ldmatrix.sync.aligned.m8n8.x4.shared.b16 {%0,%1,%2,%3}, [%4];"
                 : "=r"(f[0]), "=r"(f[1]), "=r"(f[2]), "=r"(f[3]) : "r"(a));
}
__device__ __forceinline__ void ldsm_x4t(uint32_t* f, uint32_t a) {
    asm volatile("ldmatrix.sync.aligned.m8n8.x4.trans.shared.b16 {%0,%1,%2,%3}, [%4];"
                 : "=r"(f[0]), "=r"(f[1]), "=r"(f[2]), "=r"(f[3]) : "r"(a));
}
__device__ __forceinline__ void ldsm_x2(uint32_t* f, uint32_t a) {
    asm volatile("ldmatrix.sync.aligned.m8n8.x2.shared.b16 {%0,%1}, [%2];"
                 : "=r"(f[0]), "=r"(f[1]) : "r"(a));
}
// fp16 inputs, fp32 accumulate
__device__ __forceinline__ void mma16816(float* d, const uint32_t* a,
                                         const uint32_t* b) {
    asm volatile(
        "mma.sync.aligned.m16n8k16.row.col.f32.f16.f16.f32 "
        "{%0,%1,%2,%3}, {%4,%5,%6,%7}, {%8,%9}, {%0,%1,%2,%3};"
        : "+f"(d[0]), "+f"(d[1]), "+f"(d[2]), "+f"(d[3])
        : "r"(a[0]), "r"(a[1]), "r"(a[2]), "r"(a[3]), "r"(b[0]), "r"(b[1]));
}
__device__ __forceinline__ uint32_t pk2h(float f0, float f1) {
    __half2 h = __floats2half2_rn(f0, f1);
    return *reinterpret_cast<uint32_t*>(&h);
}

// ----------------------------- prep kernels --------------------------------
__global__ void convert_hi(const float4* __restrict__ s,
                           __half* __restrict__ hi, int n4) {
    int i = blockIdx.x * blockDim.x + threadIdx.x;
    if (i >= n4) return;
    float4 v = s[i];
    __align__(8) __half h[4];
    h[0] = __float2half_rn(v.x); h[1] = __float2half_rn(v.y);
    h[2] = __float2half_rn(v.z); h[3] = __float2half_rn(v.w);
    *reinterpret_cast<uint2*>(hi + (size_t)i * 4) = *reinterpret_cast<uint2*>(h);
}

// w[K,N] -> hi/lo transposed [N,K], pre-scaled by 32 (keeps lo in fp16 normals)
__global__ void split_transpose(const float* __restrict__ w,
                                __half* __restrict__ hiT,
                                __half* __restrict__ loT, int K, int N) {
    __shared__ float t[32][33];
    const int n0 = blockIdx.x * 32, k0 = blockIdx.y * 32;
    for (int r = threadIdx.y; r < 32; r += 8)
        t[r][threadIdx.x] = w[(size_t)(k0 + r) * N + n0 + threadIdx.x];
    __syncthreads();
    for (int r = threadIdx.y; r < 32; r += 8) {
        float v = t[threadIdx.x][r] * 32.0f;
        __half h = __float2half_rn(v);
        __half l = __float2half_rn(v - __half2float(h));
        size_t o = (size_t)(n0 + r) * K + k0 + threadIdx.x;
        hiT[o] = h; loT[o] = l;
    }
}

// ----------------------------- mma.sync GEMM (2-pass fp16) -----------------
#define BK_ 32
#define LROW_ 80
#define MATB_ (128 * LROW_)              // 10240
#define STGB_ (3 * MATB_)                // 30720
#define GEMM_SMEM (2 * STGB_)            // 61440

template <bool BIAS, bool SPLITOUT>
__global__ __launch_bounds__(256, 2)
void mma_gemm(const __half* __restrict__ Ahi,
              const __half* __restrict__ BhiT,
              const __half* __restrict__ BloT,
              const float* __restrict__ bias,
              float* __restrict__ Cf,
              __half* __restrict__ Chi,
              __half* __restrict__ Clo,
              int scale_cols, int Nn, int K) {
    extern __shared__ char smem[];
    const uint32_t sb = smem_u32(smem);
    const int tid = threadIdx.x;
    const int wid = tid >> 5;
    const int lane = tid & 31;
    const int row0 = blockIdx.y * 128;
    const int col0 = blockIdx.x * 128;
    const int wm = (wid >> 2) * 64;
    const int wn = (wid & 3) * 32;

    float acc[4][4][4];
#pragma unroll
    for (int i = 0; i < 4; i++)
#pragma unroll
        for (int j = 0; j < 4; j++)
#pragma unroll
            for (int k = 0; k < 4; k++) acc[i][j][k] = 0.f;

#define LOAD_STAGE(cc, ss)                                                   \
    {                                                                        \
        const uint32_t base = sb + (ss) * STGB_;                             \
        const int k0 = (cc) * BK_;                                           \
        _Pragma("unroll")                                                    \
        for (int t = 0; t < 6; t++) {                                        \
            const int idx = tid + t * 256;                                   \
            const int mat = idx >> 9, rem = idx & 511;                       \
            const int r = rem >> 2, ch = rem & 3;                            \
            const uint32_t off = (uint32_t)(mat * MATB_ + r * LROW_ + ch * 16); \
            const __half* src;                                               \
            if (mat == 0)      src = Ahi  + (size_t)(row0 + r) * K + k0 + ch * 8; \
            else if (mat == 1) src = BhiT + (size_t)(col0 + r) * K + k0 + ch * 8; \
            else               src = BloT + (size_t)(col0 + r) * K + k0 + ch * 8; \
            cp16(base + off, src);                                           \
        }                                                                    \
        CP_COMMIT();                                                         \
    }

    const int nch = K / BK_;    // 24
    LOAD_STAGE(0, 0);

    for (int c = 0; c < nch; c++) {
        const int cur = c & 1;
        if (c + 1 < nch) {
            LOAD_STAGE(c + 1, 1 - cur);
            CP_WAIT(1);
        } else {
            CP_WAIT(0);
        }
        __syncthreads();

        const uint32_t stg = sb + cur * STGB_;
#pragma unroll
        for (int kk = 0; kk < 2; kk++) {
            uint32_t ah[4][4], bh[4][2], bl[4][2];
            const uint32_t acol = (uint32_t)((kk * 16 + (lane >> 4) * 8) * 2);
            const uint32_t bcol =
                (uint32_t)((kk * 16 + ((lane >> 3) & 1) * 8) * 2);
#pragma unroll
            for (int mt = 0; mt < 4; mt++) {
                const uint32_t arow =
                    (uint32_t)((wm + mt * 16 + (lane & 15)) * LROW_);
                ldsm_x4(ah[mt], stg + arow + acol);
            }
#pragma unroll
            for (int nt = 0; nt < 4; nt++) {
                const uint32_t brow =
                    (uint32_t)((wn + nt * 8 + (lane & 7)) * LROW_);
                ldsm_x2(bh[nt], stg + MATB_ + brow + bcol);
                ldsm_x2(bl[nt], stg + 2 * MATB_ + brow + bcol);
            }
#pragma unroll
            for (int mt = 0; mt < 4; mt++)
#pragma unroll
                for (int nt = 0; nt < 4; nt++)
                    mma16816(acc[mt][nt], ah[mt], bh[nt]);
#pragma unroll
            for (int mt = 0; mt < 4; mt++)
#pragma unroll
                for (int nt = 0; nt < 4; nt++)
                    mma16816(acc[mt][nt], ah[mt], bl[nt]);
        }
        __syncthreads();
    }
#undef LOAD_STAGE

    const float wsc = 0.03125f;   // 1/32
    const int g = lane >> 2, t4 = lane & 3;
#pragma unroll
    for (int nt = 0; nt < 4; nt++) {
        const int col = col0 + wn + nt * 8 + t4 * 2;
        if (SPLITOUT) {
            const float sc = ((col < scale_cols) ? 0.125f : 1.0f) * wsc;
#pragma unroll
            for (int mt = 0; mt < 4; mt++) {
                const int ra = row0 + wm + mt * 16 + g;
#pragma unroll
                for (int half = 0; half < 2; half++) {
                    const int r = ra + half * 8;
                    const float v0 = acc[mt][nt][half * 2 + 0] * sc;
                    const float v1 = acc[mt][nt][half * 2 + 1] * sc;
                    const __half h0 = __float2half_rn(v0);
                    const __half h1 = __float2half_rn(v1);
                    const float l0 = v0 - __half2float(h0);
                    const float l1 = v1 - __half2float(h1);
                    const size_t off = (size_t)r * Nn + col;
                    *reinterpret_cast<uint32_t*>(Chi + off) =
                        pk2h(__half2float(h0), __half2float(h1));
                    *reinterpret_cast<uint32_t*>(Clo + off) = pk2h(l0, l1);
                }
            }
        } else {
            float b0 = 0.f, b1 = 0.f;
            if (BIAS) { b0 = bias[col]; b1 = bias[col + 1]; }
#pragma unroll
            for (int mt = 0; mt < 4; mt++) {
                const int ra = row0 + wm + mt * 16 + g;
                float2 v0 = make_float2(acc[mt][nt][0] * wsc + b0,
                                        acc[mt][nt][1] * wsc + b1);
                float2 v1 = make_float2(acc[mt][nt][2] * wsc + b0,
                                        acc[mt][nt][3] * wsc + b1);
                *reinterpret_cast<float2*>(&Cf[(size_t)ra * Nn + col]) = v0;
                *reinterpret_cast<float2*>(&Cf[(size_t)(ra + 8) * Nn + col]) = v1;
            }
        }
    }
}

// ----------------------------- mma flash attention (2-pass fp16) -----------
// S = Qhi·(Khi+Klo); O = Phi·(Vhi+Vlo). Q-lo never loaded; P-lo dropped.
// P scaled x1024 (l scaled identically; O/l invariant).
#define ATT_LD 144
#define ATT_MAT 18432
#define ATT_STG0 ATT_MAT                  // Q hi only
#define ATT_STGSZ (4 * ATT_MAT)           // Khi,Klo,Vhi,Vlo
#define ATT_SMEM (ATT_STG0 + 2 * ATT_STGSZ)  // 165888

__global__ __launch_bounds__(256, 1)
void attn_mma(const __half* __restrict__ qhi,
              const __half* __restrict__ qlo,
              __half* __restrict__ ohi) {
    extern __shared__ char smem[];
    const uint32_t sb = smem_u32(smem);
    const int tid = threadIdx.x, wid = tid >> 5, lane = tid & 31;
    const int b = blockIdx.y / H_, h = blockIdx.y % H_;
    const int q0 = blockIdx.x * 128;
    const size_t rowbase = (size_t)b * N_;

    // ---- load Q hi only ----
#pragma unroll
    for (int t = 0; t < 4; t++) {
        const int idx = tid + t * 256;
        const int r = idx >> 3, c = idx & 7;
        cp16(sb + r * ATT_LD + c * 16,
             qhi + ((rowbase + q0 + r) * QKVC_ + h * D_ + c * 8));
    }

#define LOAD_STAGE_ATT(ktile, ss)                                            \
    {                                                                        \
        const uint32_t base = sb + ATT_STG0 + (ss) * ATT_STGSZ;              \
        const size_t krow = rowbase + (ktile) * 128;                         \
        _Pragma("unroll")                                                    \
        for (int t = 0; t < 16; t++) {                                       \
            const int idx = tid + t * 256;                                   \
            const int mat = idx >> 10, rem = idx & 1023;                     \
            const int r = rem >> 3, c = rem & 7;                             \
            const uint32_t so = base + mat * ATT_MAT + r * ATT_LD + c * 16;  \
            const __half* sp = ((mat & 1) ? qlo : qhi) +                     \
                ((krow + r) * QKVC_ + ((mat >> 1) ? 2 * C_ : C_) +           \
                 h * D_ + c * 8);                                            \
            cp16(so, sp);                                                    \
        }                                                                    \
        CP_COMMIT();                                                         \
    }

    LOAD_STAGE_ATT(0, 0);

    float m_lo = -INFINITY, m_hi = -INFINITY, l_lo = 0.f, l_hi = 0.f;
    float o[8][4];
#pragma unroll
    for (int i = 0; i < 8; i++)
#pragma unroll
        for (int j = 0; j < 4; j++) o[i][j] = 0.f;

    const uint32_t qa =
        sb + (wid * 16 + (lane & 15)) * ATT_LD + ((lane >> 4) * 8) * 2;

    for (int kt = 0; kt < N_ / 128; kt++) {
        if (kt + 1 < N_ / 128) {
            LOAD_STAGE_ATT(kt + 1, (kt + 1) & 1);
            CP_WAIT(1);
        } else {
            CP_WAIT(0);
        }
        __syncthreads();

        const uint32_t stg = sb + ATT_STG0 + (kt & 1) * ATT_STGSZ;

        // ---- S = Qhi @ (Khi + Klo)^T ----
        float s[16][4];
#pragma unroll
        for (int nt = 0; nt < 16; nt++)
#pragma unroll
            for (int j = 0; j < 4; j++) s[nt][j] = 0.f;

#pragma unroll
        for (int k4 = 0; k4 < 4; k4++) {
            uint32_t qh[4];
            ldsm_x4(qh, qa + k4 * 32);
            const uint32_t ka = stg + (lane & 7) * ATT_LD +
                                (k4 * 16 + ((lane >> 3) & 1) * 8) * 2;
#pragma unroll
            for (int blk = 0; blk < 2; blk++) {
                uint32_t kh[8][2], kl[8][2];
#pragma unroll
                for (int j = 0; j < 8; j++) {
                    const int nt = blk * 8 + j;
                    ldsm_x2(kh[j], ka + nt * 8 * ATT_LD);
                    ldsm_x2(kl[j], ka + ATT_MAT + nt * 8 * ATT_LD);
                }
#pragma unroll
                for (int j = 0; j < 8; j++)
                    mma16816(s[blk * 8 + j], qh, kh[j]);
#pragma unroll
                for (int j = 0; j < 8; j++)
                    mma16816(s[blk * 8 + j], qh, kl[j]);
            }
        }

        // ---- online softmax ----
        float tmlo = -INFINITY, tmhi = -INFINITY;
#pragma unroll
        for (int nt = 0; nt < 16; nt++) {
            tmlo = fmaxf(tmlo, fmaxf(s[nt][0], s[nt][1]));
            tmhi = fmaxf(tmhi, fmaxf(s[nt][2], s[nt][3]));
        }
        tmlo = fmaxf(tmlo, __shfl_xor_sync(0xffffffffu, tmlo, 1));
        tmlo = fmaxf(tmlo, __shfl_xor_sync(0xffffffffu, tmlo, 2));
        tmhi = fmaxf(tmhi, __shfl_xor_sync(0xffffffffu, tmhi, 1));
        tmhi = fmaxf(tmhi, __shfl_xor_sync(0xffffffffu, tmhi, 2));

        const float mnlo = fmaxf(m_lo, tmlo);
        const float mnhi = fmaxf(m_hi, tmhi);
        const float corrlo = __expf(m_lo - mnlo);
        const float corrhi = __expf(m_hi - mnhi);
        m_lo = mnlo; m_hi = mnhi;

        float pslo = 0.f, pshi = 0.f;
#pragma unroll
        for (int nt = 0; nt < 16; nt++) {
            s[nt][0] = __expf(s[nt][0] - mnlo) * 1024.f;
            s[nt][1] = __expf(s[nt][1] - mnlo) * 1024.f;
            s[nt][2] = __expf(s[nt][2] - mnhi) * 1024.f;
            s[nt][3] = __expf(s[nt][3] - mnhi) * 1024.f;
            pslo += s[nt][0] + s[nt][1];
            pshi += s[nt][2] + s[nt][3];
        }
        pslo += __shfl_xor_sync(0xffffffffu, pslo, 1);
        pslo += __shfl_xor_sync(0xffffffffu, pslo, 2);
        pshi += __shfl_xor_sync(0xffffffffu, pshi, 1);
        pshi += __shfl_xor_sync(0xffffffffu, pshi, 2);
        l_lo = l_lo * corrlo + pslo;
        l_hi = l_hi * corrhi + pshi;

#pragma unroll
        for (int nt = 0; nt < 8; nt++) {
            o[nt][0] *= corrlo; o[nt][1] *= corrlo;
            o[nt][2] *= corrhi; o[nt][3] *= corrhi;
        }

        // ---- O += Phi @ (Vhi + Vlo) ----
#pragma unroll
        for (int t8 = 0; t8 < 8; t8++) {
            uint32_t ah[4];
#pragma unroll
            for (int half = 0; half < 2; half++) {
                ah[half * 2 + 0] = pk2h(s[2 * t8 + half][0],
                                        s[2 * t8 + half][1]);
                ah[half * 2 + 1] = pk2h(s[2 * t8 + half][2],
                                        s[2 * t8 + half][3]);
            }

            const uint32_t va = stg + 2 * ATT_MAT +
                ((lane & 7) + 8 * ((lane >> 3) & 1) + t8 * 16) * ATT_LD +
                ((lane >> 4) & 1) * 16;
            uint32_t vh[4][4], vl[4][4];
#pragma unroll
            for (int nt2 = 0; nt2 < 4; nt2++) {
                ldsm_x4t(vh[nt2], va + nt2 * 32);
                ldsm_x4t(vl[nt2], va + ATT_MAT + nt2 * 32);
            }
#pragma unroll
            for (int nt2 = 0; nt2 < 4; nt2++) {
                mma16816(o[2 * nt2],     ah, vh[nt2]);
                mma16816(o[2 * nt2 + 1], ah, vh[nt2] + 2);
            }
#pragma unroll
            for (int nt2 = 0; nt2 < 4; nt2++) {
                mma16816(o[2 * nt2],     ah, vl[nt2]);
                mma16816(o[2 * nt2 + 1], ah, vl[nt2] + 2);
            }
        }
        __syncthreads();
    }
#undef LOAD_STAGE_ATT

    // normalize + store hi-only fp16
    const float invlo = 1.f / l_lo;
    const float invhi = 1.f / l_hi;
    const size_t rlo = rowbase + q0 + wid * 16 + (lane >> 2);
    const int colb = h * D_ + (lane & 3) * 2;
#pragma unroll
    for (int nt = 0; nt < 8; nt++) {
        const int col = colb + nt * 8;
        *reinterpret_cast<uint32_t*>(ohi + rlo * C_ + col) =
            pk2h(o[nt][0] * invlo, o[nt][1] * invlo);
        *reinterpret_cast<uint32_t*>(ohi + (rlo + 8) * C_ + col) =
            pk2h(o[nt][2] * invhi, o[nt][3] * invhi);
    }
}

// ----------------------------- launch -------------------------------------
extern "C" void kernel_launch(void* const* d_in, const int* in_sizes, int n_in,
                              void* d_out, int out_size) {
    const float* x      = (const float*)d_in[0];
    const float* w_qkv  = (const float*)d_in[1];
    const float* w_proj = (const float*)d_in[2];
    const float* b_proj = (const float*)d_in[3];
    float* out = (float*)d_out;

    __half *xhi, *whiT, *wloT, *phiT, *ploT, *qhi, *qlo, *ahi;
    cudaGetSymbolAddress((void**)&xhi,  g_xhi);
    cudaGetSymbolAddress((void**)&whiT, g_whiT);
    cudaGetSymbolAddress((void**)&wloT, g_wloT);
    cudaGetSymbolAddress((void**)&phiT, g_phiT);
    cudaGetSymbolAddress((void**)&ploT, g_ploT);
    cudaGetSymbolAddress((void**)&qhi,  g_qkvhi);
    cudaGetSymbolAddress((void**)&qlo,  g_qkvlo);
    cudaGetSymbolAddress((void**)&ahi,  g_ahi);

    cudaFuncSetAttribute((const void*)mma_gemm<false, true>,
                         cudaFuncAttributeMaxDynamicSharedMemorySize, GEMM_SMEM);
    cudaFuncSetAttribute((const void*)mma_gemm<true, false>,
                         cudaFuncAttributeMaxDynamicSharedMemorySize, GEMM_SMEM);
    cudaFuncSetAttribute((const void*)attn_mma,
                         cudaFuncAttributeMaxDynamicSharedMemorySize, ATT_SMEM);

    // 0) prep
    {
        int n4 = (M_ * C_) / 4;
        convert_hi<<<(n4 + 255) / 256, 256>>>((const float4*)x, xhi, n4);
        dim3 blk(32, 8);
        dim3 g1(QKVC_ / 32, C_ / 32);
        split_transpose<<<g1, blk>>>(w_qkv, whiT, wloT, C_, QKVC_);
        dim3 g2(C_ / 32, C_ / 32);
        split_transpose<<<g2, blk>>>(w_proj, phiT, ploT, C_, C_);
    }
    // 1) QKV projection (2-pass) -> split fp16, Q pre-scaled by 0.125
    {
        dim3 grid(QKVC_ / 128, M_ / 128);
        mma_gemm<false, true><<<grid, 256, GEMM_SMEM>>>(
            xhi, whiT, wloT, nullptr, nullptr, qhi, qlo, C_, QKVC_, C_);
    }
    // 2) attention (2-pass) -> fp16 hi output
    {
        dim3 grid(N_ / 128, B_ * H_);
        attn_mma<<<grid, 256, ATT_SMEM>>>(qhi, qlo, ahi);
    }
    // 3) output projection + bias (2-pass) -> fp32 out
    {
        dim3 grid(C_ / 128, M_ / 128);
        mma_gemm<true, false><<<grid, 256, GEMM_SMEM>>>(
            ahi, phiT, ploT, b_proj, out, nullptr, nullptr, 0, C_, C_);
    }
}

// round 11
// speedup vs baseline: 1.7336x; 1.2192x over previous
#include <cuda_runtime.h>
#include <cuda_fp16.h>
#include <math.h>
#include <stdint.h>

#define B_ 8
#define N_ 1024
#define C_ 768
#define H_ 12
#define D_ 64
#define QKVC_ (3 * C_)
#define M_ (B_ * N_)

// ----------------------------- scratch ------------------------------------
__device__ __half g_xhi[M_ * C_];
__device__ __half g_whiT[QKVC_ * C_], g_wloT[QKVC_ * C_];
__device__ __half g_phiT[C_ * C_],    g_ploT[C_ * C_];
__device__ __half g_qkvhi[M_ * QKVC_];
__device__ __half g_ahi[M_ * C_];

// ----------------------------- helpers ------------------------------------
__device__ __forceinline__ uint32_t smem_u32(const void* p) {
    uint32_t a;
    asm("{ .reg .u64 t; cvta.to.shared.u64 t, %1; cvt.u32.u64 %0, t; }"
        : "=r"(a) : "l"(p));
    return a;
}
__device__ __forceinline__ void cp16(uint32_t s, const void* g) {
    asm volatile("cp.async.cg.shared.global [%0], [%1], 16;"
                 :: "r"(s), "l"(g) : "memory");
}
#define CP_COMMIT() asm volatile("cp.async.commit_group;" ::: "memory")
#define CP_WAIT(n)  asm volatile("cp.async.wait_group %0;" :: "n"(n) : "memory")

__device__ __forceinline__ void ldsm_x4(uint32_t* f, uint32_t a) {
    asm volatile("ldmatrix.sync.aligned.m8n8.x4.shared.b16 {%0,%1,%2,%3}, [%4];"
                 : "=r"(f[0]), "=r"(f[1]), "=r"(f[2]), "=r"(f[3]) : "r"(a));
}
__device__ __forceinline__ void ldsm_x4t(uint32_t* f, uint32_t a) {
    asm volatile("ldmatrix.sync.aligned.m8n8.x4.trans.shared.b16 {%0,%1,%2,%3}, [%4];"
                 : "=r"(f[0]), "=r"(f[1]), "=r"(f[2]), "=r"(f[3]) : "r"(a));
}
__device__ __forceinline__ void ldsm_x2(uint32_t* f, uint32_t a) {
    asm volatile("ldmatrix.sync.aligned.m8n8.x2.shared.b16 {%0,%1}, [%2];"
                 : "=r"(f[0]), "=r"(f[1]) : "r"(a));
}
// fp16 inputs, fp32 accumulate
__device__ __forceinline__ void mma16816(float* d, const uint32_t* a,
                                         const uint32_t* b) {
    asm volatile(
        "mma.sync.aligned.m16n8k16.row.col.f32.f16.f16.f32 "
        "{%0,%1,%2,%3}, {%4,%5,%6,%7}, {%8,%9}, {%0,%1,%2,%3};"
        : "+f"(d[0]), "+f"(d[1]), "+f"(d[2]), "+f"(d[3])
        : "r"(a[0]), "r"(a[1]), "r"(a[2]), "r"(a[3]), "r"(b[0]), "r"(b[1]));
}
__device__ __forceinline__ uint32_t pk2h(float f0, float f1) {
    __half2 h = __floats2half2_rn(f0, f1);
    return *reinterpret_cast<uint32_t*>(&h);
}

// ----------------------------- prep kernels --------------------------------
__global__ void convert_hi(const float4* __restrict__ s,
                           __half* __restrict__ hi, int n4) {
    int i = blockIdx.x * blockDim.x + threadIdx.x;
    if (i >= n4) return;
    float4 v = s[i];
    __align__(8) __half h[4];
    h[0] = __float2half_rn(v.x); h[1] = __float2half_rn(v.y);
    h[2] = __float2half_rn(v.z); h[3] = __float2half_rn(v.w);
    *reinterpret_cast<uint2*>(hi + (size_t)i * 4) = *reinterpret_cast<uint2*>(h);
}

// w[K,N] -> hi/lo transposed [N,K], pre-scaled by 32 (keeps lo in fp16 normals)
__global__ void split_transpose(const float* __restrict__ w,
                                __half* __restrict__ hiT,
                                __half* __restrict__ loT, int K, int N) {
    __shared__ float t[32][33];
    const int n0 = blockIdx.x * 32, k0 = blockIdx.y * 32;
    for (int r = threadIdx.y; r < 32; r += 8)
        t[r][threadIdx.x] = w[(size_t)(k0 + r) * N + n0 + threadIdx.x];
    __syncthreads();
    for (int r = threadIdx.y; r < 32; r += 8) {
        float v = t[threadIdx.x][r] * 32.0f;
        __half h = __float2half_rn(v);
        __half l = __float2half_rn(v - __half2float(h));
        size_t o = (size_t)(n0 + r) * K + k0 + threadIdx.x;
        hiT[o] = h; loT[o] = l;
    }
}

// ----------------------------- mma.sync GEMM (2-pass fp16) -----------------
#define BK_ 32
#define LROW_ 80
#define MATB_ (128 * LROW_)              // 10240
#define STGB_ (3 * MATB_)                // 30720
#define GEMM_SMEM (2 * STGB_)            // 61440

template <bool BIAS, bool SPLITOUT>
__global__ __launch_bounds__(256, 2)
void mma_gemm(const __half* __restrict__ Ahi,
              const __half* __restrict__ BhiT,
              const __half* __restrict__ BloT,
              const float* __restrict__ bias,
              float* __restrict__ Cf,
              __half* __restrict__ Chi,
              int scale_cols, int Nn, int K) {
    extern __shared__ char smem[];
    const uint32_t sb = smem_u32(smem);
    const int tid = threadIdx.x;
    const int wid = tid >> 5;
    const int lane = tid & 31;
    const int row0 = blockIdx.y * 128;
    const int col0 = blockIdx.x * 128;
    const int wm = (wid >> 2) * 64;
    const int wn = (wid & 3) * 32;

    float acc[4][4][4];
#pragma unroll
    for (int i = 0; i < 4; i++)
#pragma unroll
        for (int j = 0; j < 4; j++)
#pragma unroll
            for (int k = 0; k < 4; k++) acc[i][j][k] = 0.f;

#define LOAD_STAGE(cc, ss)                                                   \
    {                                                                        \
        const uint32_t base = sb + (ss) * STGB_;                             \
        const int k0 = (cc) * BK_;                                           \
        _Pragma("unroll")                                                    \
        for (int t = 0; t < 6; t++) {                                        \
            const int idx = tid + t * 256;                                   \
            const int mat = idx >> 9, rem = idx & 511;                       \
            const int r = rem >> 2, ch = rem & 3;                            \
            const uint32_t off = (uint32_t)(mat * MATB_ + r * LROW_ + ch * 16); \
            const __half* src;                                               \
            if (mat == 0)      src = Ahi  + (size_t)(row0 + r) * K + k0 + ch * 8; \
            else if (mat == 1) src = BhiT + (size_t)(col0 + r) * K + k0 + ch * 8; \
            else               src = BloT + (size_t)(col0 + r) * K + k0 + ch * 8; \
            cp16(base + off, src);                                           \
        }                                                                    \
        CP_COMMIT();                                                         \
    }

    const int nch = K / BK_;    // 24
    LOAD_STAGE(0, 0);

    for (int c = 0; c < nch; c++) {
        const int cur = c & 1;
        if (c + 1 < nch) {
            LOAD_STAGE(c + 1, 1 - cur);
            CP_WAIT(1);
        } else {
            CP_WAIT(0);
        }
        __syncthreads();

        const uint32_t stg = sb + cur * STGB_;
#pragma unroll
        for (int kk = 0; kk < 2; kk++) {
            uint32_t ah[4][4], bh[4][2], bl[4][2];
            const uint32_t acol = (uint32_t)((kk * 16 + (lane >> 4) * 8) * 2);
            const uint32_t bcol =
                (uint32_t)((kk * 16 + ((lane >> 3) & 1) * 8) * 2);
#pragma unroll
            for (int mt = 0; mt < 4; mt++) {
                const uint32_t arow =
                    (uint32_t)((wm + mt * 16 + (lane & 15)) * LROW_);
                ldsm_x4(ah[mt], stg + arow + acol);
            }
#pragma unroll
            for (int nt = 0; nt < 4; nt++) {
                const uint32_t brow =
                    (uint32_t)((wn + nt * 8 + (lane & 7)) * LROW_);
                ldsm_x2(bh[nt], stg + MATB_ + brow + bcol);
                ldsm_x2(bl[nt], stg + 2 * MATB_ + brow + bcol);
            }
#pragma unroll
            for (int mt = 0; mt < 4; mt++)
#pragma unroll
                for (int nt = 0; nt < 4; nt++)
                    mma16816(acc[mt][nt], ah[mt], bh[nt]);
#pragma unroll
            for (int mt = 0; mt < 4; mt++)
#pragma unroll
                for (int nt = 0; nt < 4; nt++)
                    mma16816(acc[mt][nt], ah[mt], bl[nt]);
        }
        __syncthreads();
    }
#undef LOAD_STAGE

    const float wsc = 0.03125f;   // 1/32
    const int g = lane >> 2, t4 = lane & 3;
#pragma unroll
    for (int nt = 0; nt < 4; nt++) {
        const int col = col0 + wn + nt * 8 + t4 * 2;
        if (SPLITOUT) {
            const float sc = ((col < scale_cols) ? 0.125f : 1.0f) * wsc;
#pragma unroll
            for (int mt = 0; mt < 4; mt++) {
                const int ra = row0 + wm + mt * 16 + g;
#pragma unroll
                for (int half = 0; half < 2; half++) {
                    const int r = ra + half * 8;
                    const size_t off = (size_t)r * Nn + col;
                    *reinterpret_cast<uint32_t*>(Chi + off) =
                        pk2h(acc[mt][nt][half * 2 + 0] * sc,
                             acc[mt][nt][half * 2 + 1] * sc);
                }
            }
        } else {
            float b0 = 0.f, b1 = 0.f;
            if (BIAS) { b0 = bias[col]; b1 = bias[col + 1]; }
#pragma unroll
            for (int mt = 0; mt < 4; mt++) {
                const int ra = row0 + wm + mt * 16 + g;
                float2 v0 = make_float2(acc[mt][nt][0] * wsc + b0,
                                        acc[mt][nt][1] * wsc + b1);
                float2 v1 = make_float2(acc[mt][nt][2] * wsc + b0,
                                        acc[mt][nt][3] * wsc + b1);
                *reinterpret_cast<float2*>(&Cf[(size_t)ra * Nn + col]) = v0;
                *reinterpret_cast<float2*>(&Cf[(size_t)(ra + 8) * Nn + col]) = v1;
            }
        }
    }
}

// ----------------------------- mma flash attention (pure fp16) -------------
// S = Qhi·Khi (1 pass); O = Phi·Vhi (1 pass). P scaled x1024 (exact pow2).
// Smem: Q + 2 stages x (Khi,Vhi) = 5 mats = 92160 B -> 2 CTAs/SM.
#define ATT_LD 144
#define ATT_MAT 18432
#define ATT_STG0 ATT_MAT                  // Q hi
#define ATT_STGSZ (2 * ATT_MAT)           // Khi, Vhi
#define ATT_SMEM (ATT_STG0 + 2 * ATT_STGSZ)  // 92160

__global__ __launch_bounds__(256, 2)
void attn_mma(const __half* __restrict__ qhi,
              __half* __restrict__ ohi) {
    extern __shared__ char smem[];
    const uint32_t sb = smem_u32(smem);
    const int tid = threadIdx.x, wid = tid >> 5, lane = tid & 31;
    const int b = blockIdx.y / H_, h = blockIdx.y % H_;
    const int q0 = blockIdx.x * 128;
    const size_t rowbase = (size_t)b * N_;

    // ---- load Q hi ----
#pragma unroll
    for (int t = 0; t < 4; t++) {
        const int idx = tid + t * 256;
        const int r = idx >> 3, c = idx & 7;
        cp16(sb + r * ATT_LD + c * 16,
             qhi + ((rowbase + q0 + r) * QKVC_ + h * D_ + c * 8));
    }

#define LOAD_STAGE_ATT(ktile, ss)                                            \
    {                                                                        \
        const uint32_t base = sb + ATT_STG0 + (ss) * ATT_STGSZ;              \
        const size_t krow = rowbase + (ktile) * 128;                         \
        _Pragma("unroll")                                                    \
        for (int t = 0; t < 8; t++) {                                        \
            const int idx = tid + t * 256;                                   \
            const int mat = idx >> 10, rem = idx & 1023;                     \
            const int r = rem >> 3, c = rem & 7;                             \
            const uint32_t so = base + mat * ATT_MAT + r * ATT_LD + c * 16;  \
            const __half* sp = qhi +                                         \
                ((krow + r) * QKVC_ + (mat ? 2 * C_ : C_) + h * D_ + c * 8); \
            cp16(so, sp);                                                    \
        }                                                                    \
        CP_COMMIT();                                                         \
    }

    LOAD_STAGE_ATT(0, 0);

    float m_lo = -INFINITY, m_hi = -INFINITY, l_lo = 0.f, l_hi = 0.f;
    float o[8][4];
#pragma unroll
    for (int i = 0; i < 8; i++)
#pragma unroll
        for (int j = 0; j < 4; j++) o[i][j] = 0.f;

    const uint32_t qa =
        sb + (wid * 16 + (lane & 15)) * ATT_LD + ((lane >> 4) * 8) * 2;

    for (int kt = 0; kt < N_ / 128; kt++) {
        if (kt + 1 < N_ / 128) {
            LOAD_STAGE_ATT(kt + 1, (kt + 1) & 1);
            CP_WAIT(1);
        } else {
            CP_WAIT(0);
        }
        __syncthreads();

        const uint32_t stg = sb + ATT_STG0 + (kt & 1) * ATT_STGSZ;

        // ---- S = Qhi @ Khi^T ----
        float s[16][4];
#pragma unroll
        for (int nt = 0; nt < 16; nt++)
#pragma unroll
            for (int j = 0; j < 4; j++) s[nt][j] = 0.f;

#pragma unroll
        for (int k4 = 0; k4 < 4; k4++) {
            uint32_t qh[4];
            ldsm_x4(qh, qa + k4 * 32);
            const uint32_t ka = stg + (lane & 7) * ATT_LD +
                                (k4 * 16 + ((lane >> 3) & 1) * 8) * 2;
#pragma unroll
            for (int blk = 0; blk < 2; blk++) {
                uint32_t kh[8][2];
#pragma unroll
                for (int j = 0; j < 8; j++)
                    ldsm_x2(kh[j], ka + (blk * 8 + j) * 8 * ATT_LD);
#pragma unroll
                for (int j = 0; j < 8; j++)
                    mma16816(s[blk * 8 + j], qh, kh[j]);
            }
        }

        // ---- online softmax ----
        float tmlo = -INFINITY, tmhi = -INFINITY;
#pragma unroll
        for (int nt = 0; nt < 16; nt++) {
            tmlo = fmaxf(tmlo, fmaxf(s[nt][0], s[nt][1]));
            tmhi = fmaxf(tmhi, fmaxf(s[nt][2], s[nt][3]));
        }
        tmlo = fmaxf(tmlo, __shfl_xor_sync(0xffffffffu, tmlo, 1));
        tmlo = fmaxf(tmlo, __shfl_xor_sync(0xffffffffu, tmlo, 2));
        tmhi = fmaxf(tmhi, __shfl_xor_sync(0xffffffffu, tmhi, 1));
        tmhi = fmaxf(tmhi, __shfl_xor_sync(0xffffffffu, tmhi, 2));

        const float mnlo = fmaxf(m_lo, tmlo);
        const float mnhi = fmaxf(m_hi, tmhi);
        const float corrlo = __expf(m_lo - mnlo);
        const float corrhi = __expf(m_hi - mnhi);
        m_lo = mnlo; m_hi = mnhi;

        float pslo = 0.f, pshi = 0.f;
#pragma unroll
        for (int nt = 0; nt < 16; nt++) {
            s[nt][0] = __expf(s[nt][0] - mnlo) * 1024.f;
            s[nt][1] = __expf(s[nt][1] - mnlo) * 1024.f;
            s[nt][2] = __expf(s[nt][2] - mnhi) * 1024.f;
            s[nt][3] = __expf(s[nt][3] - mnhi) * 1024.f;
            pslo += s[nt][0] + s[nt][1];
            pshi += s[nt][2] + s[nt][3];
        }
        pslo += __shfl_xor_sync(0xffffffffu, pslo, 1);
        pslo += __shfl_xor_sync(0xffffffffu, pslo, 2);
        pshi += __shfl_xor_sync(0xffffffffu, pshi, 1);
        pshi += __shfl_xor_sync(0xffffffffu, pshi, 2);
        l_lo = l_lo * corrlo + pslo;
        l_hi = l_hi * corrhi + pshi;

#pragma unroll
        for (int nt = 0; nt < 8; nt++) {
            o[nt][0] *= corrlo; o[nt][1] *= corrlo;
            o[nt][2] *= corrhi; o[nt][3] *= corrhi;
        }

        // ---- O += Phi @ Vhi ----
#pragma unroll
        for (int t8 = 0; t8 < 8; t8++) {
            uint32_t ah[4];
#pragma unroll
            for (int half = 0; half < 2; half++) {
                ah[half * 2 + 0] = pk2h(s[2 * t8 + half][0],
                                        s[2 * t8 + half][1]);
                ah[half * 2 + 1] = pk2h(s[2 * t8 + half][2],
                                        s[2 * t8 + half][3]);
            }

            const uint32_t va = stg + ATT_MAT +
                ((lane & 7) + 8 * ((lane >> 3) & 1) + t8 * 16) * ATT_LD +
                ((lane >> 4) & 1) * 16;
            uint32_t vh[4][4];
#pragma unroll
            for (int nt2 = 0; nt2 < 4; nt2++)
                ldsm_x4t(vh[nt2], va + nt2 * 32);
#pragma unroll
            for (int nt2 = 0; nt2 < 4; nt2++) {
                mma16816(o[2 * nt2],     ah, vh[nt2]);
                mma16816(o[2 * nt2 + 1], ah, vh[nt2] + 2);
            }
        }
        __syncthreads();
    }
#undef LOAD_STAGE_ATT

    // normalize + store hi fp16
    const float invlo = 1.f / l_lo;
    const float invhi = 1.f / l_hi;
    const size_t rlo = rowbase + q0 + wid * 16 + (lane >> 2);
    const int colb = h * D_ + (lane & 3) * 2;
#pragma unroll
    for (int nt = 0; nt < 8; nt++) {
        const int col = colb + nt * 8;
        *reinterpret_cast<uint32_t*>(ohi + rlo * C_ + col) =
            pk2h(o[nt][0] * invlo, o[nt][1] * invlo);
        *reinterpret_cast<uint32_t*>(ohi + (rlo + 8) * C_ + col) =
            pk2h(o[nt][2] * invhi, o[nt][3] * invhi);
    }
}

// ----------------------------- launch -------------------------------------
extern "C" void kernel_launch(void* const* d_in, const int* in_sizes, int n_in,
                              void* d_out, int out_size) {
    const float* x      = (const float*)d_in[0];
    const float* w_qkv  = (const float*)d_in[1];
    const float* w_proj = (const float*)d_in[2];
    const float* b_proj = (const float*)d_in[3];
    float* out = (float*)d_out;

    __half *xhi, *whiT, *wloT, *phiT, *ploT, *qhi, *ahi;
    cudaGetSymbolAddress((void**)&xhi,  g_xhi);
    cudaGetSymbolAddress((void**)&whiT, g_whiT);
    cudaGetSymbolAddress((void**)&wloT, g_wloT);
    cudaGetSymbolAddress((void**)&phiT, g_phiT);
    cudaGetSymbolAddress((void**)&ploT, g_ploT);
    cudaGetSymbolAddress((void**)&qhi,  g_qkvhi);
    cudaGetSymbolAddress((void**)&ahi,  g_ahi);

    cudaFuncSetAttribute((const void*)mma_gemm<false, true>,
                         cudaFuncAttributeMaxDynamicSharedMemorySize, GEMM_SMEM);
    cudaFuncSetAttribute((const void*)mma_gemm<true, false>,
                         cudaFuncAttributeMaxDynamicSharedMemorySize, GEMM_SMEM);
    cudaFuncSetAttribute((const void*)attn_mma,
                         cudaFuncAttributeMaxDynamicSharedMemorySize, ATT_SMEM);

    // 0) prep
    {
        int n4 = (M_ * C_) / 4;
        convert_hi<<<(n4 + 255) / 256, 256>>>((const float4*)x, xhi, n4);
        dim3 blk(32, 8);
        dim3 g1(QKVC_ / 32, C_ / 32);
        split_transpose<<<g1, blk>>>(w_qkv, whiT, wloT, C_, QKVC_);
        dim3 g2(C_ / 32, C_ / 32);
        split_transpose<<<g2, blk>>>(w_proj, phiT, ploT, C_, C_);
    }
    // 1) QKV projection (2-pass) -> fp16 hi, Q pre-scaled by 0.125
    {
        dim3 grid(QKVC_ / 128, M_ / 128);
        mma_gemm<false, true><<<grid, 256, GEMM_SMEM>>>(
            xhi, whiT, wloT, nullptr, nullptr, qhi, C_, QKVC_, C_);
    }
    // 2) attention (pure fp16, 1-pass S and PV) -> fp16 hi output
    {
        dim3 grid(N_ / 128, B_ * H_);
        attn_mma<<<grid, 256, ATT_SMEM>>>(qhi, ahi);
    }
    // 3) output projection + bias (2-pass) -> fp32 out
    {
        dim3 grid(C_ / 128, M_ / 128);
        mma_gemm<true, false><<<grid, 256, GEMM_SMEM>>>(
            ahi, phiT, ploT, b_proj, out, nullptr, 0, C_, C_);
    }
}

// round 12
// speedup vs baseline: 2.1816x; 1.2585x over previous
#include <cuda_runtime.h>
#include <cuda_fp16.h>
#include <math.h>
#include <stdint.h>

#define B_ 8
#define N_ 1024
#define C_ 768
#define H_ 12
#define D_ 64
#define QKVC_ (3 * C_)
#define M_ (B_ * N_)

// ----------------------------- scratch ------------------------------------
__device__ __half g_xhi[M_ * C_];
__device__ __half g_whiT[QKVC_ * C_], g_wloT[QKVC_ * C_];
__device__ __half g_phiT[C_ * C_],    g_ploT[C_ * C_];
__device__ __half g_qkvhi[M_ * QKVC_];
__device__ __half g_ahi[M_ * C_];

// ----------------------------- helpers ------------------------------------
__device__ __forceinline__ uint32_t smem_u32(const void* p) {
    uint32_t a;
    asm("{ .reg .u64 t; cvta.to.shared.u64 t, %1; cvt.u32.u64 %0, t; }"
        : "=r"(a) : "l"(p));
    return a;
}
__device__ __forceinline__ void cp16(uint32_t s, const void* g) {
    asm volatile("cp.async.cg.shared.global [%0], [%1], 16;"
                 :: "r"(s), "l"(g) : "memory");
}
#define CP_COMMIT() asm volatile("cp.async.commit_group;" ::: "memory")
#define CP_WAIT(n)  asm volatile("cp.async.wait_group %0;" :: "n"(n) : "memory")

__device__ __forceinline__ void ldsm_x4(uint32_t* f, uint32_t a) {
    asm volatile("ldmatrix.sync.aligned.m8n8.x4.shared.b16 {%0,%1,%2,%3}, [%4];"
                 : "=r"(f[0]), "=r"(f[1]), "=r"(f[2]), "=r"(f[3]) : "r"(a));
}
__device__ __forceinline__ void ldsm_x4t(uint32_t* f, uint32_t a) {
    asm volatile("ldmatrix.sync.aligned.m8n8.x4.trans.shared.b16 {%0,%1,%2,%3}, [%4];"
                 : "=r"(f[0]), "=r"(f[1]), "=r"(f[2]), "=r"(f[3]) : "r"(a));
}
__device__ __forceinline__ void ldsm_x2(uint32_t* f, uint32_t a) {
    asm volatile("ldmatrix.sync.aligned.m8n8.x2.shared.b16 {%0,%1}, [%2];"
                 : "=r"(f[0]), "=r"(f[1]) : "r"(a));
}
// fp16 inputs, fp32 accumulate
__device__ __forceinline__ void mma16816(float* d, const uint32_t* a,
                                         const uint32_t* b) {
    asm volatile(
        "mma.sync.aligned.m16n8k16.row.col.f32.f16.f16.f32 "
        "{%0,%1,%2,%3}, {%4,%5,%6,%7}, {%8,%9}, {%0,%1,%2,%3};"
        : "+f"(d[0]), "+f"(d[1]), "+f"(d[2]), "+f"(d[3])
        : "r"(a[0]), "r"(a[1]), "r"(a[2]), "r"(a[3]), "r"(b[0]), "r"(b[1]));
}
__device__ __forceinline__ uint32_t pk2h(float f0, float f1) {
    __half2 h = __floats2half2_rn(f0, f1);
    return *reinterpret_cast<uint32_t*>(&h);
}

// ----------------------------- prep kernels --------------------------------
__global__ void convert_hi(const float4* __restrict__ s,
                           __half* __restrict__ hi, int n4) {
    int i = blockIdx.x * blockDim.x + threadIdx.x;
    if (i >= n4) return;
    float4 v = s[i];
    __align__(8) __half h[4];
    h[0] = __float2half_rn(v.x); h[1] = __float2half_rn(v.y);
    h[2] = __float2half_rn(v.z); h[3] = __float2half_rn(v.w);
    *reinterpret_cast<uint2*>(hi + (size_t)i * 4) = *reinterpret_cast<uint2*>(h);
}

// w[K,N] -> hi/lo transposed [N,K], pre-scaled by 32 (keeps lo in fp16 normals)
__global__ void split_transpose(const float* __restrict__ w,
                                __half* __restrict__ hiT,
                                __half* __restrict__ loT, int K, int N) {
    __shared__ float t[32][33];
    const int n0 = blockIdx.x * 32, k0 = blockIdx.y * 32;
    for (int r = threadIdx.y; r < 32; r += 8)
        t[r][threadIdx.x] = w[(size_t)(k0 + r) * N + n0 + threadIdx.x];
    __syncthreads();
    for (int r = threadIdx.y; r < 32; r += 8) {
        float v = t[threadIdx.x][r] * 32.0f;
        __half h = __float2half_rn(v);
        __half l = __float2half_rn(v - __half2float(h));
        size_t o = (size_t)(n0 + r) * K + k0 + threadIdx.x;
        hiT[o] = h; loT[o] = l;
    }
}

// ----------------------------- mma.sync GEMM -------------------------------
// TWOPASS: C = Ahi@(Bhi+Blo)^T; else C = Ahi@Bhi^T. B pre-scaled x32,
// epilogue x(1/32). 256 thr, 8 warps 2x4, warp tile 64x32, BK=32, 2-stage.
#define BK_ 32
#define LROW_ 80
#define MATB_ (128 * LROW_)              // 10240
#define GEMM_SMEM_2P (2 * 3 * MATB_)     // 61440
#define GEMM_SMEM_1P (2 * 2 * MATB_)     // 40960

template <bool BIAS, bool SPLITOUT, bool TWOPASS>
__global__ __launch_bounds__(256, 2)
void mma_gemm(const __half* __restrict__ Ahi,
              const __half* __restrict__ BhiT,
              const __half* __restrict__ BloT,
              const float* __restrict__ bias,
              float* __restrict__ Cf,
              __half* __restrict__ Chi,
              int scale_cols, int Nn, int K) {
    constexpr int NMAT = TWOPASS ? 3 : 2;
    constexpr int STGB = NMAT * MATB_;
    extern __shared__ char smem[];
    const uint32_t sb = smem_u32(smem);
    const int tid = threadIdx.x;
    const int wid = tid >> 5;
    const int lane = tid & 31;
    const int row0 = blockIdx.y * 128;
    const int col0 = blockIdx.x * 128;
    const int wm = (wid >> 2) * 64;
    const int wn = (wid & 3) * 32;

    float acc[4][4][4];
#pragma unroll
    for (int i = 0; i < 4; i++)
#pragma unroll
        for (int j = 0; j < 4; j++)
#pragma unroll
            for (int k = 0; k < 4; k++) acc[i][j][k] = 0.f;

#define LOAD_STAGE(cc, ss)                                                   \
    {                                                                        \
        const uint32_t base = sb + (ss) * STGB;                              \
        const int k0 = (cc) * BK_;                                           \
        _Pragma("unroll")                                                    \
        for (int t = 0; t < 2 * NMAT; t++) {                                 \
            const int idx = tid + t * 256;                                   \
            const int mat = idx >> 9, rem = idx & 511;                       \
            const int r = rem >> 2, ch = rem & 3;                            \
            const uint32_t off = (uint32_t)(mat * MATB_ + r * LROW_ + ch * 16); \
            const __half* src;                                               \
            if (mat == 0)      src = Ahi  + (size_t)(row0 + r) * K + k0 + ch * 8; \
            else if (mat == 1) src = BhiT + (size_t)(col0 + r) * K + k0 + ch * 8; \
            else               src = BloT + (size_t)(col0 + r) * K + k0 + ch * 8; \
            cp16(base + off, src);                                           \
        }                                                                    \
        CP_COMMIT();                                                         \
    }

    const int nch = K / BK_;    // 24
    LOAD_STAGE(0, 0);

    for (int c = 0; c < nch; c++) {
        const int cur = c & 1;
        if (c + 1 < nch) {
            LOAD_STAGE(c + 1, 1 - cur);
            CP_WAIT(1);
        } else {
            CP_WAIT(0);
        }
        __syncthreads();

        const uint32_t stg = sb + cur * STGB;
#pragma unroll
        for (int kk = 0; kk < 2; kk++) {
            uint32_t ah[4][4], bh[4][2], bl[4][2];
            const uint32_t acol = (uint32_t)((kk * 16 + (lane >> 4) * 8) * 2);
            const uint32_t bcol =
                (uint32_t)((kk * 16 + ((lane >> 3) & 1) * 8) * 2);
#pragma unroll
            for (int mt = 0; mt < 4; mt++) {
                const uint32_t arow =
                    (uint32_t)((wm + mt * 16 + (lane & 15)) * LROW_);
                ldsm_x4(ah[mt], stg + arow + acol);
            }
#pragma unroll
            for (int nt = 0; nt < 4; nt++) {
                const uint32_t brow =
                    (uint32_t)((wn + nt * 8 + (lane & 7)) * LROW_);
                ldsm_x2(bh[nt], stg + MATB_ + brow + bcol);
                if (TWOPASS)
                    ldsm_x2(bl[nt], stg + 2 * MATB_ + brow + bcol);
            }
#pragma unroll
            for (int mt = 0; mt < 4; mt++)
#pragma unroll
                for (int nt = 0; nt < 4; nt++)
                    mma16816(acc[mt][nt], ah[mt], bh[nt]);
            if (TWOPASS) {
#pragma unroll
                for (int mt = 0; mt < 4; mt++)
#pragma unroll
                    for (int nt = 0; nt < 4; nt++)
                        mma16816(acc[mt][nt], ah[mt], bl[nt]);
            }
        }
        __syncthreads();
    }
#undef LOAD_STAGE

    const float wsc = 0.03125f;   // 1/32
    const int g = lane >> 2, t4 = lane & 3;
#pragma unroll
    for (int nt = 0; nt < 4; nt++) {
        const int col = col0 + wn + nt * 8 + t4 * 2;
        if (SPLITOUT) {
            const float sc = ((col < scale_cols) ? 0.125f : 1.0f) * wsc;
#pragma unroll
            for (int mt = 0; mt < 4; mt++) {
                const int ra = row0 + wm + mt * 16 + g;
#pragma unroll
                for (int half = 0; half < 2; half++) {
                    const int r = ra + half * 8;
                    const size_t off = (size_t)r * Nn + col;
                    *reinterpret_cast<uint32_t*>(Chi + off) =
                        pk2h(acc[mt][nt][half * 2 + 0] * sc,
                             acc[mt][nt][half * 2 + 1] * sc);
                }
            }
        } else {
            float b0 = 0.f, b1 = 0.f;
            if (BIAS) { b0 = bias[col]; b1 = bias[col + 1]; }
#pragma unroll
            for (int mt = 0; mt < 4; mt++) {
                const int ra = row0 + wm + mt * 16 + g;
                float2 v0 = make_float2(acc[mt][nt][0] * wsc + b0,
                                        acc[mt][nt][1] * wsc + b1);
                float2 v1 = make_float2(acc[mt][nt][2] * wsc + b0,
                                        acc[mt][nt][3] * wsc + b1);
                *reinterpret_cast<float2*>(&Cf[(size_t)ra * Nn + col]) = v0;
                *reinterpret_cast<float2*>(&Cf[(size_t)(ra + 8) * Nn + col]) = v1;
            }
        }
    }
}

// ----------------------------- mma flash attention (pure fp16) -------------
// S = Qhi·Khi; O = Phi·Vhi. P scaled x1024 (exact pow2). 2 CTAs/SM.
#define ATT_LD 144
#define ATT_MAT 18432
#define ATT_STG0 ATT_MAT                  // Q hi
#define ATT_STGSZ (2 * ATT_MAT)           // Khi, Vhi
#define ATT_SMEM (ATT_STG0 + 2 * ATT_STGSZ)  // 92160

__global__ __launch_bounds__(256, 2)
void attn_mma(const __half* __restrict__ qhi,
              __half* __restrict__ ohi) {
    extern __shared__ char smem[];
    const uint32_t sb = smem_u32(smem);
    const int tid = threadIdx.x, wid = tid >> 5, lane = tid & 31;
    const int b = blockIdx.y / H_, h = blockIdx.y % H_;
    const int q0 = blockIdx.x * 128;
    const size_t rowbase = (size_t)b * N_;

    // ---- load Q hi ----
#pragma unroll
    for (int t = 0; t < 4; t++) {
        const int idx = tid + t * 256;
        const int r = idx >> 3, c = idx & 7;
        cp16(sb + r * ATT_LD + c * 16,
             qhi + ((rowbase + q0 + r) * QKVC_ + h * D_ + c * 8));
    }

#define LOAD_STAGE_ATT(ktile, ss)                                            \
    {                                                                        \
        const uint32_t base = sb + ATT_STG0 + (ss) * ATT_STGSZ;              \
        const size_t krow = rowbase + (ktile) * 128;                         \
        _Pragma("unroll")                                                    \
        for (int t = 0; t < 8; t++) {                                        \
            const int idx = tid + t * 256;                                   \
            const int mat = idx >> 10, rem = idx & 1023;                     \
            const int r = rem >> 3, c = rem & 7;                             \
            const uint32_t so = base + mat * ATT_MAT + r * ATT_LD + c * 16;  \
            const __half* sp = qhi +                                         \
                ((krow + r) * QKVC_ + (mat ? 2 * C_ : C_) + h * D_ + c * 8); \
            cp16(so, sp);                                                    \
        }                                                                    \
        CP_COMMIT();                                                         \
    }

    LOAD_STAGE_ATT(0, 0);

    float m_lo = -INFINITY, m_hi = -INFINITY, l_lo = 0.f, l_hi = 0.f;
    float o[8][4];
#pragma unroll
    for (int i = 0; i < 8; i++)
#pragma unroll
        for (int j = 0; j < 4; j++) o[i][j] = 0.f;

    const uint32_t qa =
        sb + (wid * 16 + (lane & 15)) * ATT_LD + ((lane >> 4) * 8) * 2;

    for (int kt = 0; kt < N_ / 128; kt++) {
        if (kt + 1 < N_ / 128) {
            LOAD_STAGE_ATT(kt + 1, (kt + 1) & 1);
            CP_WAIT(1);
        } else {
            CP_WAIT(0);
        }
        __syncthreads();

        const uint32_t stg = sb + ATT_STG0 + (kt & 1) * ATT_STGSZ;

        // ---- S = Qhi @ Khi^T ----
        float s[16][4];
#pragma unroll
        for (int nt = 0; nt < 16; nt++)
#pragma unroll
            for (int j = 0; j < 4; j++) s[nt][j] = 0.f;

#pragma unroll
        for (int k4 = 0; k4 < 4; k4++) {
            uint32_t qh[4];
            ldsm_x4(qh, qa + k4 * 32);
            const uint32_t ka = stg + (lane & 7) * ATT_LD +
                                (k4 * 16 + ((lane >> 3) & 1) * 8) * 2;
#pragma unroll
            for (int blk = 0; blk < 2; blk++) {
                uint32_t kh[8][2];
#pragma unroll
                for (int j = 0; j < 8; j++)
                    ldsm_x2(kh[j], ka + (blk * 8 + j) * 8 * ATT_LD);
#pragma unroll
                for (int j = 0; j < 8; j++)
                    mma16816(s[blk * 8 + j], qh, kh[j]);
            }
        }

        // ---- online softmax ----
        float tmlo = -INFINITY, tmhi = -INFINITY;
#pragma unroll
        for (int nt = 0; nt < 16; nt++) {
            tmlo = fmaxf(tmlo, fmaxf(s[nt][0], s[nt][1]));
            tmhi = fmaxf(tmhi, fmaxf(s[nt][2], s[nt][3]));
        }
        tmlo = fmaxf(tmlo, __shfl_xor_sync(0xffffffffu, tmlo, 1));
        tmlo = fmaxf(tmlo, __shfl_xor_sync(0xffffffffu, tmlo, 2));
        tmhi = fmaxf(tmhi, __shfl_xor_sync(0xffffffffu, tmhi, 1));
        tmhi = fmaxf(tmhi, __shfl_xor_sync(0xffffffffu, tmhi, 2));

        const float mnlo = fmaxf(m_lo, tmlo);
        const float mnhi = fmaxf(m_hi, tmhi);
        const float corrlo = __expf(m_lo - mnlo);
        const float corrhi = __expf(m_hi - mnhi);
        m_lo = mnlo; m_hi = mnhi;

        float pslo = 0.f, pshi = 0.f;
#pragma unroll
        for (int nt = 0; nt < 16; nt++) {
            s[nt][0] = __expf(s[nt][0] - mnlo) * 1024.f;
            s[nt][1] = __expf(s[nt][1] - mnlo) * 1024.f;
            s[nt][2] = __expf(s[nt][2] - mnhi) * 1024.f;
            s[nt][3] = __expf(s[nt][3] - mnhi) * 1024.f;
            pslo += s[nt][0] + s[nt][1];
            pshi += s[nt][2] + s[nt][3];
        }
        pslo += __shfl_xor_sync(0xffffffffu, pslo, 1);
        pslo += __shfl_xor_sync(0xffffffffu, pslo, 2);
        pshi += __shfl_xor_sync(0xffffffffu, pshi, 1);
        pshi += __shfl_xor_sync(0xffffffffu, pshi, 2);
        l_lo = l_lo * corrlo + pslo;
        l_hi = l_hi * corrhi + pshi;

#pragma unroll
        for (int nt = 0; nt < 8; nt++) {
            o[nt][0] *= corrlo; o[nt][1] *= corrlo;
            o[nt][2] *= corrhi; o[nt][3] *= corrhi;
        }

        // ---- O += Phi @ Vhi ----
#pragma unroll
        for (int t8 = 0; t8 < 8; t8++) {
            uint32_t ah[4];
#pragma unroll
            for (int half = 0; half < 2; half++) {
                ah[half * 2 + 0] = pk2h(s[2 * t8 + half][0],
                                        s[2 * t8 + half][1]);
                ah[half * 2 + 1] = pk2h(s[2 * t8 + half][2],
                                        s[2 * t8 + half][3]);
            }

            const uint32_t va = stg + ATT_MAT +
                ((lane & 7) + 8 * ((lane >> 3) & 1) + t8 * 16) * ATT_LD +
                ((lane >> 4) & 1) * 16;
            uint32_t vh[4][4];
#pragma unroll
            for (int nt2 = 0; nt2 < 4; nt2++)
                ldsm_x4t(vh[nt2], va + nt2 * 32);
#pragma unroll
            for (int nt2 = 0; nt2 < 4; nt2++) {
                mma16816(o[2 * nt2],     ah, vh[nt2]);
                mma16816(o[2 * nt2 + 1], ah, vh[nt2] + 2);
            }
        }
        __syncthreads();
    }
#undef LOAD_STAGE_ATT

    // normalize + store hi fp16
    const float invlo = 1.f / l_lo;
    const float invhi = 1.f / l_hi;
    const size_t rlo = rowbase + q0 + wid * 16 + (lane >> 2);
    const int colb = h * D_ + (lane & 3) * 2;
#pragma unroll
    for (int nt = 0; nt < 8; nt++) {
        const int col = colb + nt * 8;
        *reinterpret_cast<uint32_t*>(ohi + rlo * C_ + col) =
            pk2h(o[nt][0] * invlo, o[nt][1] * invlo);
        *reinterpret_cast<uint32_t*>(ohi + (rlo + 8) * C_ + col) =
            pk2h(o[nt][2] * invhi, o[nt][3] * invhi);
    }
}

// ----------------------------- launch -------------------------------------
extern "C" void kernel_launch(void* const* d_in, const int* in_sizes, int n_in,
                              void* d_out, int out_size) {
    const float* x      = (const float*)d_in[0];
    const float* w_qkv  = (const float*)d_in[1];
    const float* w_proj = (const float*)d_in[2];
    const float* b_proj = (const float*)d_in[3];
    float* out = (float*)d_out;

    __half *xhi, *whiT, *wloT, *phiT, *ploT, *qhi, *ahi;
    cudaGetSymbolAddress((void**)&xhi,  g_xhi);
    cudaGetSymbolAddress((void**)&whiT, g_whiT);
    cudaGetSymbolAddress((void**)&wloT, g_wloT);
    cudaGetSymbolAddress((void**)&phiT, g_phiT);
    cudaGetSymbolAddress((void**)&ploT, g_ploT);
    cudaGetSymbolAddress((void**)&qhi,  g_qkvhi);
    cudaGetSymbolAddress((void**)&ahi,  g_ahi);

    cudaFuncSetAttribute((const void*)mma_gemm<false, true, false>,
                         cudaFuncAttributeMaxDynamicSharedMemorySize,
                         GEMM_SMEM_1P);
    cudaFuncSetAttribute((const void*)mma_gemm<true, false, true>,
                         cudaFuncAttributeMaxDynamicSharedMemorySize,
                         GEMM_SMEM_2P);
    cudaFuncSetAttribute((const void*)attn_mma,
                         cudaFuncAttributeMaxDynamicSharedMemorySize, ATT_SMEM);

    // 0) prep
    {
        int n4 = (M_ * C_) / 4;
        convert_hi<<<(n4 + 255) / 256, 256>>>((const float4*)x, xhi, n4);
        dim3 blk(32, 8);
        dim3 g1(QKVC_ / 32, C_ / 32);
        split_transpose<<<g1, blk>>>(w_qkv, whiT, wloT, C_, QKVC_);
        dim3 g2(C_ / 32, C_ / 32);
        split_transpose<<<g2, blk>>>(w_proj, phiT, ploT, C_, C_);
    }
    // 1) QKV projection (1-pass fp16) -> fp16 hi, Q pre-scaled by 0.125
    {
        dim3 grid(QKVC_ / 128, M_ / 128);
        mma_gemm<false, true, false><<<grid, 256, GEMM_SMEM_1P>>>(
            xhi, whiT, nullptr, nullptr, nullptr, qhi, C_, QKVC_, C_);
    }
    // 2) attention (pure fp16) -> fp16 hi output
    {
        dim3 grid(N_ / 128, B_ * H_);
        attn_mma<<<grid, 256, ATT_SMEM>>>(qhi, ahi);
    }
    // 3) output projection + bias (2-pass) -> fp32 out
    {
        dim3 grid(C_ / 128, M_ / 128);
        mma_gemm<true, false, true><<<grid, 256, GEMM_SMEM_2P>>>(
            ahi, phiT, ploT, b_proj, out, nullptr, 0, C_, C_);
    }
}

// round 14
// speedup vs baseline: 2.3906x; 1.0958x over previous
#include <cuda_runtime.h>
#include <cuda_fp16.h>
#include <math.h>
#include <stdint.h>

#define B_ 8
#define N_ 1024
#define C_ 768
#define H_ 12
#define D_ 64
#define QKVC_ (3 * C_)
#define M_ (B_ * N_)

// ----------------------------- scratch ------------------------------------
__device__ __half g_xhi[M_ * C_];
__device__ __half g_whiT[QKVC_ * C_], g_wloT[QKVC_ * C_];
__device__ __half g_phiT[C_ * C_];
__device__ __half g_qkvhi[M_ * QKVC_];
__device__ __half g_ahi[M_ * C_];

// ----------------------------- helpers ------------------------------------
__device__ __forceinline__ uint32_t smem_u32(const void* p) {
    uint32_t a;
    asm("{ .reg .u64 t; cvta.to.shared.u64 t, %1; cvt.u32.u64 %0, t; }"
        : "=r"(a) : "l"(p));
    return a;
}
__device__ __forceinline__ void cp16(uint32_t s, const void* g) {
    asm volatile("cp.async.cg.shared.global [%0], [%1], 16;"
                 :: "r"(s), "l"(g) : "memory");
}
#define CP_COMMIT() asm volatile("cp.async.commit_group;" ::: "memory")
#define CP_WAIT(n)  asm volatile("cp.async.wait_group %0;" :: "n"(n) : "memory")

__device__ __forceinline__ void ldsm_x4(uint32_t* f, uint32_t a) {
    asm volatile("ldmatrix.sync.aligned.m8n8.x4.shared.b16 {%0,%1,%2,%3}, [%4];"
                 : "=r"(f[0]), "=r"(f[1]), "=r"(f[2]), "=r"(f[3]) : "r"(a));
}
__device__ __forceinline__ void ldsm_x4t(uint32_t* f, uint32_t a) {
    asm volatile("ldmatrix.sync.aligned.m8n8.x4.trans.shared.b16 {%0,%1,%2,%3}, [%4];"
                 : "=r"(f[0]), "=r"(f[1]), "=r"(f[2]), "=r"(f[3]) : "r"(a));
}
__device__ __forceinline__ void ldsm_x2(uint32_t* f, uint32_t a) {
    asm volatile("ldmatrix.sync.aligned.m8n8.x2.shared.b16 {%0,%1}, [%2];"
                 : "=r"(f[0]), "=r"(f[1]) : "r"(a));
}
// fp16 inputs, fp32 accumulate
__device__ __forceinline__ void mma16816(float* d, const uint32_t* a,
                                         const uint32_t* b) {
    asm volatile(
        "mma.sync.aligned.m16n8k16.row.col.f32.f16.f16.f32 "
        "{%0,%1,%2,%3}, {%4,%5,%6,%7}, {%8,%9}, {%0,%1,%2,%3};"
        : "+f"(d[0]), "+f"(d[1]), "+f"(d[2]), "+f"(d[3])
        : "r"(a[0]), "r"(a[1]), "r"(a[2]), "r"(a[3]), "r"(b[0]), "r"(b[1]));
}
__device__ __forceinline__ uint32_t pk2h(float f0, float f1) {
    __half2 h = __floats2half2_rn(f0, f1);
    return *reinterpret_cast<uint32_t*>(&h);
}

// ----------------------------- prep kernels --------------------------------
__global__ void convert_hi(const float4* __restrict__ s,
                           __half* __restrict__ hi, int n4) {
    int i = blockIdx.x * blockDim.x + threadIdx.x;
    if (i >= n4) return;
    float4 v = s[i];
    __align__(8) __half h[4];
    h[0] = __float2half_rn(v.x); h[1] = __float2half_rn(v.y);
    h[2] = __float2half_rn(v.z); h[3] = __float2half_rn(v.w);
    *reinterpret_cast<uint2*>(hi + (size_t)i * 4) = *reinterpret_cast<uint2*>(h);
}

// w[K,N] -> hi(/lo) transposed [N,K], pre-scaled by 32
template <bool LO>
__global__ void split_transpose(const float* __restrict__ w,
                                __half* __restrict__ hiT,
                                __half* __restrict__ loT, int K, int N) {
    __shared__ float t[32][33];
    const int n0 = blockIdx.x * 32, k0 = blockIdx.y * 32;
    for (int r = threadIdx.y; r < 32; r += 8)
        t[r][threadIdx.x] = w[(size_t)(k0 + r) * N + n0 + threadIdx.x];
    __syncthreads();
    for (int r = threadIdx.y; r < 32; r += 8) {
        float v = t[threadIdx.x][r] * 32.0f;
        __half h = __float2half_rn(v);
        size_t o = (size_t)(n0 + r) * K + k0 + threadIdx.x;
        hiT[o] = h;
        if (LO) loT[o] = __float2half_rn(v - __half2float(h));
    }
}

// ----------------------------- mma.sync GEMM -------------------------------
// TWOPASS: C = Ahi@(Bhi+Blo)^T; else C = Ahi@Bhi^T. B pre-scaled x32,
// epilogue x(1/32). 256 thr, 8 warps 2x4, warp tile 64x32, BK=32, 2-stage.
#define BK_ 32
#define LROW_ 80
#define MATB_ (128 * LROW_)              // 10240
#define GEMM_SMEM_2P (2 * 3 * MATB_)     // 61440
#define GEMM_SMEM_1P (2 * 2 * MATB_)     // 40960

template <bool BIAS, bool SPLITOUT, bool TWOPASS>
__global__ __launch_bounds__(256, 2)
void mma_gemm(const __half* __restrict__ Ahi,
              const __half* __restrict__ BhiT,
              const __half* __restrict__ BloT,
              const float* __restrict__ bias,
              float* __restrict__ Cf,
              __half* __restrict__ Chi,
              int scale_cols, int Nn, int K) {
    constexpr int NMAT = TWOPASS ? 3 : 2;
    constexpr int STGB = NMAT * MATB_;
    extern __shared__ char smem[];
    const uint32_t sb = smem_u32(smem);
    const int tid = threadIdx.x;
    const int wid = tid >> 5;
    const int lane = tid & 31;
    const int row0 = blockIdx.y * 128;
    const int col0 = blockIdx.x * 128;
    const int wm = (wid >> 2) * 64;
    const int wn = (wid & 3) * 32;

    float acc[4][4][4];
#pragma unroll
    for (int i = 0; i < 4; i++)
#pragma unroll
        for (int j = 0; j < 4; j++)
#pragma unroll
            for (int k = 0; k < 4; k++) acc[i][j][k] = 0.f;

#define LOAD_STAGE(cc, ss)                                                   \
    {                                                                        \
        const uint32_t base = sb + (ss) * STGB;                              \
        const int k0 = (cc) * BK_;                                           \
        _Pragma("unroll")                                                    \
        for (int t = 0; t < 2 * NMAT; t++) {                                 \
            const int idx = tid + t * 256;                                   \
            const int mat = idx >> 9, rem = idx & 511;                       \
            const int r = rem >> 2, ch = rem & 3;                            \
            const uint32_t off = (uint32_t)(mat * MATB_ + r * LROW_ + ch * 16); \
            const __half* src;                                               \
            if (mat == 0)      src = Ahi  + (size_t)(row0 + r) * K + k0 + ch * 8; \
            else if (mat == 1) src = BhiT + (size_t)(col0 + r) * K + k0 + ch * 8; \
            else               src = BloT + (size_t)(col0 + r) * K + k0 + ch * 8; \
            cp16(base + off, src);                                           \
        }                                                                    \
        CP_COMMIT();                                                         \
    }

    const int nch = K / BK_;    // 24
    LOAD_STAGE(0, 0);

    for (int c = 0; c < nch; c++) {
        const int cur = c & 1;
        if (c + 1 < nch) {
            LOAD_STAGE(c + 1, 1 - cur);
            CP_WAIT(1);
        } else {
            CP_WAIT(0);
        }
        __syncthreads();

        const uint32_t stg = sb + cur * STGB;
#pragma unroll
        for (int kk = 0; kk < 2; kk++) {
            uint32_t ah[4][4], bh[4][2], bl[4][2];
            const uint32_t acol = (uint32_t)((kk * 16 + (lane >> 4) * 8) * 2);
            const uint32_t bcol =
                (uint32_t)((kk * 16 + ((lane >> 3) & 1) * 8) * 2);
#pragma unroll
            for (int mt = 0; mt < 4; mt++) {
                const uint32_t arow =
                    (uint32_t)((wm + mt * 16 + (lane & 15)) * LROW_);
                ldsm_x4(ah[mt], stg + arow + acol);
            }
#pragma unroll
            for (int nt = 0; nt < 4; nt++) {
                const uint32_t brow =
                    (uint32_t)((wn + nt * 8 + (lane & 7)) * LROW_);
                ldsm_x2(bh[nt], stg + MATB_ + brow + bcol);
                if (TWOPASS)
                    ldsm_x2(bl[nt], stg + 2 * MATB_ + brow + bcol);
            }
#pragma unroll
            for (int mt = 0; mt < 4; mt++)
#pragma unroll
                for (int nt = 0; nt < 4; nt++)
                    mma16816(acc[mt][nt], ah[mt], bh[nt]);
            if (TWOPASS) {
#pragma unroll
                for (int mt = 0; mt < 4; mt++)
#pragma unroll
                    for (int nt = 0; nt < 4; nt++)
                        mma16816(acc[mt][nt], ah[mt], bl[nt]);
            }
        }
        __syncthreads();
    }
#undef LOAD_STAGE

    const float wsc = 0.03125f;   // 1/32
    const int g = lane >> 2, t4 = lane & 3;
#pragma unroll
    for (int nt = 0; nt < 4; nt++) {
        const int col = col0 + wn + nt * 8 + t4 * 2;
        if (SPLITOUT) {
            const float sc = ((col < scale_cols) ? 0.125f : 1.0f) * wsc;
#pragma unroll
            for (int mt = 0; mt < 4; mt++) {
                const int ra = row0 + wm + mt * 16 + g;
#pragma unroll
                for (int half = 0; half < 2; half++) {
                    const int r = ra + half * 8;
                    const size_t off = (size_t)r * Nn + col;
                    *reinterpret_cast<uint32_t*>(Chi + off) =
                        pk2h(acc[mt][nt][half * 2 + 0] * sc,
                             acc[mt][nt][half * 2 + 1] * sc);
                }
            }
        } else {
            float b0 = 0.f, b1 = 0.f;
            if (BIAS) { b0 = bias[col]; b1 = bias[col + 1]; }
#pragma unroll
            for (int mt = 0; mt < 4; mt++) {
                const int ra = row0 + wm + mt * 16 + g;
                float2 v0 = make_float2(acc[mt][nt][0] * wsc + b0,
                                        acc[mt][nt][1] * wsc + b1);
                float2 v1 = make_float2(acc[mt][nt][2] * wsc + b0,
                                        acc[mt][nt][3] * wsc + b1);
                *reinterpret_cast<float2*>(&Cf[(size_t)ra * Nn + col]) = v0;
                *reinterpret_cast<float2*>(&Cf[(size_t)(ra + 8) * Nn + col]) = v1;
            }
        }
    }
}

// ----------------------------- mma flash attention (pure fp16, R12) --------
// S = Qhi·Khi; O = Phi·Vhi. fp32 __expf softmax, P scaled x1024 (exact pow2).
#define ATT_LD 144
#define ATT_MAT 18432
#define ATT_STG0 ATT_MAT                  // Q hi
#define ATT_STGSZ (2 * ATT_MAT)           // Khi, Vhi
#define ATT_SMEM (ATT_STG0 + 2 * ATT_STGSZ)  // 92160

__global__ __launch_bounds__(256, 2)
void attn_mma(const __half* __restrict__ qhi,
              __half* __restrict__ ohi) {
    extern __shared__ char smem[];
    const uint32_t sb = smem_u32(smem);
    const int tid = threadIdx.x, wid = tid >> 5, lane = tid & 31;
    const int b = blockIdx.y / H_, h = blockIdx.y % H_;
    const int q0 = blockIdx.x * 128;
    const size_t rowbase = (size_t)b * N_;

    // ---- load Q hi ----
#pragma unroll
    for (int t = 0; t < 4; t++) {
        const int idx = tid + t * 256;
        const int r = idx >> 3, c = idx & 7;
        cp16(sb + r * ATT_LD + c * 16,
             qhi + ((rowbase + q0 + r) * QKVC_ + h * D_ + c * 8));
    }

#define LOAD_STAGE_ATT(ktile, ss)                                            \
    {                                                                        \
        const uint32_t base = sb + ATT_STG0 + (ss) * ATT_STGSZ;              \
        const size_t krow = rowbase + (ktile) * 128;                         \
        _Pragma("unroll")                                                    \
        for (int t = 0; t < 8; t++) {                                        \
            const int idx = tid + t * 256;                                   \
            const int mat = idx >> 10, rem = idx & 1023;                     \
            const int r = rem >> 3, c = rem & 7;                             \
            const uint32_t so = base + mat * ATT_MAT + r * ATT_LD + c * 16;  \
            const __half* sp = qhi +                                         \
                ((krow + r) * QKVC_ + (mat ? 2 * C_ : C_) + h * D_ + c * 8); \
            cp16(so, sp);                                                    \
        }                                                                    \
        CP_COMMIT();                                                         \
    }

    LOAD_STAGE_ATT(0, 0);

    float m_lo = -INFINITY, m_hi = -INFINITY, l_lo = 0.f, l_hi = 0.f;
    float o[8][4];
#pragma unroll
    for (int i = 0; i < 8; i++)
#pragma unroll
        for (int j = 0; j < 4; j++) o[i][j] = 0.f;

    const uint32_t qa =
        sb + (wid * 16 + (lane & 15)) * ATT_LD + ((lane >> 4) * 8) * 2;

    for (int kt = 0; kt < N_ / 128; kt++) {
        if (kt + 1 < N_ / 128) {
            LOAD_STAGE_ATT(kt + 1, (kt + 1) & 1);
            CP_WAIT(1);
        } else {
            CP_WAIT(0);
        }
        __syncthreads();

        const uint32_t stg = sb + ATT_STG0 + (kt & 1) * ATT_STGSZ;

        // ---- S = Qhi @ Khi^T ----
        float s[16][4];
#pragma unroll
        for (int nt = 0; nt < 16; nt++)
#pragma unroll
            for (int j = 0; j < 4; j++) s[nt][j] = 0.f;

#pragma unroll
        for (int k4 = 0; k4 < 4; k4++) {
            uint32_t qh[4];
            ldsm_x4(qh, qa + k4 * 32);
            const uint32_t ka = stg + (lane & 7) * ATT_LD +
                                (k4 * 16 + ((lane >> 3) & 1) * 8) * 2;
#pragma unroll
            for (int blk = 0; blk < 2; blk++) {
                uint32_t kh[8][2];
#pragma unroll
                for (int j = 0; j < 8; j++)
                    ldsm_x2(kh[j], ka + (blk * 8 + j) * 8 * ATT_LD);
#pragma unroll
                for (int j = 0; j < 8; j++)
                    mma16816(s[blk * 8 + j], qh, kh[j]);
            }
        }

        // ---- online softmax (fp32 __expf, verified accuracy) ----
        float tmlo = -INFINITY, tmhi = -INFINITY;
#pragma unroll
        for (int nt = 0; nt < 16; nt++) {
            tmlo = fmaxf(tmlo, fmaxf(s[nt][0], s[nt][1]));
            tmhi = fmaxf(tmhi, fmaxf(s[nt][2], s[nt][3]));
        }
        tmlo = fmaxf(tmlo, __shfl_xor_sync(0xffffffffu, tmlo, 1));
        tmlo = fmaxf(tmlo, __shfl_xor_sync(0xffffffffu, tmlo, 2));
        tmhi = fmaxf(tmhi, __shfl_xor_sync(0xffffffffu, tmhi, 1));
        tmhi = fmaxf(tmhi, __shfl_xor_sync(0xffffffffu, tmhi, 2));

        const float mnlo = fmaxf(m_lo, tmlo);
        const float mnhi = fmaxf(m_hi, tmhi);
        const float corrlo = __expf(m_lo - mnlo);
        const float corrhi = __expf(m_hi - mnhi);
        m_lo = mnlo; m_hi = mnhi;

        float pslo = 0.f, pshi = 0.f;
#pragma unroll
        for (int nt = 0; nt < 16; nt++) {
            s[nt][0] = __expf(s[nt][0] - mnlo) * 1024.f;
            s[nt][1] = __expf(s[nt][1] - mnlo) * 1024.f;
            s[nt][2] = __expf(s[nt][2] - mnhi) * 1024.f;
            s[nt][3] = __expf(s[nt][3] - mnhi) * 1024.f;
            pslo += s[nt][0] + s[nt][1];
            pshi += s[nt][2] + s[nt][3];
        }
        pslo += __shfl_xor_sync(0xffffffffu, pslo, 1);
        pslo += __shfl_xor_sync(0xffffffffu, pslo, 2);
        pshi += __shfl_xor_sync(0xffffffffu, pshi, 1);
        pshi += __shfl_xor_sync(0xffffffffu, pshi, 2);
        l_lo = l_lo * corrlo + pslo;
        l_hi = l_hi * corrhi + pshi;

#pragma unroll
        for (int nt = 0; nt < 8; nt++) {
            o[nt][0] *= corrlo; o[nt][1] *= corrlo;
            o[nt][2] *= corrhi; o[nt][3] *= corrhi;
        }

        // ---- O += Phi @ Vhi ----
#pragma unroll
        for (int t8 = 0; t8 < 8; t8++) {
            uint32_t ah[4];
#pragma unroll
            for (int half = 0; half < 2; half++) {
                ah[half * 2 + 0] = pk2h(s[2 * t8 + half][0],
                                        s[2 * t8 + half][1]);
                ah[half * 2 + 1] = pk2h(s[2 * t8 + half][2],
                                        s[2 * t8 + half][3]);
            }

            const uint32_t va = stg + ATT_MAT +
                ((lane & 7) + 8 * ((lane >> 3) & 1) + t8 * 16) * ATT_LD +
                ((lane >> 4) & 1) * 16;
            uint32_t vh[4][4];
#pragma unroll
            for (int nt2 = 0; nt2 < 4; nt2++)
                ldsm_x4t(vh[nt2], va + nt2 * 32);
#pragma unroll
            for (int nt2 = 0; nt2 < 4; nt2++) {
                mma16816(o[2 * nt2],     ah, vh[nt2]);
                mma16816(o[2 * nt2 + 1], ah, vh[nt2] + 2);
            }
        }
        __syncthreads();
    }
#undef LOAD_STAGE_ATT

    // normalize + store hi fp16
    const float invlo = 1.f / l_lo;
    const float invhi = 1.f / l_hi;
    const size_t rlo = rowbase + q0 + wid * 16 + (lane >> 2);
    const int colb = h * D_ + (lane & 3) * 2;
#pragma unroll
    for (int nt = 0; nt < 8; nt++) {
        const int col = colb + nt * 8;
        *reinterpret_cast<uint32_t*>(ohi + rlo * C_ + col) =
            pk2h(o[nt][0] * invlo, o[nt][1] * invlo);
        *reinterpret_cast<uint32_t*>(ohi + (rlo + 8) * C_ + col) =
            pk2h(o[nt][2] * invhi, o[nt][3] * invhi);
    }
}

// ----------------------------- launch -------------------------------------
extern "C" void kernel_launch(void* const* d_in, const int* in_sizes, int n_in,
                              void* d_out, int out_size) {
    const float* x      = (const float*)d_in[0];
    const float* w_qkv  = (const float*)d_in[1];
    const float* w_proj = (const float*)d_in[2];
    const float* b_proj = (const float*)d_in[3];
    float* out = (float*)d_out;

    __half *xhi, *whiT, *wloT, *phiT, *qhi, *ahi;
    cudaGetSymbolAddress((void**)&xhi,  g_xhi);
    cudaGetSymbolAddress((void**)&whiT, g_whiT);
    cudaGetSymbolAddress((void**)&wloT, g_wloT);
    cudaGetSymbolAddress((void**)&phiT, g_phiT);
    cudaGetSymbolAddress((void**)&qhi,  g_qkvhi);
    cudaGetSymbolAddress((void**)&ahi,  g_ahi);

    cudaFuncSetAttribute((const void*)mma_gemm<false, true, false>,
                         cudaFuncAttributeMaxDynamicSharedMemorySize,
                         GEMM_SMEM_1P);
    cudaFuncSetAttribute((const void*)mma_gemm<true, false, false>,
                         cudaFuncAttributeMaxDynamicSharedMemorySize,
                         GEMM_SMEM_1P);
    cudaFuncSetAttribute((const void*)attn_mma,
                         cudaFuncAttributeMaxDynamicSharedMemorySize, ATT_SMEM);

    // 0) prep
    {
        int n4 = (M_ * C_) / 4;
        convert_hi<<<(n4 + 255) / 256, 256>>>((const float4*)x, xhi, n4);
        dim3 blk(32, 8);
        dim3 g1(QKVC_ / 32, C_ / 32);
        split_transpose<true><<<g1, blk>>>(w_qkv, whiT, wloT, C_, QKVC_);
        dim3 g2(C_ / 32, C_ / 32);
        split_transpose<false><<<g2, blk>>>(w_proj, phiT, nullptr, C_, C_);
    }
    // 1) QKV projection (1-pass fp16) -> fp16 hi, Q pre-scaled by 0.125
    {
        dim3 grid(QKVC_ / 128, M_ / 128);
        mma_gemm<false, true, false><<<grid, 256, GEMM_SMEM_1P>>>(
            xhi, whiT, nullptr, nullptr, nullptr, qhi, C_, QKVC_, C_);
    }
    // 2) attention (pure fp16, fp32 softmax) -> fp16 hi output
    {
        dim3 grid(N_ / 128, B_ * H_);
        attn_mma<<<grid, 256, ATT_SMEM>>>(qhi, ahi);
    }
    // 3) output projection + bias (1-pass) -> fp32 out
    {
        dim3 grid(C_ / 128, M_ / 128);
        mma_gemm<true, false, false><<<grid, 256, GEMM_SMEM_1P>>>(
            ahi, phiT, nullptr, b_proj, out, nullptr, 0, C_, C_);
    }
}

// round 15
// speedup vs baseline: 2.5478x; 1.0658x over previous
#include <cuda_runtime.h>
#include <cuda_fp16.h>
#include <math.h>
#include <stdint.h>

#define B_ 8
#define N_ 1024
#define C_ 768
#define H_ 12
#define D_ 64
#define QKVC_ (3 * C_)
#define M_ (B_ * N_)

// ----------------------------- scratch ------------------------------------
__device__ __half g_xhi[M_ * C_];
__device__ __half g_whiT[QKVC_ * C_];
__device__ __half g_phiT[C_ * C_];
__device__ __half g_qkvhi[M_ * QKVC_];
__device__ __half g_ahi[M_ * C_];

// ----------------------------- helpers ------------------------------------
__device__ __forceinline__ uint32_t smem_u32(const void* p) {
    uint32_t a;
    asm("{ .reg .u64 t; cvta.to.shared.u64 t, %1; cvt.u32.u64 %0, t; }"
        : "=r"(a) : "l"(p));
    return a;
}
__device__ __forceinline__ void cp16(uint32_t s, const void* g) {
    asm volatile("cp.async.cg.shared.global [%0], [%1], 16;"
                 :: "r"(s), "l"(g) : "memory");
}
#define CP_COMMIT() asm volatile("cp.async.commit_group;" ::: "memory")
#define CP_WAIT(n)  asm volatile("cp.async.wait_group %0;" :: "n"(n) : "memory")

__device__ __forceinline__ void ldsm_x4(uint32_t* f, uint32_t a) {
    asm volatile("ldmatrix.sync.aligned.m8n8.x4.shared.b16 {%0,%1,%2,%3}, [%4];"
                 : "=r"(f[0]), "=r"(f[1]), "=r"(f[2]), "=r"(f[3]) : "r"(a));
}
__device__ __forceinline__ void ldsm_x4t(uint32_t* f, uint32_t a) {
    asm volatile("ldmatrix.sync.aligned.m8n8.x4.trans.shared.b16 {%0,%1,%2,%3}, [%4];"
                 : "=r"(f[0]), "=r"(f[1]), "=r"(f[2]), "=r"(f[3]) : "r"(a));
}
__device__ __forceinline__ void ldsm_x2(uint32_t* f, uint32_t a) {
    asm volatile("ldmatrix.sync.aligned.m8n8.x2.shared.b16 {%0,%1}, [%2];"
                 : "=r"(f[0]), "=r"(f[1]) : "r"(a));
}
// fp16 inputs, fp32 accumulate
__device__ __forceinline__ void mma16816(float* d, const uint32_t* a,
                                         const uint32_t* b) {
    asm volatile(
        "mma.sync.aligned.m16n8k16.row.col.f32.f16.f16.f32 "
        "{%0,%1,%2,%3}, {%4,%5,%6,%7}, {%8,%9}, {%0,%1,%2,%3};"
        : "+f"(d[0]), "+f"(d[1]), "+f"(d[2]), "+f"(d[3])
        : "r"(a[0]), "r"(a[1]), "r"(a[2]), "r"(a[3]), "r"(b[0]), "r"(b[1]));
}
__device__ __forceinline__ uint32_t pk2h(float f0, float f1) {
    __half2 h = __floats2half2_rn(f0, f1);
    return *reinterpret_cast<uint32_t*>(&h);
}
__device__ __forceinline__ float ex2f(float x) {
    float r;
    asm("ex2.approx.ftz.f32 %0, %1;" : "=f"(r) : "f"(x));
    return r;
}

// ----------------------------- prep kernels --------------------------------
__global__ void convert_hi(const float4* __restrict__ s,
                           __half* __restrict__ hi, int n4) {
    int i = blockIdx.x * blockDim.x + threadIdx.x;
    if (i >= n4) return;
    float4 v = s[i];
    __align__(8) __half h[4];
    h[0] = __float2half_rn(v.x); h[1] = __float2half_rn(v.y);
    h[2] = __float2half_rn(v.z); h[3] = __float2half_rn(v.w);
    *reinterpret_cast<uint2*>(hi + (size_t)i * 4) = *reinterpret_cast<uint2*>(h);
}

// Both weight transposes in one launch: z=0 -> w_qkv [768,2304],
// z=1 -> w_proj [768,768]. Output hi fp16, pre-scaled x32.
__global__ void transpose_both(const float* __restrict__ wq,
                               const float* __restrict__ wp,
                               __half* __restrict__ qT,
                               __half* __restrict__ pT) {
    __shared__ float t[32][33];
    const int z = blockIdx.z;
    const int N = z ? C_ : QKVC_;
    const int n0 = blockIdx.x * 32, k0 = blockIdx.y * 32;
    if (n0 >= N) return;
    const float* w = z ? wp : wq;
    __half* oT = z ? pT : qT;
    for (int r = threadIdx.y; r < 32; r += 8)
        t[r][threadIdx.x] = w[(size_t)(k0 + r) * N + n0 + threadIdx.x];
    __syncthreads();
    for (int r = threadIdx.y; r < 32; r += 8) {
        float v = t[threadIdx.x][r] * 32.0f;
        oT[(size_t)(n0 + r) * C_ + k0 + threadIdx.x] = __float2half_rn(v);
    }
}

// ----------------------------- mma.sync GEMM (1-pass fp16) -----------------
// C = Ahi @ Bhi^T. B pre-scaled x32, epilogue x(1/32).
// 256 thr, 8 warps 2x4, warp tile 64x32, BK=32, 2-stage, 2 CTAs/SM.
#define BK_ 32
#define LROW_ 80
#define MATB_ (128 * LROW_)              // 10240
#define GEMM_SMEM (2 * 2 * MATB_)        // 40960

template <bool BIAS, bool SPLITOUT>
__global__ __launch_bounds__(256, 2)
void mma_gemm(const __half* __restrict__ Ahi,
              const __half* __restrict__ BhiT,
              const float* __restrict__ bias,
              float* __restrict__ Cf,
              __half* __restrict__ Chi,
              int scale_cols, int Nn, int K) {
    constexpr int STGB = 2 * MATB_;
    extern __shared__ char smem[];
    const uint32_t sb = smem_u32(smem);
    const int tid = threadIdx.x;
    const int wid = tid >> 5;
    const int lane = tid & 31;
    const int row0 = blockIdx.y * 128;
    const int col0 = blockIdx.x * 128;
    const int wm = (wid >> 2) * 64;
    const int wn = (wid & 3) * 32;

    float acc[4][4][4];
#pragma unroll
    for (int i = 0; i < 4; i++)
#pragma unroll
        for (int j = 0; j < 4; j++)
#pragma unroll
            for (int k = 0; k < 4; k++) acc[i][j][k] = 0.f;

#define LOAD_STAGE(cc, ss)                                                   \
    {                                                                        \
        const uint32_t base = sb + (ss) * STGB;                              \
        const int k0 = (cc) * BK_;                                           \
        _Pragma("unroll")                                                    \
        for (int t = 0; t < 4; t++) {                                        \
            const int idx = tid + t * 256;                                   \
            const int mat = idx >> 9, rem = idx & 511;                       \
            const int r = rem >> 2, ch = rem & 3;                            \
            const uint32_t off = (uint32_t)(mat * MATB_ + r * LROW_ + ch * 16); \
            const __half* src = mat                                          \
                ? BhiT + (size_t)(col0 + r) * K + k0 + ch * 8                \
                : Ahi  + (size_t)(row0 + r) * K + k0 + ch * 8;               \
            cp16(base + off, src);                                           \
        }                                                                    \
        CP_COMMIT();                                                         \
    }

    const int nch = K / BK_;    // 24
    LOAD_STAGE(0, 0);

    for (int c = 0; c < nch; c++) {
        const int cur = c & 1;
        if (c + 1 < nch) {
            LOAD_STAGE(c + 1, 1 - cur);
            CP_WAIT(1);
        } else {
            CP_WAIT(0);
        }
        __syncthreads();

        const uint32_t stg = sb + cur * STGB;
#pragma unroll
        for (int kk = 0; kk < 2; kk++) {
            uint32_t ah[4][4], bh[4][2];
            const uint32_t acol = (uint32_t)((kk * 16 + (lane >> 4) * 8) * 2);
            const uint32_t bcol =
                (uint32_t)((kk * 16 + ((lane >> 3) & 1) * 8) * 2);
#pragma unroll
            for (int mt = 0; mt < 4; mt++) {
                const uint32_t arow =
                    (uint32_t)((wm + mt * 16 + (lane & 15)) * LROW_);
                ldsm_x4(ah[mt], stg + arow + acol);
            }
#pragma unroll
            for (int nt = 0; nt < 4; nt++) {
                const uint32_t brow =
                    (uint32_t)((wn + nt * 8 + (lane & 7)) * LROW_);
                ldsm_x2(bh[nt], stg + MATB_ + brow + bcol);
            }
#pragma unroll
            for (int mt = 0; mt < 4; mt++)
#pragma unroll
                for (int nt = 0; nt < 4; nt++)
                    mma16816(acc[mt][nt], ah[mt], bh[nt]);
        }
        __syncthreads();
    }
#undef LOAD_STAGE

    const float wsc = 0.03125f;   // 1/32
    // Q cols scaled by 0.125*log2(e): S comes out in the log2 domain.
    const float QSC = 0.125f * 1.4426950408889634f;
    const int g = lane >> 2, t4 = lane & 3;
#pragma unroll
    for (int nt = 0; nt < 4; nt++) {
        const int col = col0 + wn + nt * 8 + t4 * 2;
        if (SPLITOUT) {
            const float sc = ((col < scale_cols) ? QSC : 1.0f) * wsc;
#pragma unroll
            for (int mt = 0; mt < 4; mt++) {
                const int ra = row0 + wm + mt * 16 + g;
#pragma unroll
                for (int half = 0; half < 2; half++) {
                    const int r = ra + half * 8;
                    const size_t off = (size_t)r * Nn + col;
                    *reinterpret_cast<uint32_t*>(Chi + off) =
                        pk2h(acc[mt][nt][half * 2 + 0] * sc,
                             acc[mt][nt][half * 2 + 1] * sc);
                }
            }
        } else {
            float b0 = 0.f, b1 = 0.f;
            if (BIAS) { b0 = bias[col]; b1 = bias[col + 1]; }
#pragma unroll
            for (int mt = 0; mt < 4; mt++) {
                const int ra = row0 + wm + mt * 16 + g;
                float2 v0 = make_float2(acc[mt][nt][0] * wsc + b0,
                                        acc[mt][nt][1] * wsc + b1);
                float2 v1 = make_float2(acc[mt][nt][2] * wsc + b0,
                                        acc[mt][nt][3] * wsc + b1);
                *reinterpret_cast<float2*>(&Cf[(size_t)ra * Nn + col]) = v0;
                *reinterpret_cast<float2*>(&Cf[(size_t)(ra + 8) * Nn + col]) = v1;
            }
        }
    }
}

// ----------------------------- mma flash attention (pure fp16) -------------
// S in log2 domain (q pre-scaled by 0.125*log2e). P = ex2(s - m + 10);
// l carries the same x1024 factor (O/l invariant).
#define ATT_LD 144
#define ATT_MAT 18432
#define ATT_STG0 ATT_MAT                  // Q hi
#define ATT_STGSZ (2 * ATT_MAT)           // Khi, Vhi
#define ATT_SMEM (ATT_STG0 + 2 * ATT_STGSZ)  // 92160

__global__ __launch_bounds__(256, 2)
void attn_mma(const __half* __restrict__ qhi,
              __half* __restrict__ ohi) {
    extern __shared__ char smem[];
    const uint32_t sb = smem_u32(smem);
    const int tid = threadIdx.x, wid = tid >> 5, lane = tid & 31;
    const int b = blockIdx.y / H_, h = blockIdx.y % H_;
    const int q0 = blockIdx.x * 128;
    const size_t rowbase = (size_t)b * N_;

    // ---- load Q hi ----
#pragma unroll
    for (int t = 0; t < 4; t++) {
        const int idx = tid + t * 256;
        const int r = idx >> 3, c = idx & 7;
        cp16(sb + r * ATT_LD + c * 16,
             qhi + ((rowbase + q0 + r) * QKVC_ + h * D_ + c * 8));
    }

#define LOAD_STAGE_ATT(ktile, ss)                                            \
    {                                                                        \
        const uint32_t base = sb + ATT_STG0 + (ss) * ATT_STGSZ;              \
        const size_t krow = rowbase + (ktile) * 128;                         \
        _Pragma("unroll")                                                    \
        for (int t = 0; t < 8; t++) {                                        \
            const int idx = tid + t * 256;                                   \
            const int mat = idx >> 10, rem = idx & 1023;                     \
            const int r = rem >> 3, c = rem & 7;                             \
            const uint32_t so = base + mat * ATT_MAT + r * ATT_LD + c * 16;  \
            const __half* sp = qhi +                                         \
                ((krow + r) * QKVC_ + (mat ? 2 * C_ : C_) + h * D_ + c * 8); \
            cp16(so, sp);                                                    \
        }                                                                    \
        CP_COMMIT();                                                         \
    }

    LOAD_STAGE_ATT(0, 0);

    float m_lo = -INFINITY, m_hi = -INFINITY, l_lo = 0.f, l_hi = 0.f;
    float o[8][4];
#pragma unroll
    for (int i = 0; i < 8; i++)
#pragma unroll
        for (int j = 0; j < 4; j++) o[i][j] = 0.f;

    const uint32_t qa =
        sb + (wid * 16 + (lane & 15)) * ATT_LD + ((lane >> 4) * 8) * 2;

    for (int kt = 0; kt < N_ / 128; kt++) {
        if (kt + 1 < N_ / 128) {
            LOAD_STAGE_ATT(kt + 1, (kt + 1) & 1);
            CP_WAIT(1);
        } else {
            CP_WAIT(0);
        }
        __syncthreads();

        const uint32_t stg = sb + ATT_STG0 + (kt & 1) * ATT_STGSZ;

        // ---- S = Qhi @ Khi^T (log2 domain) ----
        float s[16][4];
#pragma unroll
        for (int nt = 0; nt < 16; nt++)
#pragma unroll
            for (int j = 0; j < 4; j++) s[nt][j] = 0.f;

#pragma unroll
        for (int k4 = 0; k4 < 4; k4++) {
            uint32_t qh[4];
            ldsm_x4(qh, qa + k4 * 32);
            const uint32_t ka = stg + (lane & 7) * ATT_LD +
                                (k4 * 16 + ((lane >> 3) & 1) * 8) * 2;
#pragma unroll
            for (int blk = 0; blk < 2; blk++) {
                uint32_t kh[8][2];
#pragma unroll
                for (int j = 0; j < 8; j++)
                    ldsm_x2(kh[j], ka + (blk * 8 + j) * 8 * ATT_LD);
#pragma unroll
                for (int j = 0; j < 8; j++)
                    mma16816(s[blk * 8 + j], qh, kh[j]);
            }
        }

        // ---- online softmax: p = ex2(s - m + 10) ----
        float tmlo = -INFINITY, tmhi = -INFINITY;
#pragma unroll
        for (int nt = 0; nt < 16; nt++) {
            tmlo = fmaxf(tmlo, fmaxf(s[nt][0], s[nt][1]));
            tmhi = fmaxf(tmhi, fmaxf(s[nt][2], s[nt][3]));
        }
        tmlo = fmaxf(tmlo, __shfl_xor_sync(0xffffffffu, tmlo, 1));
        tmlo = fmaxf(tmlo, __shfl_xor_sync(0xffffffffu, tmlo, 2));
        tmhi = fmaxf(tmhi, __shfl_xor_sync(0xffffffffu, tmhi, 1));
        tmhi = fmaxf(tmhi, __shfl_xor_sync(0xffffffffu, tmhi, 2));

        const float mnlo = fmaxf(m_lo, tmlo);
        const float mnhi = fmaxf(m_hi, tmhi);
        const float corrlo = ex2f(m_lo - mnlo);
        const float corrhi = ex2f(m_hi - mnhi);
        m_lo = mnlo; m_hi = mnhi;

        const float klo = 10.f - mnlo;
        const float khi = 10.f - mnhi;
        float pslo = 0.f, pshi = 0.f;
#pragma unroll
        for (int nt = 0; nt < 16; nt++) {
            s[nt][0] = ex2f(s[nt][0] + klo);
            s[nt][1] = ex2f(s[nt][1] + klo);
            s[nt][2] = ex2f(s[nt][2] + khi);
            s[nt][3] = ex2f(s[nt][3] + khi);
            pslo += s[nt][0] + s[nt][1];
            pshi += s[nt][2] + s[nt][3];
        }
        pslo += __shfl_xor_sync(0xffffffffu, pslo, 1);
        pslo += __shfl_xor_sync(0xffffffffu, pslo, 2);
        pshi += __shfl_xor_sync(0xffffffffu, pshi, 1);
        pshi += __shfl_xor_sync(0xffffffffu, pshi, 2);
        l_lo = l_lo * corrlo + pslo;
        l_hi = l_hi * corrhi + pshi;

#pragma unroll
        for (int nt = 0; nt < 8; nt++) {
            o[nt][0] *= corrlo; o[nt][1] *= corrlo;
            o[nt][2] *= corrhi; o[nt][3] *= corrhi;
        }

        // ---- O += Phi @ Vhi ----
#pragma unroll
        for (int t8 = 0; t8 < 8; t8++) {
            uint32_t ah[4];
#pragma unroll
            for (int half = 0; half < 2; half++) {
                ah[half * 2 + 0] = pk2h(s[2 * t8 + half][0],
                                        s[2 * t8 + half][1]);
                ah[half * 2 + 1] = pk2h(s[2 * t8 + half][2],
                                        s[2 * t8 + half][3]);
            }

            const uint32_t va = stg + ATT_MAT +
                ((lane & 7) + 8 * ((lane >> 3) & 1) + t8 * 16) * ATT_LD +
                ((lane >> 4) & 1) * 16;
            uint32_t vh[4][4];
#pragma unroll
            for (int nt2 = 0; nt2 < 4; nt2++)
                ldsm_x4t(vh[nt2], va + nt2 * 32);
#pragma unroll
            for (int nt2 = 0; nt2 < 4; nt2++) {
                mma16816(o[2 * nt2],     ah, vh[nt2]);
                mma16816(o[2 * nt2 + 1], ah, vh[nt2] + 2);
            }
        }
        __syncthreads();
    }
#undef LOAD_STAGE_ATT

    // normalize + store hi fp16
    const float invlo = 1.f / l_lo;
    const float invhi = 1.f / l_hi;
    const size_t rlo = rowbase + q0 + wid * 16 + (lane >> 2);
    const int colb = h * D_ + (lane & 3) * 2;
#pragma unroll
    for (int nt = 0; nt < 8; nt++) {
        const int col = colb + nt * 8;
        *reinterpret_cast<uint32_t*>(ohi + rlo * C_ + col) =
            pk2h(o[nt][0] * invlo, o[nt][1] * invlo);
        *reinterpret_cast<uint32_t*>(ohi + (rlo + 8) * C_ + col) =
            pk2h(o[nt][2] * invhi, o[nt][3] * invhi);
    }
}

// ----------------------------- launch -------------------------------------
extern "C" void kernel_launch(void* const* d_in, const int* in_sizes, int n_in,
                              void* d_out, int out_size) {
    const float* x      = (const float*)d_in[0];
    const float* w_qkv  = (const float*)d_in[1];
    const float* w_proj = (const float*)d_in[2];
    const float* b_proj = (const float*)d_in[3];
    float* out = (float*)d_out;

    __half *xhi, *whiT, *phiT, *qhi, *ahi;
    cudaGetSymbolAddress((void**)&xhi,  g_xhi);
    cudaGetSymbolAddress((void**)&whiT, g_whiT);
    cudaGetSymbolAddress((void**)&phiT, g_phiT);
    cudaGetSymbolAddress((void**)&qhi,  g_qkvhi);
    cudaGetSymbolAddress((void**)&ahi,  g_ahi);

    cudaFuncSetAttribute((const void*)mma_gemm<false, true>,
                         cudaFuncAttributeMaxDynamicSharedMemorySize,
                         GEMM_SMEM);
    cudaFuncSetAttribute((const void*)mma_gemm<true, false>,
                         cudaFuncAttributeMaxDynamicSharedMemorySize,
                         GEMM_SMEM);
    cudaFuncSetAttribute((const void*)attn_mma,
                         cudaFuncAttributeMaxDynamicSharedMemorySize, ATT_SMEM);

    // 0) prep: x -> fp16; both weight transposes in one launch
    {
        int n4 = (M_ * C_) / 4;
        convert_hi<<<(n4 + 255) / 256, 256>>>((const float4*)x, xhi, n4);
        dim3 blk(32, 8);
        dim3 g(QKVC_ / 32, C_ / 32, 2);
        transpose_both<<<g, blk>>>(w_qkv, w_proj, whiT, phiT);
    }
    // 1) QKV projection (1-pass fp16); Q pre-scaled by 0.125*log2e
    {
        dim3 grid(QKVC_ / 128, M_ / 128);
        mma_gemm<false, true><<<grid, 256, GEMM_SMEM>>>(
            xhi, whiT, nullptr, nullptr, qhi, C_, QKVC_, C_);
    }
    // 2) attention (pure fp16, exp2 softmax)
    {
        dim3 grid(N_ / 128, B_ * H_);
        attn_mma<<<grid, 256, ATT_SMEM>>>(qhi, ahi);
    }
    // 3) output projection + bias (1-pass) -> fp32 out
    {
        dim3 grid(C_ / 128, M_ / 128);
        mma_gemm<true, false><<<grid, 256, GEMM_SMEM>>>(
            ahi, phiT, b_proj, out, nullptr, 0, C_, C_);
    }
}

// round 16
// speedup vs baseline: 2.5503x; 1.0010x over previous
#include <cuda_runtime.h>
#include <cuda_fp16.h>
#include <math.h>
#include <stdint.h>

#define B_ 8
#define N_ 1024
#define C_ 768
#define H_ 12
#define D_ 64
#define QKVC_ (3 * C_)
#define M_ (B_ * N_)

// ----------------------------- scratch ------------------------------------
__device__ __half g_xhi[M_ * C_];
__device__ __half g_whiT[QKVC_ * C_];
__device__ __half g_phiT[C_ * C_];
__device__ __half g_qkvhi[M_ * QKVC_];
__device__ __half g_ahi[M_ * C_];

// ----------------------------- helpers ------------------------------------
__device__ __forceinline__ uint32_t smem_u32(const void* p) {
    uint32_t a;
    asm("{ .reg .u64 t; cvta.to.shared.u64 t, %1; cvt.u32.u64 %0, t; }"
        : "=r"(a) : "l"(p));
    return a;
}
__device__ __forceinline__ void cp16(uint32_t s, const void* g) {
    asm volatile("cp.async.cg.shared.global [%0], [%1], 16;"
                 :: "r"(s), "l"(g) : "memory");
}
#define CP_COMMIT() asm volatile("cp.async.commit_group;" ::: "memory")
#define CP_WAIT(n)  asm volatile("cp.async.wait_group %0;" :: "n"(n) : "memory")

__device__ __forceinline__ void ldsm_x4(uint32_t* f, uint32_t a) {
    asm volatile("ldmatrix.sync.aligned.m8n8.x4.shared.b16 {%0,%1,%2,%3}, [%4];"
                 : "=r"(f[0]), "=r"(f[1]), "=r"(f[2]), "=r"(f[3]) : "r"(a));
}
__device__ __forceinline__ void ldsm_x4t(uint32_t* f, uint32_t a) {
    asm volatile("ldmatrix.sync.aligned.m8n8.x4.trans.shared.b16 {%0,%1,%2,%3}, [%4];"
                 : "=r"(f[0]), "=r"(f[1]), "=r"(f[2]), "=r"(f[3]) : "r"(a));
}
__device__ __forceinline__ void ldsm_x2(uint32_t* f, uint32_t a) {
    asm volatile("ldmatrix.sync.aligned.m8n8.x2.shared.b16 {%0,%1}, [%2];"
                 : "=r"(f[0]), "=r"(f[1]) : "r"(a));
}
// fp16 inputs, fp32 accumulate
__device__ __forceinline__ void mma16816(float* d, const uint32_t* a,
                                         const uint32_t* b) {
    asm volatile(
        "mma.sync.aligned.m16n8k16.row.col.f32.f16.f16.f32 "
        "{%0,%1,%2,%3}, {%4,%5,%6,%7}, {%8,%9}, {%0,%1,%2,%3};"
        : "+f"(d[0]), "+f"(d[1]), "+f"(d[2]), "+f"(d[3])
        : "r"(a[0]), "r"(a[1]), "r"(a[2]), "r"(a[3]), "r"(b[0]), "r"(b[1]));
}
__device__ __forceinline__ uint32_t pk2h(float f0, float f1) {
    __half2 h = __floats2half2_rn(f0, f1);
    return *reinterpret_cast<uint32_t*>(&h);
}
__device__ __forceinline__ float ex2f(float x) {
    float r;
    asm("ex2.approx.ftz.f32 %0, %1;" : "=f"(r) : "f"(x));
    return r;
}

// ----------------------------- prep (single launch) ------------------------
// z=0: transpose w_qkv [768,2304] -> whiT [2304,768] (x32)
// z=1: transpose w_proj [768,768] -> phiT (x32)
// z=2: convert x fp32 -> fp16
__global__ void prep_all(const float* __restrict__ x,
                         const float* __restrict__ wq,
                         const float* __restrict__ wp,
                         __half* __restrict__ xhi,
                         __half* __restrict__ qT,
                         __half* __restrict__ pT) {
    const int z = blockIdx.z;
    if (z == 2) {
        const int tid = threadIdx.y * 32 + threadIdx.x;
        const int blk = blockIdx.y * 72 + blockIdx.x;   // 0..1727
        const int n4 = (M_ * C_) / 4;                   // 1572864
        const float4* s = reinterpret_cast<const float4*>(x);
        for (int i = blk * 256 + tid; i < n4; i += 1728 * 256) {
            float4 v = s[i];
            __align__(8) __half h[4];
            h[0] = __float2half_rn(v.x); h[1] = __float2half_rn(v.y);
            h[2] = __float2half_rn(v.z); h[3] = __float2half_rn(v.w);
            *reinterpret_cast<uint2*>(xhi + (size_t)i * 4) =
                *reinterpret_cast<uint2*>(h);
        }
        return;
    }
    __shared__ float t[32][33];
    const int N = z ? C_ : QKVC_;
    const int n0 = blockIdx.x * 32, k0 = blockIdx.y * 32;
    if (n0 >= N) return;
    const float* w = z ? wp : wq;
    __half* oT = z ? pT : qT;
    for (int r = threadIdx.y; r < 32; r += 8)
        t[r][threadIdx.x] = w[(size_t)(k0 + r) * N + n0 + threadIdx.x];
    __syncthreads();
    for (int r = threadIdx.y; r < 32; r += 8) {
        float v = t[threadIdx.x][r] * 32.0f;
        oT[(size_t)(n0 + r) * C_ + k0 + threadIdx.x] = __float2half_rn(v);
    }
}

// ----------------------------- mma.sync GEMM (1-pass fp16) -----------------
#define BK_ 32
#define LROW_ 80
#define MATB_ (128 * LROW_)              // 10240
#define GEMM_SMEM (2 * 2 * MATB_)        // 40960

template <bool BIAS, bool SPLITOUT>
__global__ __launch_bounds__(256, 2)
void mma_gemm(const __half* __restrict__ Ahi,
              const __half* __restrict__ BhiT,
              const float* __restrict__ bias,
              float* __restrict__ Cf,
              __half* __restrict__ Chi,
              int scale_cols, int Nn, int K) {
    constexpr int STGB = 2 * MATB_;
    extern __shared__ char smem[];
    const uint32_t sb = smem_u32(smem);
    const int tid = threadIdx.x;
    const int wid = tid >> 5;
    const int lane = tid & 31;
    const int row0 = blockIdx.y * 128;
    const int col0 = blockIdx.x * 128;
    const int wm = (wid >> 2) * 64;
    const int wn = (wid & 3) * 32;

    float acc[4][4][4];
#pragma unroll
    for (int i = 0; i < 4; i++)
#pragma unroll
        for (int j = 0; j < 4; j++)
#pragma unroll
            for (int k = 0; k < 4; k++) acc[i][j][k] = 0.f;

#define LOAD_STAGE(cc, ss)                                                   \
    {                                                                        \
        const uint32_t base = sb + (ss) * STGB;                              \
        const int k0 = (cc) * BK_;                                           \
        _Pragma("unroll")                                                    \
        for (int t = 0; t < 4; t++) {                                        \
            const int idx = tid + t * 256;                                   \
            const int mat = idx >> 9, rem = idx & 511;                       \
            const int r = rem >> 2, ch = rem & 3;                            \
            const uint32_t off = (uint32_t)(mat * MATB_ + r * LROW_ + ch * 16); \
            const __half* src = mat                                          \
                ? BhiT + (size_t)(col0 + r) * K + k0 + ch * 8                \
                : Ahi  + (size_t)(row0 + r) * K + k0 + ch * 8;               \
            cp16(base + off, src);                                           \
        }                                                                    \
        CP_COMMIT();                                                         \
    }

    const int nch = K / BK_;    // 24
    LOAD_STAGE(0, 0);

    for (int c = 0; c < nch; c++) {
        const int cur = c & 1;
        if (c + 1 < nch) {
            LOAD_STAGE(c + 1, 1 - cur);
            CP_WAIT(1);
        } else {
            CP_WAIT(0);
        }
        __syncthreads();

        const uint32_t stg = sb + cur * STGB;
#pragma unroll
        for (int kk = 0; kk < 2; kk++) {
            uint32_t ah[4][4], bh[4][2];
            const uint32_t acol = (uint32_t)((kk * 16 + (lane >> 4) * 8) * 2);
            const uint32_t bcol =
                (uint32_t)((kk * 16 + ((lane >> 3) & 1) * 8) * 2);
#pragma unroll
            for (int mt = 0; mt < 4; mt++) {
                const uint32_t arow =
                    (uint32_t)((wm + mt * 16 + (lane & 15)) * LROW_);
                ldsm_x4(ah[mt], stg + arow + acol);
            }
#pragma unroll
            for (int nt = 0; nt < 4; nt++) {
                const uint32_t brow =
                    (uint32_t)((wn + nt * 8 + (lane & 7)) * LROW_);
                ldsm_x2(bh[nt], stg + MATB_ + brow + bcol);
            }
#pragma unroll
            for (int mt = 0; mt < 4; mt++)
#pragma unroll
                for (int nt = 0; nt < 4; nt++)
                    mma16816(acc[mt][nt], ah[mt], bh[nt]);
        }
        __syncthreads();
    }
#undef LOAD_STAGE

    const float wsc = 0.03125f;   // 1/32
    const float QSC = 0.125f * 1.4426950408889634f;   // S in log2 domain
    const int g = lane >> 2, t4 = lane & 3;
#pragma unroll
    for (int nt = 0; nt < 4; nt++) {
        const int col = col0 + wn + nt * 8 + t4 * 2;
        if (SPLITOUT) {
            const float sc = ((col < scale_cols) ? QSC : 1.0f) * wsc;
#pragma unroll
            for (int mt = 0; mt < 4; mt++) {
                const int ra = row0 + wm + mt * 16 + g;
#pragma unroll
                for (int half = 0; half < 2; half++) {
                    const int r = ra + half * 8;
                    const size_t off = (size_t)r * Nn + col;
                    *reinterpret_cast<uint32_t*>(Chi + off) =
                        pk2h(acc[mt][nt][half * 2 + 0] * sc,
                             acc[mt][nt][half * 2 + 1] * sc);
                }
            }
        } else {
            float b0 = 0.f, b1 = 0.f;
            if (BIAS) { b0 = bias[col]; b1 = bias[col + 1]; }
#pragma unroll
            for (int mt = 0; mt < 4; mt++) {
                const int ra = row0 + wm + mt * 16 + g;
                float2 v0 = make_float2(acc[mt][nt][0] * wsc + b0,
                                        acc[mt][nt][1] * wsc + b1);
                float2 v1 = make_float2(acc[mt][nt][2] * wsc + b0,
                                        acc[mt][nt][3] * wsc + b1);
                *reinterpret_cast<float2*>(&Cf[(size_t)ra * Nn + col]) = v0;
                *reinterpret_cast<float2*>(&Cf[(size_t)(ra + 8) * Nn + col]) = v1;
            }
        }
    }
}

// ----------------------------- mma flash attention (pure fp16) -------------
// S in log2 domain. P = ex2(s - m + 10); per-chunk exp interleaved with PV;
// l kept lane-local, reduced once at the end.
#define ATT_LD 144
#define ATT_MAT 18432
#define ATT_STG0 ATT_MAT                  // Q hi
#define ATT_STGSZ (2 * ATT_MAT)           // Khi, Vhi
#define ATT_SMEM (ATT_STG0 + 2 * ATT_STGSZ)  // 92160

__global__ __launch_bounds__(256, 2)
void attn_mma(const __half* __restrict__ qhi,
              __half* __restrict__ ohi) {
    extern __shared__ char smem[];
    const uint32_t sb = smem_u32(smem);
    const int tid = threadIdx.x, wid = tid >> 5, lane = tid & 31;
    const int b = blockIdx.y / H_, h = blockIdx.y % H_;
    const int q0 = blockIdx.x * 128;
    const size_t rowbase = (size_t)b * N_;

    // ---- load Q hi ----
#pragma unroll
    for (int t = 0; t < 4; t++) {
        const int idx = tid + t * 256;
        const int r = idx >> 3, c = idx & 7;
        cp16(sb + r * ATT_LD + c * 16,
             qhi + ((rowbase + q0 + r) * QKVC_ + h * D_ + c * 8));
    }

#define LOAD_STAGE_ATT(ktile, ss)                                            \
    {                                                                        \
        const uint32_t base = sb + ATT_STG0 + (ss) * ATT_STGSZ;              \
        const size_t krow = rowbase + (ktile) * 128;                         \
        _Pragma("unroll")                                                    \
        for (int t = 0; t < 8; t++) {                                        \
            const int idx = tid + t * 256;                                   \
            const int mat = idx >> 10, rem = idx & 1023;                     \
            const int r = rem >> 3, c = rem & 7;                             \
            const uint32_t so = base + mat * ATT_MAT + r * ATT_LD + c * 16;  \
            const __half* sp = qhi +                                         \
                ((krow + r) * QKVC_ + (mat ? 2 * C_ : C_) + h * D_ + c * 8); \
            cp16(so, sp);                                                    \
        }                                                                    \
        CP_COMMIT();                                                         \
    }

    LOAD_STAGE_ATT(0, 0);

    float m_lo = -INFINITY, m_hi = -INFINITY;
    float l_lo = 0.f, l_hi = 0.f;      // lane-local; reduced at end
    float o[8][4];
#pragma unroll
    for (int i = 0; i < 8; i++)
#pragma unroll
        for (int j = 0; j < 4; j++) o[i][j] = 0.f;

    const uint32_t qa =
        sb + (wid * 16 + (lane & 15)) * ATT_LD + ((lane >> 4) * 8) * 2;

    for (int kt = 0; kt < N_ / 128; kt++) {
        if (kt + 1 < N_ / 128) {
            LOAD_STAGE_ATT(kt + 1, (kt + 1) & 1);
            CP_WAIT(1);
        } else {
            CP_WAIT(0);
        }
        __syncthreads();

        const uint32_t stg = sb + ATT_STG0 + (kt & 1) * ATT_STGSZ;

        // ---- S = Qhi @ Khi^T (log2 domain), K via ldsm_x4 pairs ----
        float s[16][4];
#pragma unroll
        for (int nt = 0; nt < 16; nt++)
#pragma unroll
            for (int j = 0; j < 4; j++) s[nt][j] = 0.f;

#pragma unroll
        for (int k4 = 0; k4 < 4; k4++) {
            uint32_t qh[4];
            ldsm_x4(qh, qa + k4 * 32);
            // x4 B-load: lanes 0-15 -> nt (even), lanes 16-31 -> nt+1
            const uint32_t ka = stg +
                ((lane & 7) + ((lane >> 4) & 1) * 8) * ATT_LD +
                (k4 * 16 + ((lane >> 3) & 1) * 8) * 2;
#pragma unroll
            for (int blk = 0; blk < 2; blk++) {
                uint32_t kf[4][4];
#pragma unroll
                for (int j = 0; j < 4; j++)
                    ldsm_x4(kf[j], ka + (blk * 8 + j * 2) * 8 * ATT_LD);
#pragma unroll
                for (int j = 0; j < 4; j++) {
                    mma16816(s[blk * 8 + 2 * j],     qh, kf[j]);
                    mma16816(s[blk * 8 + 2 * j + 1], qh, kf[j] + 2);
                }
            }
        }

        // ---- row max (quad shfl) ----
        float tmlo = -INFINITY, tmhi = -INFINITY;
#pragma unroll
        for (int nt = 0; nt < 16; nt++) {
            tmlo = fmaxf(tmlo, fmaxf(s[nt][0], s[nt][1]));
            tmhi = fmaxf(tmhi, fmaxf(s[nt][2], s[nt][3]));
        }
        tmlo = fmaxf(tmlo, __shfl_xor_sync(0xffffffffu, tmlo, 1));
        tmlo = fmaxf(tmlo, __shfl_xor_sync(0xffffffffu, tmlo, 2));
        tmhi = fmaxf(tmhi, __shfl_xor_sync(0xffffffffu, tmhi, 1));
        tmhi = fmaxf(tmhi, __shfl_xor_sync(0xffffffffu, tmhi, 2));

        const float mnlo = fmaxf(m_lo, tmlo);
        const float mnhi = fmaxf(m_hi, tmhi);
        const float corrlo = ex2f(m_lo - mnlo);
        const float corrhi = ex2f(m_hi - mnhi);
        m_lo = mnlo; m_hi = mnhi;

        const float klo = 10.f - mnlo;
        const float khi = 10.f - mnhi;
        float pslo = 0.f, pshi = 0.f;

#pragma unroll
        for (int nt = 0; nt < 8; nt++) {
            o[nt][0] *= corrlo; o[nt][1] *= corrlo;
            o[nt][2] *= corrhi; o[nt][3] *= corrhi;
        }

        // ---- per-chunk: exp -> pack -> V-ldsm -> PV MMA (pipe mixing) ----
#pragma unroll
        for (int t8 = 0; t8 < 8; t8++) {
            const float e0 = ex2f(s[2 * t8][0] + klo);
            const float e1 = ex2f(s[2 * t8][1] + klo);
            const float e2 = ex2f(s[2 * t8][2] + khi);
            const float e3 = ex2f(s[2 * t8][3] + khi);
            const float f0 = ex2f(s[2 * t8 + 1][0] + klo);
            const float f1 = ex2f(s[2 * t8 + 1][1] + klo);
            const float f2 = ex2f(s[2 * t8 + 1][2] + khi);
            const float f3 = ex2f(s[2 * t8 + 1][3] + khi);
            pslo += (e0 + e1) + (f0 + f1);
            pshi += (e2 + e3) + (f2 + f3);

            uint32_t ah[4];
            ah[0] = pk2h(e0, e1);
            ah[1] = pk2h(e2, e3);
            ah[2] = pk2h(f0, f1);
            ah[3] = pk2h(f2, f3);

            const uint32_t va = stg + ATT_MAT +
                ((lane & 7) + 8 * ((lane >> 3) & 1) + t8 * 16) * ATT_LD +
                ((lane >> 4) & 1) * 16;
            uint32_t vh[4][4];
#pragma unroll
            for (int nt2 = 0; nt2 < 4; nt2++)
                ldsm_x4t(vh[nt2], va + nt2 * 32);
#pragma unroll
            for (int nt2 = 0; nt2 < 4; nt2++) {
                mma16816(o[2 * nt2],     ah, vh[nt2]);
                mma16816(o[2 * nt2 + 1], ah, vh[nt2] + 2);
            }
        }
        l_lo = l_lo * corrlo + pslo;
        l_hi = l_hi * corrhi + pshi;
        __syncthreads();
    }
#undef LOAD_STAGE_ATT

    // ---- final l reduction (deferred), normalize + store hi fp16 ----
    l_lo += __shfl_xor_sync(0xffffffffu, l_lo, 1);
    l_lo += __shfl_xor_sync(0xffffffffu, l_lo, 2);
    l_hi += __shfl_xor_sync(0xffffffffu, l_hi, 1);
    l_hi += __shfl_xor_sync(0xffffffffu, l_hi, 2);
    const float invlo = 1.f / l_lo;
    const float invhi = 1.f / l_hi;
    const size_t rlo = rowbase + q0 + wid * 16 + (lane >> 2);
    const int colb = h * D_ + (lane & 3) * 2;
#pragma unroll
    for (int nt = 0; nt < 8; nt++) {
        const int col = colb + nt * 8;
        *reinterpret_cast<uint32_t*>(ohi + rlo * C_ + col) =
            pk2h(o[nt][0] * invlo, o[nt][1] * invlo);
        *reinterpret_cast<uint32_t*>(ohi + (rlo + 8) * C_ + col) =
            pk2h(o[nt][2] * invhi, o[nt][3] * invhi);
    }
}

// ----------------------------- launch -------------------------------------
extern "C" void kernel_launch(void* const* d_in, const int* in_sizes, int n_in,
                              void* d_out, int out_size) {
    const float* x      = (const float*)d_in[0];
    const float* w_qkv  = (const float*)d_in[1];
    const float* w_proj = (const float*)d_in[2];
    const float* b_proj = (const float*)d_in[3];
    float* out = (float*)d_out;

    __half *xhi, *whiT, *phiT, *qhi, *ahi;
    cudaGetSymbolAddress((void**)&xhi,  g_xhi);
    cudaGetSymbolAddress((void**)&whiT, g_whiT);
    cudaGetSymbolAddress((void**)&phiT, g_phiT);
    cudaGetSymbolAddress((void**)&qhi,  g_qkvhi);
    cudaGetSymbolAddress((void**)&ahi,  g_ahi);

    cudaFuncSetAttribute((const void*)mma_gemm<false, true>,
                         cudaFuncAttributeMaxDynamicSharedMemorySize,
                         GEMM_SMEM);
    cudaFuncSetAttribute((const void*)mma_gemm<true, false>,
                         cudaFuncAttributeMaxDynamicSharedMemorySize,
                         GEMM_SMEM);
    cudaFuncSetAttribute((const void*)attn_mma,
                         cudaFuncAttributeMaxDynamicSharedMemorySize, ATT_SMEM);

    // 0) prep: one launch (2 transposes + x convert)
    {
        dim3 blk(32, 8);
        dim3 g(QKVC_ / 32, C_ / 32, 3);
        prep_all<<<g, blk>>>(x, w_qkv, w_proj, xhi, whiT, phiT);
    }
    // 1) QKV projection (1-pass fp16); Q pre-scaled by 0.125*log2e
    {
        dim3 grid(QKVC_ / 128, M_ / 128);
        mma_gemm<false, true><<<grid, 256, GEMM_SMEM>>>(
            xhi, whiT, nullptr, nullptr, qhi, C_, QKVC_, C_);
    }
    // 2) attention (pure fp16, interleaved exp2 softmax)
    {
        dim3 grid(N_ / 128, B_ * H_);
        attn_mma<<<grid, 256, ATT_SMEM>>>(qhi, ahi);
    }
    // 3) output projection + bias (1-pass) -> fp32 out
    {
        dim3 grid(C_ / 128, M_ / 128);
        mma_gemm<true, false><<<grid, 256, GEMM_SMEM>>>(
            ahi, phiT, b_proj, out, nullptr, 0, C_, C_);
    }
}

// round 17
// speedup vs baseline: 2.6288x; 1.0308x over previous
#include <cuda_runtime.h>
#include <cuda_fp16.h>
#include <math.h>
#include <stdint.h>

#define B_ 8
#define N_ 1024
#define C_ 768
#define H_ 12
#define D_ 64
#define QKVC_ (3 * C_)
#define M_ (B_ * N_)

// ----------------------------- scratch ------------------------------------
__device__ __half g_xhi[M_ * C_];
__device__ __half g_whiT[QKVC_ * C_];
__device__ __half g_phiT[C_ * C_];
__device__ __half g_qkvhi[M_ * QKVC_];
__device__ __half g_ahi[M_ * C_];

// ----------------------------- helpers ------------------------------------
__device__ __forceinline__ uint32_t smem_u32(const void* p) {
    uint32_t a;
    asm("{ .reg .u64 t; cvta.to.shared.u64 t, %1; cvt.u32.u64 %0, t; }"
        : "=r"(a) : "l"(p));
    return a;
}
__device__ __forceinline__ void cp16(uint32_t s, const void* g) {
    asm volatile("cp.async.cg.shared.global [%0], [%1], 16;"
                 :: "r"(s), "l"(g) : "memory");
}
#define CP_COMMIT() asm volatile("cp.async.commit_group;" ::: "memory")
#define CP_WAIT(n)  asm volatile("cp.async.wait_group %0;" :: "n"(n) : "memory")

__device__ __forceinline__ void ldsm_x4(uint32_t* f, uint32_t a) {
    asm volatile("ldmatrix.sync.aligned.m8n8.x4.shared.b16 {%0,%1,%2,%3}, [%4];"
                 : "=r"(f[0]), "=r"(f[1]), "=r"(f[2]), "=r"(f[3]) : "r"(a));
}
__device__ __forceinline__ void ldsm_x4t(uint32_t* f, uint32_t a) {
    asm volatile("ldmatrix.sync.aligned.m8n8.x4.trans.shared.b16 {%0,%1,%2,%3}, [%4];"
                 : "=r"(f[0]), "=r"(f[1]), "=r"(f[2]), "=r"(f[3]) : "r"(a));
}
__device__ __forceinline__ void ldsm_x2(uint32_t* f, uint32_t a) {
    asm volatile("ldmatrix.sync.aligned.m8n8.x2.shared.b16 {%0,%1}, [%2];"
                 : "=r"(f[0]), "=r"(f[1]) : "r"(a));
}
// fp16 inputs, fp32 accumulate
__device__ __forceinline__ void mma16816(float* d, const uint32_t* a,
                                         const uint32_t* b) {
    asm volatile(
        "mma.sync.aligned.m16n8k16.row.col.f32.f16.f16.f32 "
        "{%0,%1,%2,%3}, {%4,%5,%6,%7}, {%8,%9}, {%0,%1,%2,%3};"
        : "+f"(d[0]), "+f"(d[1]), "+f"(d[2]), "+f"(d[3])
        : "r"(a[0]), "r"(a[1]), "r"(a[2]), "r"(a[3]), "r"(b[0]), "r"(b[1]));
}
__device__ __forceinline__ uint32_t pk2h(float f0, float f1) {
    __half2 h = __floats2half2_rn(f0, f1);
    return *reinterpret_cast<uint32_t*>(&h);
}
__device__ __forceinline__ float ex2f(float x) {
    float r;
    asm("ex2.approx.ftz.f32 %0, %1;" : "=f"(r) : "f"(x));
    return r;
}

// ----------------------------- prep (single launch) ------------------------
__global__ void prep_all(const float* __restrict__ x,
                         const float* __restrict__ wq,
                         const float* __restrict__ wp,
                         __half* __restrict__ xhi,
                         __half* __restrict__ qT,
                         __half* __restrict__ pT) {
    const int z = blockIdx.z;
    if (z == 2) {
        const int tid = threadIdx.y * 32 + threadIdx.x;
        const int blk = blockIdx.y * 72 + blockIdx.x;
        const int n4 = (M_ * C_) / 4;
        const float4* s = reinterpret_cast<const float4*>(x);
        for (int i = blk * 256 + tid; i < n4; i += 1728 * 256) {
            float4 v = s[i];
            __align__(8) __half h[4];
            h[0] = __float2half_rn(v.x); h[1] = __float2half_rn(v.y);
            h[2] = __float2half_rn(v.z); h[3] = __float2half_rn(v.w);
            *reinterpret_cast<uint2*>(xhi + (size_t)i * 4) =
                *reinterpret_cast<uint2*>(h);
        }
        return;
    }
    __shared__ float t[32][33];
    const int N = z ? C_ : QKVC_;
    const int n0 = blockIdx.x * 32, k0 = blockIdx.y * 32;
    if (n0 >= N) return;
    const float* w = z ? wp : wq;
    __half* oT = z ? pT : qT;
    for (int r = threadIdx.y; r < 32; r += 8)
        t[r][threadIdx.x] = w[(size_t)(k0 + r) * N + n0 + threadIdx.x];
    __syncthreads();
    for (int r = threadIdx.y; r < 32; r += 8) {
        float v = t[threadIdx.x][r] * 32.0f;
        oT[(size_t)(n0 + r) * C_ + k0 + threadIdx.x] = __float2half_rn(v);
    }
}

// ----------------------------- mma.sync GEMM (1-pass fp16, BK=64) ----------
// MTILE = 128 (QKV) or 64 (proj, halves wave-quantization tail).
// 256 thr, 8 warps 2x4; warp tile (MTILE/2)x32. 2 stages, 2 CTAs/SM.
#define LROW_ 144
#define GROW_(m) ((m) + 128)             // rows per stage: MTILE A + 128 B

template <bool BIAS, bool SPLITOUT, int MTILE>
__global__ __launch_bounds__(256, 2)
void mma_gemm(const __half* __restrict__ Ahi,
              const __half* __restrict__ BhiT,
              const float* __restrict__ bias,
              float* __restrict__ Cf,
              __half* __restrict__ Chi,
              int scale_cols, int Nn, int K) {
    constexpr int MT = MTILE / 32;                 // m-frags per warp (4 or 2)
    constexpr int AMATB = MTILE * LROW_;
    constexpr int BMATB = 128 * LROW_;
    constexpr int STGB = AMATB + BMATB;
    extern __shared__ char smem[];
    const uint32_t sb = smem_u32(smem);
    const int tid = threadIdx.x;
    const int wid = tid >> 5;
    const int lane = tid & 31;
    const int row0 = blockIdx.y * MTILE;
    const int col0 = blockIdx.x * 128;
    const int wm = (wid >> 2) * (MTILE / 2);
    const int wn = (wid & 3) * 32;

    float acc[MT][4][4];
#pragma unroll
    for (int i = 0; i < MT; i++)
#pragma unroll
        for (int j = 0; j < 4; j++)
#pragma unroll
            for (int k = 0; k < 4; k++) acc[i][j][k] = 0.f;

    // stage load: (MTILE+128) rows x 128B, 8 x 16B chunks/row
#define LOAD_STAGE(cc, ss)                                                   \
    {                                                                        \
        const uint32_t base = sb + (ss) * STGB;                              \
        const int k0 = (cc) * 64;                                            \
        const int tot = GROW_(MTILE) * 8;                                    \
        _Pragma("unroll")                                                    \
        for (int t = 0; t < tot / 256; t++) {                                \
            const int idx = tid + t * 256;                                   \
            const int r = idx >> 3, ch = idx & 7;                            \
            const uint32_t off = (uint32_t)(r * LROW_ + ch * 16);            \
            const __half* src = (r < MTILE)                                  \
                ? Ahi  + (size_t)(row0 + r) * K + k0 + ch * 8                \
                : BhiT + (size_t)(col0 + r - MTILE) * K + k0 + ch * 8;       \
            cp16(base + off, src);                                           \
        }                                                                    \
        CP_COMMIT();                                                         \
    }

    const int nch = K / 64;    // 12
    LOAD_STAGE(0, 0);

    for (int c = 0; c < nch; c++) {
        const int cur = c & 1;
        if (c + 1 < nch) {
            LOAD_STAGE(c + 1, 1 - cur);
            CP_WAIT(1);
        } else {
            CP_WAIT(0);
        }
        __syncthreads();

        const uint32_t stg = sb + cur * STGB;
        const uint32_t bbase = stg + AMATB;
#pragma unroll
        for (int kk = 0; kk < 4; kk++) {
            uint32_t ah[MT][4], bh[4][2];
            const uint32_t acol = (uint32_t)((kk * 16 + (lane >> 4) * 8) * 2);
            const uint32_t bcol =
                (uint32_t)((kk * 16 + ((lane >> 3) & 1) * 8) * 2);
#pragma unroll
            for (int mt = 0; mt < MT; mt++) {
                const uint32_t arow =
                    (uint32_t)((wm + mt * 16 + (lane & 15)) * LROW_);
                ldsm_x4(ah[mt], stg + arow + acol);
            }
#pragma unroll
            for (int nt = 0; nt < 4; nt++) {
                const uint32_t brow =
                    (uint32_t)((wn + nt * 8 + (lane & 7)) * LROW_);
                ldsm_x2(bh[nt], bbase + brow + bcol);
            }
#pragma unroll
            for (int mt = 0; mt < MT; mt++)
#pragma unroll
                for (int nt = 0; nt < 4; nt++)
                    mma16816(acc[mt][nt], ah[mt], bh[nt]);
        }
        __syncthreads();
    }
#undef LOAD_STAGE

    const float wsc = 0.03125f;   // 1/32
    const float QSC = 0.125f * 1.4426950408889634f;   // S in log2 domain
    const int g = lane >> 2, t4 = lane & 3;
#pragma unroll
    for (int nt = 0; nt < 4; nt++) {
        const int col = col0 + wn + nt * 8 + t4 * 2;
        if (SPLITOUT) {
            const float sc = ((col < scale_cols) ? QSC : 1.0f) * wsc;
#pragma unroll
            for (int mt = 0; mt < MT; mt++) {
                const int ra = row0 + wm + mt * 16 + g;
#pragma unroll
                for (int half = 0; half < 2; half++) {
                    const int r = ra + half * 8;
                    const size_t off = (size_t)r * Nn + col;
                    *reinterpret_cast<uint32_t*>(Chi + off) =
                        pk2h(acc[mt][nt][half * 2 + 0] * sc,
                             acc[mt][nt][half * 2 + 1] * sc);
                }
            }
        } else {
            float b0 = 0.f, b1 = 0.f;
            if (BIAS) { b0 = bias[col]; b1 = bias[col + 1]; }
#pragma unroll
            for (int mt = 0; mt < MT; mt++) {
                const int ra = row0 + wm + mt * 16 + g;
                float2 v0 = make_float2(acc[mt][nt][0] * wsc + b0,
                                        acc[mt][nt][1] * wsc + b1);
                float2 v1 = make_float2(acc[mt][nt][2] * wsc + b0,
                                        acc[mt][nt][3] * wsc + b1);
                *reinterpret_cast<float2*>(&Cf[(size_t)ra * Nn + col]) = v0;
                *reinterpret_cast<float2*>(&Cf[(size_t)(ra + 8) * Nn + col]) = v1;
            }
        }
    }
}

#define GEMM_SMEM_128 (2 * (GROW_(128) * LROW_))   // 73728
#define GEMM_SMEM_64  (2 * (GROW_(64) * LROW_))    // 55296

// ----------------------------- mma flash attention (pure fp16) -------------
#define ATT_LD 144
#define ATT_MAT 18432
#define ATT_STG0 ATT_MAT
#define ATT_STGSZ (2 * ATT_MAT)
#define ATT_SMEM (ATT_STG0 + 2 * ATT_STGSZ)  // 92160

__global__ __launch_bounds__(256, 2)
void attn_mma(const __half* __restrict__ qhi,
              __half* __restrict__ ohi) {
    extern __shared__ char smem[];
    const uint32_t sb = smem_u32(smem);
    const int tid = threadIdx.x, wid = tid >> 5, lane = tid & 31;
    const int b = blockIdx.y / H_, h = blockIdx.y % H_;
    const int q0 = blockIdx.x * 128;
    const size_t rowbase = (size_t)b * N_;

#pragma unroll
    for (int t = 0; t < 4; t++) {
        const int idx = tid + t * 256;
        const int r = idx >> 3, c = idx & 7;
        cp16(sb + r * ATT_LD + c * 16,
             qhi + ((rowbase + q0 + r) * QKVC_ + h * D_ + c * 8));
    }

#define LOAD_STAGE_ATT(ktile, ss)                                            \
    {                                                                        \
        const uint32_t base = sb + ATT_STG0 + (ss) * ATT_STGSZ;              \
        const size_t krow = rowbase + (ktile) * 128;                         \
        _Pragma("unroll")                                                    \
        for (int t = 0; t < 8; t++) {                                        \
            const int idx = tid + t * 256;                                   \
            const int mat = idx >> 10, rem = idx & 1023;                     \
            const int r = rem >> 3, c = rem & 7;                             \
            const uint32_t so = base + mat * ATT_MAT + r * ATT_LD + c * 16;  \
            const __half* sp = qhi +                                         \
                ((krow + r) * QKVC_ + (mat ? 2 * C_ : C_) + h * D_ + c * 8); \
            cp16(so, sp);                                                    \
        }                                                                    \
        CP_COMMIT();                                                         \
    }

    LOAD_STAGE_ATT(0, 0);

    float m_lo = -INFINITY, m_hi = -INFINITY;
    float l_lo = 0.f, l_hi = 0.f;
    float o[8][4];
#pragma unroll
    for (int i = 0; i < 8; i++)
#pragma unroll
        for (int j = 0; j < 4; j++) o[i][j] = 0.f;

    const uint32_t qa =
        sb + (wid * 16 + (lane & 15)) * ATT_LD + ((lane >> 4) * 8) * 2;

    for (int kt = 0; kt < N_ / 128; kt++) {
        if (kt + 1 < N_ / 128) {
            LOAD_STAGE_ATT(kt + 1, (kt + 1) & 1);
            CP_WAIT(1);
        } else {
            CP_WAIT(0);
        }
        __syncthreads();

        const uint32_t stg = sb + ATT_STG0 + (kt & 1) * ATT_STGSZ;

        float s[16][4];
#pragma unroll
        for (int nt = 0; nt < 16; nt++)
#pragma unroll
            for (int j = 0; j < 4; j++) s[nt][j] = 0.f;

#pragma unroll
        for (int k4 = 0; k4 < 4; k4++) {
            uint32_t qh[4];
            ldsm_x4(qh, qa + k4 * 32);
            const uint32_t ka = stg +
                ((lane & 7) + ((lane >> 4) & 1) * 8) * ATT_LD +
                (k4 * 16 + ((lane >> 3) & 1) * 8) * 2;
#pragma unroll
            for (int blk = 0; blk < 2; blk++) {
                uint32_t kf[4][4];
#pragma unroll
                for (int j = 0; j < 4; j++)
                    ldsm_x4(kf[j], ka + (blk * 8 + j * 2) * 8 * ATT_LD);
#pragma unroll
                for (int j = 0; j < 4; j++) {
                    mma16816(s[blk * 8 + 2 * j],     qh, kf[j]);
                    mma16816(s[blk * 8 + 2 * j + 1], qh, kf[j] + 2);
                }
            }
        }

        float tmlo = -INFINITY, tmhi = -INFINITY;
#pragma unroll
        for (int nt = 0; nt < 16; nt++) {
            tmlo = fmaxf(tmlo, fmaxf(s[nt][0], s[nt][1]));
            tmhi = fmaxf(tmhi, fmaxf(s[nt][2], s[nt][3]));
        }
        tmlo = fmaxf(tmlo, __shfl_xor_sync(0xffffffffu, tmlo, 1));
        tmlo = fmaxf(tmlo, __shfl_xor_sync(0xffffffffu, tmlo, 2));
        tmhi = fmaxf(tmhi, __shfl_xor_sync(0xffffffffu, tmhi, 1));
        tmhi = fmaxf(tmhi, __shfl_xor_sync(0xffffffffu, tmhi, 2));

        const float mnlo = fmaxf(m_lo, tmlo);
        const float mnhi = fmaxf(m_hi, tmhi);
        const float corrlo = ex2f(m_lo - mnlo);
        const float corrhi = ex2f(m_hi - mnhi);
        m_lo = mnlo; m_hi = mnhi;

        const float klo = 10.f - mnlo;
        const float khi = 10.f - mnhi;
        float pslo = 0.f, pshi = 0.f;

#pragma unroll
        for (int nt = 0; nt < 8; nt++) {
            o[nt][0] *= corrlo; o[nt][1] *= corrlo;
            o[nt][2] *= corrhi; o[nt][3] *= corrhi;
        }

#pragma unroll
        for (int t8 = 0; t8 < 8; t8++) {
            const float e0 = ex2f(s[2 * t8][0] + klo);
            const float e1 = ex2f(s[2 * t8][1] + klo);
            const float e2 = ex2f(s[2 * t8][2] + khi);
            const float e3 = ex2f(s[2 * t8][3] + khi);
            const float f0 = ex2f(s[2 * t8 + 1][0] + klo);
            const float f1 = ex2f(s[2 * t8 + 1][1] + klo);
            const float f2 = ex2f(s[2 * t8 + 1][2] + khi);
            const float f3 = ex2f(s[2 * t8 + 1][3] + khi);
            pslo += (e0 + e1) + (f0 + f1);
            pshi += (e2 + e3) + (f2 + f3);

            uint32_t ah[4];
            ah[0] = pk2h(e0, e1);
            ah[1] = pk2h(e2, e3);
            ah[2] = pk2h(f0, f1);
            ah[3] = pk2h(f2, f3);

            const uint32_t va = stg + ATT_MAT +
                ((lane & 7) + 8 * ((lane >> 3) & 1) + t8 * 16) * ATT_LD +
                ((lane >> 4) & 1) * 16;
            uint32_t vh[4][4];
#pragma unroll
            for (int nt2 = 0; nt2 < 4; nt2++)
                ldsm_x4t(vh[nt2], va + nt2 * 32);
#pragma unroll
            for (int nt2 = 0; nt2 < 4; nt2++) {
                mma16816(o[2 * nt2],     ah, vh[nt2]);
                mma16816(o[2 * nt2 + 1], ah, vh[nt2] + 2);
            }
        }
        l_lo = l_lo * corrlo + pslo;
        l_hi = l_hi * corrhi + pshi;
        __syncthreads();
    }
#undef LOAD_STAGE_ATT

    l_lo += __shfl_xor_sync(0xffffffffu, l_lo, 1);
    l_lo += __shfl_xor_sync(0xffffffffu, l_lo, 2);
    l_hi += __shfl_xor_sync(0xffffffffu, l_hi, 1);
    l_hi += __shfl_xor_sync(0xffffffffu, l_hi, 2);
    const float invlo = 1.f / l_lo;
    const float invhi = 1.f / l_hi;
    const size_t rlo = rowbase + q0 + wid * 16 + (lane >> 2);
    const int colb = h * D_ + (lane & 3) * 2;
#pragma unroll
    for (int nt = 0; nt < 8; nt++) {
        const int col = colb + nt * 8;
        *reinterpret_cast<uint32_t*>(ohi + rlo * C_ + col) =
            pk2h(o[nt][0] * invlo, o[nt][1] * invlo);
        *reinterpret_cast<uint32_t*>(ohi + (rlo + 8) * C_ + col) =
            pk2h(o[nt][2] * invhi, o[nt][3] * invhi);
    }
}

// ----------------------------- launch -------------------------------------
extern "C" void kernel_launch(void* const* d_in, const int* in_sizes, int n_in,
                              void* d_out, int out_size) {
    const float* x      = (const float*)d_in[0];
    const float* w_qkv  = (const float*)d_in[1];
    const float* w_proj = (const float*)d_in[2];
    const float* b_proj = (const float*)d_in[3];
    float* out = (float*)d_out;

    __half *xhi, *whiT, *phiT, *qhi, *ahi;
    cudaGetSymbolAddress((void**)&xhi,  g_xhi);
    cudaGetSymbolAddress((void**)&whiT, g_whiT);
    cudaGetSymbolAddress((void**)&phiT, g_phiT);
    cudaGetSymbolAddress((void**)&qhi,  g_qkvhi);
    cudaGetSymbolAddress((void**)&ahi,  g_ahi);

    cudaFuncSetAttribute((const void*)mma_gemm<false, true, 128>,
                         cudaFuncAttributeMaxDynamicSharedMemorySize,
                         GEMM_SMEM_128);
    cudaFuncSetAttribute((const void*)mma_gemm<true, false, 64>,
                         cudaFuncAttributeMaxDynamicSharedMemorySize,
                         GEMM_SMEM_64);
    cudaFuncSetAttribute((const void*)attn_mma,
                         cudaFuncAttributeMaxDynamicSharedMemorySize, ATT_SMEM);

    // 0) prep: one launch (2 transposes + x convert)
    {
        dim3 blk(32, 8);
        dim3 g(QKVC_ / 32, C_ / 32, 3);
        prep_all<<<g, blk>>>(x, w_qkv, w_proj, xhi, whiT, phiT);
    }
    // 1) QKV projection (1-pass fp16, BK=64); Q pre-scaled by 0.125*log2e
    {
        dim3 grid(QKVC_ / 128, M_ / 128);
        mma_gemm<false, true, 128><<<grid, 256, GEMM_SMEM_128>>>(
            xhi, whiT, nullptr, nullptr, qhi, C_, QKVC_, C_);
    }
    // 2) attention (pure fp16, exp2 softmax)
    {
        dim3 grid(N_ / 128, B_ * H_);
        attn_mma<<<grid, 256, ATT_SMEM>>>(qhi, ahi);
    }
    // 3) output projection + bias (1-pass, 64-row tiles vs wave tail)
    {
        dim3 grid(C_ / 128, M_ / 64);
        mma_gemm<true, false, 64><<<grid, 256, GEMM_SMEM_64>>>(
            ahi, phiT, b_proj, out, nullptr, 0, C_, C_);
    }
}